// round 2
// baseline (speedup 1.0000x reference)
#include <cuda_runtime.h>
#include <cuda_bf16.h>
#include <math.h>

// Problem constants
#define NB 4
#define TT 2048
#define DD 1024
#define HH 16
#define DKK 64
#define MTOK (NB*TT)          // 8192 tokens

// ---------------- scratch (device globals; no allocation allowed) -----------
__device__ float g_z  [MTOK * DD];        // 32 MB  (layernorm out, reused)
__device__ float g_qkv[MTOK * 3 * DD];    // 96 MB
__device__ float g_ctx[MTOK * DD];        // 32 MB
__device__ float g_x1 [MTOK * DD];        // 32 MB
__device__ float g_h  [MTOK * 4 * DD];    // 128 MB

// ---------------- LayerNorm: one block per row (D=1024) ---------------------
__global__ __launch_bounds__(256) void ln_kernel(const float* __restrict__ x,
                                                 const float* __restrict__ g,
                                                 const float* __restrict__ b,
                                                 float* __restrict__ z)
{
    int row = blockIdx.x;
    const float* xr = x + (size_t)row * DD;
    float* zr = z + (size_t)row * DD;
    int tid = threadIdx.x;

    float v[4];
    float sum = 0.f, sq = 0.f;
#pragma unroll
    for (int i = 0; i < 4; i++) {
        v[i] = xr[tid + i * 256];
        sum += v[i];
        sq  += v[i] * v[i];
    }
#pragma unroll
    for (int o = 16; o > 0; o >>= 1) {
        sum += __shfl_xor_sync(0xffffffffu, sum, o);
        sq  += __shfl_xor_sync(0xffffffffu, sq,  o);
    }
    __shared__ float red[2][8];
    int w = tid >> 5, l = tid & 31;
    if (l == 0) { red[0][w] = sum; red[1][w] = sq; }
    __syncthreads();
    if (tid < 32) {
        float s = (tid < 8) ? red[0][tid] : 0.f;
        float q = (tid < 8) ? red[1][tid] : 0.f;
#pragma unroll
        for (int o = 4; o > 0; o >>= 1) {
            s += __shfl_xor_sync(0xffffffffu, s, o);
            q += __shfl_xor_sync(0xffffffffu, q, o);
        }
        if (tid == 0) { red[0][0] = s; red[1][0] = q; }
    }
    __syncthreads();
    float mu  = red[0][0] * (1.f / DD);
    float var = red[1][0] * (1.f / DD) - mu * mu;
    float rstd = rsqrtf(var + 1e-5f);
#pragma unroll
    for (int i = 0; i < 4; i++) {
        int c = tid + i * 256;
        zr[c] = (v[i] - mu) * rstd * g[c] + b[c];
    }
}

// ---------------- SGEMM 128x128x16, 256 threads, 8x8 per thread -------------
// C[M,N] = A[M,K] @ B[K,N] (+ epilogue). All row-major, dims multiples of tile.
// EPI: 0 = none, 1 = +R, 2 = +bias then exact GELU, 3 = +bias +R
template <int EPI>
__global__ __launch_bounds__(256) void sgemm_kernel(
    const float* __restrict__ A, const float* __restrict__ B,
    const float* __restrict__ R, const float* __restrict__ bias,
    float* __restrict__ C, int M, int N, int K)
{
    __shared__ float As[16][128];   // transposed: As[k][m]
    __shared__ float Bs[16][128];   // Bs[k][n]

    int tid = threadIdx.x;
    int tx = tid & 15, ty = tid >> 4;
    int bm = blockIdx.y * 128;
    int bn = blockIdx.x * 128;

    const float* Ab = A + (size_t)bm * K;
    const float* Bb = B + bn;

    float acc[8][8];
#pragma unroll
    for (int i = 0; i < 8; i++)
#pragma unroll
        for (int j = 0; j < 8; j++) acc[i][j] = 0.f;

    for (int kt = 0; kt < K; kt += 16) {
        // A tile: 128 rows x 16 cols = 512 float4
#pragma unroll
        for (int i = 0; i < 2; i++) {
            int q   = tid + i * 256;
            int row = q >> 2;
            int c4  = (q & 3) * 4;
            float4 va = *(const float4*)(Ab + (size_t)row * K + kt + c4);
            As[c4 + 0][row] = va.x; As[c4 + 1][row] = va.y;
            As[c4 + 2][row] = va.z; As[c4 + 3][row] = va.w;
        }
        // B tile: 16 rows x 128 cols = 512 float4
#pragma unroll
        for (int i = 0; i < 2; i++) {
            int q   = tid + i * 256;
            int row = q >> 5;
            int col = (q & 31) * 4;
            *(float4*)(&Bs[row][col]) =
                *(const float4*)(Bb + (size_t)(kt + row) * N + col);
        }
        __syncthreads();
#pragma unroll
        for (int k = 0; k < 16; k++) {
            float a[8], bb[8];
            *(float4*)(a)     = *(float4*)(&As[k][ty * 4]);
            *(float4*)(a + 4) = *(float4*)(&As[k][64 + ty * 4]);
            *(float4*)(bb)    = *(float4*)(&Bs[k][tx * 4]);
            *(float4*)(bb + 4)= *(float4*)(&Bs[k][64 + tx * 4]);
#pragma unroll
            for (int i = 0; i < 8; i++)
#pragma unroll
                for (int j = 0; j < 8; j++)
                    acc[i][j] = fmaf(a[i], bb[j], acc[i][j]);
        }
        __syncthreads();
    }

#pragma unroll
    for (int i = 0; i < 8; i++) {
        int r = bm + ((i < 4) ? (ty * 4 + i) : (64 + ty * 4 + (i - 4)));
#pragma unroll
        for (int j = 0; j < 8; j++) {
            int c = bn + ((j < 4) ? (tx * 4 + j) : (64 + tx * 4 + (j - 4)));
            float v = acc[i][j];
            if (EPI == 2 || EPI == 3) v += bias[c];
            if (EPI == 2) v = 0.5f * v * (1.0f + erff(v * 0.7071067811865475f));
            if (EPI == 1 || EPI == 3) v += R[(size_t)r * N + c];
            C[(size_t)r * N + c] = v;
        }
    }
}

// ---------------- Flash attention (fp32, online softmax) --------------------
// qkv: [8192, 3072]; per token row: [Q(1024) | K(1024) | V(1024)], head h at
// offset h*64 inside each block. Output ctx: [8192, 1024] token-major.
// grid: (T/64 q-tiles, N*H). block: 256 threads = 16x16.
#define FA_PAD 68
extern __shared__ float fa_smem[];

__global__ __launch_bounds__(256) void flash_kernel(
    const float* __restrict__ qkv, const float* __restrict__ mask,
    float* __restrict__ ctx)
{
    float (*Qs)[FA_PAD]  = (float(*)[FA_PAD])(fa_smem);
    float (*KsT)[FA_PAD] = (float(*)[FA_PAD])(fa_smem + 64 * FA_PAD);
    float (*Vs)[FA_PAD]  = (float(*)[FA_PAD])(fa_smem + 2 * 64 * FA_PAD);
    float (*Ps)[FA_PAD]  = (float(*)[FA_PAD])(fa_smem + 3 * 64 * FA_PAD);
    float* mk            = fa_smem + 4 * 64 * FA_PAD;

    int tid = threadIdx.x;
    int tx = tid & 15, ty = tid >> 4;
    int bh = blockIdx.y;
    int n = bh >> 4, h = bh & 15;
    size_t base = (size_t)n * TT * (3 * DD);
    int q0 = blockIdx.x * 64;

    // load Q tile (scaled by dk^-1/2 = 0.125)
#pragma unroll
    for (int i = 0; i < 4; i++) {
        int q  = tid + i * 256;       // float4 index, 1024 total
        int r  = q >> 4;
        int d4 = (q & 15) * 4;
        float4 v = *(const float4*)(qkv + base + (size_t)(q0 + r) * (3 * DD) + h * DKK + d4);
        const float sc = 0.125f;
        Qs[r][d4 + 0] = v.x * sc; Qs[r][d4 + 1] = v.y * sc;
        Qs[r][d4 + 2] = v.z * sc; Qs[r][d4 + 3] = v.w * sc;
    }

    float m_i[4], l_i[4], oacc[4][4];
#pragma unroll
    for (int i = 0; i < 4; i++) {
        m_i[i] = -3.0e38f; l_i[i] = 0.f;
#pragma unroll
        for (int j = 0; j < 4; j++) oacc[i][j] = 0.f;
    }

    for (int s0 = 0; s0 < TT; s0 += 64) {
        __syncthreads();   // previous O-update done; Q visible on first iter
        // load K (transposed) and V tiles
#pragma unroll
        for (int i = 0; i < 4; i++) {
            int q  = tid + i * 256;
            int r  = q >> 4;
            int d4 = (q & 15) * 4;
            const float* tok = qkv + base + (size_t)(s0 + r) * (3 * DD) + h * DKK;
            float4 kv = *(const float4*)(tok + DD + d4);
            KsT[d4 + 0][r] = kv.x; KsT[d4 + 1][r] = kv.y;
            KsT[d4 + 2][r] = kv.z; KsT[d4 + 3][r] = kv.w;
            float4 vv = *(const float4*)(tok + 2 * DD + d4);
            *(float4*)(&Vs[r][d4]) = vv;
        }
        if (tid < 64) mk[tid] = mask[(size_t)n * TT + s0 + tid];
        __syncthreads();

        // S = Qs @ KsT  (+ mask), per-thread 4x4
        float s[4][4];
#pragma unroll
        for (int i = 0; i < 4; i++)
#pragma unroll
            for (int j = 0; j < 4; j++) s[i][j] = mk[tx * 4 + j];
#pragma unroll
        for (int d = 0; d < 64; d++) {
            float a[4], bb[4];
#pragma unroll
            for (int i = 0; i < 4; i++) a[i] = Qs[ty * 4 + i][d];
            *(float4*)bb = *(float4*)(&KsT[d][tx * 4]);
#pragma unroll
            for (int i = 0; i < 4; i++)
#pragma unroll
                for (int j = 0; j < 4; j++)
                    s[i][j] = fmaf(a[i], bb[j], s[i][j]);
        }

        // online softmax per row (row group = 16 tx lanes, contiguous)
#pragma unroll
        for (int i = 0; i < 4; i++) {
            float mx = fmaxf(fmaxf(s[i][0], s[i][1]), fmaxf(s[i][2], s[i][3]));
#pragma unroll
            for (int o = 8; o > 0; o >>= 1)
                mx = fmaxf(mx, __shfl_xor_sync(0xffffffffu, mx, o, 16));
            float mnew  = fmaxf(m_i[i], mx);
            float alpha = __expf(m_i[i] - mnew);
            float rsum = 0.f;
#pragma unroll
            for (int j = 0; j < 4; j++) {
                s[i][j] = __expf(s[i][j] - mnew);
                rsum += s[i][j];
            }
#pragma unroll
            for (int o = 8; o > 0; o >>= 1)
                rsum += __shfl_xor_sync(0xffffffffu, rsum, o, 16);
            l_i[i] = l_i[i] * alpha + rsum;
            m_i[i] = mnew;
#pragma unroll
            for (int j = 0; j < 4; j++) oacc[i][j] *= alpha;
            *(float4*)(&Ps[ty * 4 + i][tx * 4]) = *(float4*)(&s[i][0]);
        }
        __syncthreads();

        // O += Ps @ Vs
#pragma unroll
        for (int ss = 0; ss < 64; ss++) {
            float p[4], vv[4];
#pragma unroll
            for (int i = 0; i < 4; i++) p[i] = Ps[ty * 4 + i][ss];
            *(float4*)vv = *(float4*)(&Vs[ss][tx * 4]);
#pragma unroll
            for (int i = 0; i < 4; i++)
#pragma unroll
                for (int j = 0; j < 4; j++)
                    oacc[i][j] = fmaf(p[i], vv[j], oacc[i][j]);
        }
    }

    // write ctx[token][h*64 + c]
#pragma unroll
    for (int i = 0; i < 4; i++) {
        float inv = 1.f / l_i[i];
        int r = q0 + ty * 4 + i;
        float4 ov = make_float4(oacc[i][0] * inv, oacc[i][1] * inv,
                                oacc[i][2] * inv, oacc[i][3] * inv);
        *(float4*)(ctx + ((size_t)n * TT + r) * DD + h * DKK + tx * 4) = ov;
    }
}

// ---------------- launch -----------------------------------------------------
extern "C" void kernel_launch(void* const* d_in, const int* in_sizes, int n_in,
                              void* d_out, int out_size)
{
    const float* x     = (const float*)d_in[0];
    const float* mask  = (const float*)d_in[1];
    const float* Wqkv  = (const float*)d_in[2];
    const float* Wout  = (const float*)d_in[3];
    const float* ln1_g = (const float*)d_in[4];
    const float* ln1_b = (const float*)d_in[5];
    const float* ln2_g = (const float*)d_in[6];
    const float* ln2_b = (const float*)d_in[7];
    const float* W1    = (const float*)d_in[8];
    const float* b1    = (const float*)d_in[9];
    const float* W2    = (const float*)d_in[10];
    const float* b2    = (const float*)d_in[11];
    float* out = (float*)d_out;

    float *z, *qkv, *ctx, *x1, *hbuf;
    cudaGetSymbolAddress((void**)&z,    g_z);
    cudaGetSymbolAddress((void**)&qkv,  g_qkv);
    cudaGetSymbolAddress((void**)&ctx,  g_ctx);
    cudaGetSymbolAddress((void**)&x1,   g_x1);
    cudaGetSymbolAddress((void**)&hbuf, g_h);

    const int fa_smem_bytes = (4 * 64 * FA_PAD + 64) * (int)sizeof(float);
    cudaFuncSetAttribute(flash_kernel,
                         cudaFuncAttributeMaxDynamicSharedMemorySize,
                         fa_smem_bytes);

    // 1. LN1
    ln_kernel<<<MTOK, 256>>>(x, ln1_g, ln1_b, z);
    // 2. QKV = z @ Wqkv                 [8192,1024]x[1024,3072]
    sgemm_kernel<0><<<dim3(3 * DD / 128, MTOK / 128), 256>>>(
        z, Wqkv, nullptr, nullptr, qkv, MTOK, 3 * DD, DD);
    // 3. attention
    flash_kernel<<<dim3(TT / 64, NB * HH), 256, fa_smem_bytes>>>(qkv, mask, ctx);
    // 4. x1 = x + ctx @ Wout            [8192,1024]x[1024,1024]
    sgemm_kernel<1><<<dim3(DD / 128, MTOK / 128), 256>>>(
        ctx, Wout, x, nullptr, x1, MTOK, DD, DD);
    // 5. LN2
    ln_kernel<<<MTOK, 256>>>(x1, ln2_g, ln2_b, z);
    // 6. h = gelu(z @ W1 + b1)          [8192,1024]x[1024,4096]
    sgemm_kernel<2><<<dim3(4 * DD / 128, MTOK / 128), 256>>>(
        z, W1, nullptr, b1, hbuf, MTOK, 4 * DD, DD);
    // 7. out = x1 + h @ W2 + b2         [8192,4096]x[4096,1024]
    sgemm_kernel<3><<<dim3(DD / 128, MTOK / 128), 256>>>(
        hbuf, W2, x1, b2, out, MTOK, DD, 4 * DD);
}

// round 7
// speedup vs baseline: 3.4283x; 3.4283x over previous
#include <cuda_runtime.h>
#include <cuda_bf16.h>
#include <math.h>

// Problem constants
#define NB 4
#define TT 2048
#define DD 1024
#define HH 16
#define DKK 64
#define MTOK (NB*TT)          // 8192 tokens

// ---------------- scratch (device globals; no allocation allowed) -----------
__device__ float g_qkv[MTOK * 3 * DD];           // 96 MB fp32
__device__ float g_ctx[MTOK * DD];               // 32 MB fp32
__device__ float g_x1 [MTOK * DD];               // 32 MB fp32
__device__ __nv_bfloat16 g_zh [MTOK * DD];       // LN out hi
__device__ __nv_bfloat16 g_zl [MTOK * DD];       // LN out lo
__device__ __nv_bfloat16 g_ch [MTOK * DD];       // ctx hi
__device__ __nv_bfloat16 g_cl [MTOK * DD];       // ctx lo
__device__ __nv_bfloat16 g_hb [MTOK * 4 * DD];   // FFN hidden (bf16)
__device__ __nv_bfloat16 g_wqh[3 * DD * DD];     // Wqkv^T hi  [3072,1024]
__device__ __nv_bfloat16 g_wql[3 * DD * DD];
__device__ __nv_bfloat16 g_woh[DD * DD];         // Wout^T hi  [1024,1024]
__device__ __nv_bfloat16 g_wol[DD * DD];
__device__ __nv_bfloat16 g_w1t[4 * DD * DD];     // W1^T [4096,1024]
__device__ __nv_bfloat16 g_w2t[DD * 4 * DD];     // W2^T [1024,4096]

// ---------------- PTX helpers ------------------------------------------------
__device__ __forceinline__ unsigned smem_u32(const void* p) {
    unsigned a;
    asm("{ .reg .u64 t; cvta.to.shared.u64 t, %1; cvt.u32.u64 %0, t; }"
        : "=r"(a) : "l"(p));
    return a;
}
__device__ __forceinline__ void cp16(unsigned dst, const void* src) {
    asm volatile("cp.async.cg.shared.global [%0], [%1], 16;"
                 :: "r"(dst), "l"(src) : "memory");
}
__device__ __forceinline__ void cpcommit() {
    asm volatile("cp.async.commit_group;" ::: "memory");
}
template <int N> __device__ __forceinline__ void cpwait() {
    asm volatile("cp.async.wait_group %0;" :: "n"(N) : "memory");
}
__device__ __forceinline__ void ldsm4(unsigned* r, unsigned addr) {
    asm volatile("ldmatrix.sync.aligned.m8n8.x4.shared.b16 {%0,%1,%2,%3}, [%4];"
                 : "=r"(r[0]), "=r"(r[1]), "=r"(r[2]), "=r"(r[3]) : "r"(addr));
}
__device__ __forceinline__ void mma16816(float* d, const unsigned* a,
                                         const unsigned* b) {
    asm volatile(
        "mma.sync.aligned.m16n8k16.row.col.f32.bf16.bf16.f32 "
        "{%0,%1,%2,%3}, {%4,%5,%6,%7}, {%8,%9}, {%0,%1,%2,%3};"
        : "+f"(d[0]), "+f"(d[1]), "+f"(d[2]), "+f"(d[3])
        : "r"(a[0]), "r"(a[1]), "r"(a[2]), "r"(a[3]), "r"(b[0]), "r"(b[1]));
}

#define GSW(off) ((off) ^ ((((unsigned)(off)) >> 3) & 0x70u))

// ---------------- HMMA bf16 GEMM: C[M,N] = sum_passes A@B^T  -----------------
// A[M,K], B[N,K] K-major bf16. Tile 128x128, K-chunk 64 (128B rows, swizzled),
// double-buffered cp.async. 8 warps: wm=wid&3 (32 rows), wn=wid>>2 (64 cols).
// passes: p0 (Ah,Bh)  p1 (Ah,Bl)  p2 (Al,Bh)  [p3 (Al,Bl) unused]
// EPI: 0 none, 1 +R, 2 +bias,gelu, 3 +bias+R. OUTB: 1 -> write bf16.
#define GEMM_SMEM (65536 + 1024)

template <int NPASS, int EPI, int OUTB>
__global__ __launch_bounds__(256) void hmma_gemm(
    const __nv_bfloat16* __restrict__ Ah, const __nv_bfloat16* __restrict__ Al,
    const __nv_bfloat16* __restrict__ Bh, const __nv_bfloat16* __restrict__ Bl,
    const float* __restrict__ R, const float* __restrict__ bias,
    float* __restrict__ Cf, __nv_bfloat16* __restrict__ Cb,
    int M, int N, int K)
{
    extern __shared__ char dsm[];
    unsigned smb    = smem_u32(dsm);
    unsigned tile_u = (smb + 1023u) & ~1023u;

    int tid = threadIdx.x, wid = tid >> 5, lane = tid & 31;
    int wm = wid & 3, wn = wid >> 2;
    int bm = blockIdx.y << 7, bn = blockIdx.x << 7;

    const int nk = K >> 6;
    const int total = NPASS * nk;

    // ldmatrix lane addressing (byte offsets within tile, pre-swizzled)
    int li  = lane & 7, sub = lane >> 3;
    // A: row = wm*32 + mt*16 + (sub&1)*8 + li ; kb = (sub>>1)*16
    unsigned aoff[2];
#pragma unroll
    for (int mt = 0; mt < 2; mt++) {
        unsigned r = (unsigned)(wm * 32 + mt * 16 + (sub & 1) * 8 + li);
        aoff[mt] = (r << 7) + (unsigned)((sub >> 1) << 4);
        aoff[mt] ^= (r & 7u) << 4;
    }
    // B: n = wn*64 + ng*16 + (sub>>1)*8 + li ; kb = (sub&1)*16
    unsigned boff[4];
#pragma unroll
    for (int ng = 0; ng < 4; ng++) {
        unsigned r = (unsigned)(wn * 64 + ng * 16 + (sub >> 1) * 8 + li);
        boff[ng] = (r << 7) + (unsigned)((sub & 1) << 4);
        boff[ng] ^= (r & 7u) << 4;
    }

    // cp.async issue lambda-ish via macro: 4 A chunks + 4 B chunks per thread
    int ld_row = tid >> 3;            // base row for loads (tid..)
    int ld_kb  = (tid & 7) << 4;      // byte offset in 128B row

    float d[2][8][4];
#pragma unroll
    for (int mt = 0; mt < 2; mt++)
#pragma unroll
        for (int nt = 0; nt < 8; nt++)
#pragma unroll
            for (int j = 0; j < 4; j++) d[mt][nt][j] = 0.f;

#define ISSUE(it_) do {                                                        \
    int p_  = (it_) / nk, kc_ = (it_) - p_ * nk;                               \
    const __nv_bfloat16* Ap_ = (p_ >= 2) ? Al : Ah;                            \
    const __nv_bfloat16* Bp_ = (p_ & 1)  ? Bl : Bh;                            \
    unsigned ab_ = tile_u + (unsigned)((it_) & 1) * 32768u;                    \
    unsigned bb_ = ab_ + 16384u;                                               \
    const __nv_bfloat16* As_ = Ap_ + (size_t)bm * K + (kc_ << 6);              \
    const __nv_bfloat16* Bs_ = Bp_ + (size_t)bn * K + (kc_ << 6);              \
    _Pragma("unroll")                                                          \
    for (int i_ = 0; i_ < 4; i_++) {                                           \
        int row_ = ld_row + i_ * 32;                                           \
        unsigned so_ = GSW((unsigned)((row_ << 7) | ld_kb));                   \
        cp16(ab_ + so_, (const char*)(As_ + (size_t)row_ * K) + ld_kb);        \
        cp16(bb_ + so_, (const char*)(Bs_ + (size_t)row_ * K) + ld_kb);        \
    }                                                                          \
    cpcommit();                                                                \
} while (0)

    ISSUE(0);
    if (total > 1) ISSUE(1);

    for (int it = 0; it < total; ++it) {
        if (it + 1 < total) cpwait<1>(); else cpwait<0>();
        __syncthreads();
        unsigned ab = tile_u + (unsigned)(it & 1) * 32768u;
        unsigned bb = ab + 16384u;
#pragma unroll
        for (int ks = 0; ks < 4; ks++) {
            unsigned kx = (unsigned)(ks << 5);
            unsigned a[2][4], b[4][4];
#pragma unroll
            for (int mt = 0; mt < 2; mt++) ldsm4(a[mt], ab + (aoff[mt] ^ kx));
#pragma unroll
            for (int ng = 0; ng < 4; ng++) ldsm4(b[ng], bb + (boff[ng] ^ kx));
#pragma unroll
            for (int mt = 0; mt < 2; mt++)
#pragma unroll
                for (int ng = 0; ng < 4; ng++) {
                    mma16816(d[mt][2 * ng + 0], a[mt], &b[ng][0]);
                    mma16816(d[mt][2 * ng + 1], a[mt], &b[ng][2]);
                }
        }
        __syncthreads();
        if (it + 2 < total) ISSUE(it + 2);
    }
#undef ISSUE

    // epilogue: direct register -> global (fragment layout)
    int qr = lane >> 2;           // 0..7
    int qc = (lane & 3) << 1;     // 0,2,4,6
#pragma unroll
    for (int mt = 0; mt < 2; mt++) {
#pragma unroll
        for (int nt = 0; nt < 8; nt++) {
            int r0 = bm + wm * 32 + mt * 16 + qr;
            int c  = bn + wn * 64 + nt * 8 + qc;
            float v[4];
#pragma unroll
            for (int j = 0; j < 4; j++) v[j] = d[mt][nt][j];
            if (EPI == 2 || EPI == 3) {
                float2 bv = *(const float2*)(bias + c);
                v[0] += bv.x; v[1] += bv.y; v[2] += bv.x; v[3] += bv.y;
            }
            if (EPI == 2) {
#pragma unroll
                for (int j = 0; j < 4; j++)
                    v[j] = 0.5f * v[j] * (1.0f + erff(v[j] * 0.7071067811865475f));
            }
            if (EPI == 1 || EPI == 3) {
                float2 r1 = *(const float2*)(R + (size_t)r0 * N + c);
                float2 r2 = *(const float2*)(R + (size_t)(r0 + 8) * N + c);
                v[0] += r1.x; v[1] += r1.y; v[2] += r2.x; v[3] += r2.y;
            }
            if (OUTB) {
                *(__nv_bfloat162*)(Cb + (size_t)r0 * N + c) =
                    __floats2bfloat162_rn(v[0], v[1]);
                *(__nv_bfloat162*)(Cb + (size_t)(r0 + 8) * N + c) =
                    __floats2bfloat162_rn(v[2], v[3]);
            } else {
                *(float2*)(Cf + (size_t)r0 * N + c) = make_float2(v[0], v[1]);
                *(float2*)(Cf + (size_t)(r0 + 8) * N + c) = make_float2(v[2], v[3]);
            }
        }
    }
}

// ---------------- LayerNorm -> bf16 hi(/lo) ----------------------------------
template <int WLO>
__global__ __launch_bounds__(256) void ln_bf16_kernel(
    const float* __restrict__ x, const float* __restrict__ g,
    const float* __restrict__ b,
    __nv_bfloat16* __restrict__ zh, __nv_bfloat16* __restrict__ zl)
{
    int row = blockIdx.x;
    const float* xr = x + (size_t)row * DD;
    int tid = threadIdx.x;
    float v[4];
    float sum = 0.f, sq = 0.f;
#pragma unroll
    for (int i = 0; i < 4; i++) {
        v[i] = xr[tid + i * 256];
        sum += v[i]; sq += v[i] * v[i];
    }
#pragma unroll
    for (int o = 16; o > 0; o >>= 1) {
        sum += __shfl_xor_sync(0xffffffffu, sum, o);
        sq  += __shfl_xor_sync(0xffffffffu, sq,  o);
    }
    __shared__ float red[2][8];
    int w = tid >> 5, l = tid & 31;
    if (l == 0) { red[0][w] = sum; red[1][w] = sq; }
    __syncthreads();
    if (tid < 32) {
        float s = (tid < 8) ? red[0][tid] : 0.f;
        float q = (tid < 8) ? red[1][tid] : 0.f;
#pragma unroll
        for (int o = 4; o > 0; o >>= 1) {
            s += __shfl_xor_sync(0xffffffffu, s, o);
            q += __shfl_xor_sync(0xffffffffu, q, o);
        }
        if (tid == 0) { red[0][0] = s; red[1][0] = q; }
    }
    __syncthreads();
    float mu   = red[0][0] * (1.f / DD);
    float var  = red[1][0] * (1.f / DD) - mu * mu;
    float rstd = rsqrtf(var + 1e-5f);
#pragma unroll
    for (int i = 0; i < 4; i++) {
        int c = tid + i * 256;
        float y = (v[i] - mu) * rstd * g[c] + b[c];
        __nv_bfloat16 hh = __float2bfloat16(y);
        zh[(size_t)row * DD + c] = hh;
        if (WLO)
            zl[(size_t)row * DD + c] = __float2bfloat16(y - __bfloat162float(hh));
    }
}

// ---------------- fp32 -> bf16 hi/lo elementwise -----------------------------
__global__ __launch_bounds__(256) void split_kernel(
    const float2* __restrict__ x, __nv_bfloat162* __restrict__ h,
    __nv_bfloat162* __restrict__ l, int n2)
{
    int i = blockIdx.x * 256 + threadIdx.x;
    if (i >= n2) return;
    float2 v = x[i];
    __nv_bfloat16 a = __float2bfloat16(v.x), b = __float2bfloat16(v.y);
    h[i] = __halves2bfloat162(a, b);
    l[i] = __halves2bfloat162(__float2bfloat16(v.x - __bfloat162float(a)),
                              __float2bfloat16(v.y - __bfloat162float(b)));
}

// ---------------- weight transpose W[K,N] -> T[N,K] bf16 hi(/lo) -------------
template <int SPLIT>
__global__ __launch_bounds__(256) void transpose_kernel(
    const float* __restrict__ W, __nv_bfloat16* __restrict__ Th,
    __nv_bfloat16* __restrict__ Tl, int K, int N)
{
    __shared__ float t[32][33];
    int tx = threadIdx.x & 31, ty0 = threadIdx.x >> 5;
    int k0 = blockIdx.y * 32, n0 = blockIdx.x * 32;
#pragma unroll
    for (int i = 0; i < 4; i++) {
        int ty = ty0 + i * 8;
        t[ty][tx] = W[(size_t)(k0 + ty) * N + n0 + tx];
    }
    __syncthreads();
#pragma unroll
    for (int i = 0; i < 4; i++) {
        int ty = ty0 + i * 8;
        float v = t[tx][ty];
        __nv_bfloat16 hh = __float2bfloat16(v);
        Th[(size_t)(n0 + ty) * K + k0 + tx] = hh;
        if (SPLIT)
            Tl[(size_t)(n0 + ty) * K + k0 + tx] =
                __float2bfloat16(v - __bfloat162float(hh));
    }
}

// ---------------- Flash attention (fp32, online softmax) ---------------------
#define FA_PAD 68
extern __shared__ float fa_smem[];

__global__ __launch_bounds__(256) void flash_kernel(
    const float* __restrict__ qkv, const float* __restrict__ mask,
    float* __restrict__ ctx)
{
    float (*Qs)[FA_PAD]  = (float(*)[FA_PAD])(fa_smem);
    float (*KsT)[FA_PAD] = (float(*)[FA_PAD])(fa_smem + 64 * FA_PAD);
    float (*Vs)[FA_PAD]  = (float(*)[FA_PAD])(fa_smem + 2 * 64 * FA_PAD);
    float (*Ps)[FA_PAD]  = (float(*)[FA_PAD])(fa_smem + 3 * 64 * FA_PAD);
    float* mk            = fa_smem + 4 * 64 * FA_PAD;

    int tid = threadIdx.x;
    int tx = tid & 15, ty = tid >> 4;
    int bh = blockIdx.y;
    int n = bh >> 4, h = bh & 15;
    size_t base = (size_t)n * TT * (3 * DD);
    int q0 = blockIdx.x * 64;

#pragma unroll
    for (int i = 0; i < 4; i++) {
        int q  = tid + i * 256;
        int r  = q >> 4;
        int d4 = (q & 15) * 4;
        float4 v = *(const float4*)(qkv + base + (size_t)(q0 + r) * (3 * DD) + h * DKK + d4);
        const float sc = 0.125f;
        Qs[r][d4 + 0] = v.x * sc; Qs[r][d4 + 1] = v.y * sc;
        Qs[r][d4 + 2] = v.z * sc; Qs[r][d4 + 3] = v.w * sc;
    }

    float m_i[4], l_i[4], oacc[4][4];
#pragma unroll
    for (int i = 0; i < 4; i++) {
        m_i[i] = -3.0e38f; l_i[i] = 0.f;
#pragma unroll
        for (int j = 0; j < 4; j++) oacc[i][j] = 0.f;
    }

    for (int s0 = 0; s0 < TT; s0 += 64) {
        __syncthreads();
#pragma unroll
        for (int i = 0; i < 4; i++) {
            int q  = tid + i * 256;
            int r  = q >> 4;
            int d4 = (q & 15) * 4;
            const float* tok = qkv + base + (size_t)(s0 + r) * (3 * DD) + h * DKK;
            float4 kv = *(const float4*)(tok + DD + d4);
            KsT[d4 + 0][r] = kv.x; KsT[d4 + 1][r] = kv.y;
            KsT[d4 + 2][r] = kv.z; KsT[d4 + 3][r] = kv.w;
            float4 vv = *(const float4*)(tok + 2 * DD + d4);
            *(float4*)(&Vs[r][d4]) = vv;
        }
        if (tid < 64) mk[tid] = mask[(size_t)n * TT + s0 + tid];
        __syncthreads();

        float s[4][4];
#pragma unroll
        for (int i = 0; i < 4; i++)
#pragma unroll
            for (int j = 0; j < 4; j++) s[i][j] = mk[tx * 4 + j];
#pragma unroll
        for (int dd = 0; dd < 64; dd++) {
            float a[4], bb[4];
#pragma unroll
            for (int i = 0; i < 4; i++) a[i] = Qs[ty * 4 + i][dd];
            *(float4*)bb = *(float4*)(&KsT[dd][tx * 4]);
#pragma unroll
            for (int i = 0; i < 4; i++)
#pragma unroll
                for (int j = 0; j < 4; j++)
                    s[i][j] = fmaf(a[i], bb[j], s[i][j]);
        }

#pragma unroll
        for (int i = 0; i < 4; i++) {
            float mx = fmaxf(fmaxf(s[i][0], s[i][1]), fmaxf(s[i][2], s[i][3]));
#pragma unroll
            for (int o = 8; o > 0; o >>= 1)
                mx = fmaxf(mx, __shfl_xor_sync(0xffffffffu, mx, o, 16));
            float mnew  = fmaxf(m_i[i], mx);
            float alpha = __expf(m_i[i] - mnew);
            float rsum = 0.f;
#pragma unroll
            for (int j = 0; j < 4; j++) {
                s[i][j] = __expf(s[i][j] - mnew);
                rsum += s[i][j];
            }
#pragma unroll
            for (int o = 8; o > 0; o >>= 1)
                rsum += __shfl_xor_sync(0xffffffffu, rsum, o, 16);
            l_i[i] = l_i[i] * alpha + rsum;
            m_i[i] = mnew;
#pragma unroll
            for (int j = 0; j < 4; j++) oacc[i][j] *= alpha;
            *(float4*)(&Ps[ty * 4 + i][tx * 4]) = *(float4*)(&s[i][0]);
        }
        __syncthreads();

#pragma unroll
        for (int ss = 0; ss < 64; ss++) {
            float p[4], vv[4];
#pragma unroll
            for (int i = 0; i < 4; i++) p[i] = Ps[ty * 4 + i][ss];
            *(float4*)vv = *(float4*)(&Vs[ss][tx * 4]);
#pragma unroll
            for (int i = 0; i < 4; i++)
#pragma unroll
                for (int j = 0; j < 4; j++)
                    oacc[i][j] = fmaf(p[i], vv[j], oacc[i][j]);
        }
    }

#pragma unroll
    for (int i = 0; i < 4; i++) {
        float inv = 1.f / l_i[i];
        int r = q0 + ty * 4 + i;
        float4 ov = make_float4(oacc[i][0] * inv, oacc[i][1] * inv,
                                oacc[i][2] * inv, oacc[i][3] * inv);
        *(float4*)(ctx + ((size_t)n * TT + r) * DD + h * DKK + tx * 4) = ov;
    }
}

// ---------------- launch -----------------------------------------------------
extern "C" void kernel_launch(void* const* d_in, const int* in_sizes, int n_in,
                              void* d_out, int out_size)
{
    const float* x     = (const float*)d_in[0];
    const float* mask  = (const float*)d_in[1];
    const float* Wqkv  = (const float*)d_in[2];
    const float* Wout  = (const float*)d_in[3];
    const float* ln1_g = (const float*)d_in[4];
    const float* ln1_b = (const float*)d_in[5];
    const float* ln2_g = (const float*)d_in[6];
    const float* ln2_b = (const float*)d_in[7];
    const float* W1    = (const float*)d_in[8];
    const float* b1    = (const float*)d_in[9];
    const float* W2    = (const float*)d_in[10];
    const float* b2    = (const float*)d_in[11];
    float* out = (float*)d_out;

    float *qkv, *ctx, *x1;
    __nv_bfloat16 *zh, *zl, *ch, *cl, *hb, *wqh, *wql, *woh, *wol, *w1t, *w2t;
    cudaGetSymbolAddress((void**)&qkv, g_qkv);
    cudaGetSymbolAddress((void**)&ctx, g_ctx);
    cudaGetSymbolAddress((void**)&x1,  g_x1);
    cudaGetSymbolAddress((void**)&zh,  g_zh);
    cudaGetSymbolAddress((void**)&zl,  g_zl);
    cudaGetSymbolAddress((void**)&ch,  g_ch);
    cudaGetSymbolAddress((void**)&cl,  g_cl);
    cudaGetSymbolAddress((void**)&hb,  g_hb);
    cudaGetSymbolAddress((void**)&wqh, g_wqh);
    cudaGetSymbolAddress((void**)&wql, g_wql);
    cudaGetSymbolAddress((void**)&woh, g_woh);
    cudaGetSymbolAddress((void**)&wol, g_wol);
    cudaGetSymbolAddress((void**)&w1t, g_w1t);
    cudaGetSymbolAddress((void**)&w2t, g_w2t);

    const int fa_smem_bytes = (4 * 64 * FA_PAD + 64) * (int)sizeof(float);
    cudaFuncSetAttribute(flash_kernel,
                         cudaFuncAttributeMaxDynamicSharedMemorySize, fa_smem_bytes);
    cudaFuncSetAttribute(hmma_gemm<3, 0, 0>,
                         cudaFuncAttributeMaxDynamicSharedMemorySize, GEMM_SMEM);
    cudaFuncSetAttribute(hmma_gemm<3, 1, 0>,
                         cudaFuncAttributeMaxDynamicSharedMemorySize, GEMM_SMEM);
    cudaFuncSetAttribute(hmma_gemm<1, 2, 1>,
                         cudaFuncAttributeMaxDynamicSharedMemorySize, GEMM_SMEM);
    cudaFuncSetAttribute(hmma_gemm<1, 3, 0>,
                         cudaFuncAttributeMaxDynamicSharedMemorySize, GEMM_SMEM);

    // 0. weight transposes + bf16 split
    transpose_kernel<1><<<dim3(3 * DD / 32, DD / 32), 256>>>(Wqkv, wqh, wql, DD, 3 * DD);
    transpose_kernel<1><<<dim3(DD / 32, DD / 32),     256>>>(Wout, woh, wol, DD, DD);
    transpose_kernel<0><<<dim3(4 * DD / 32, DD / 32), 256>>>(W1, w1t, nullptr, DD, 4 * DD);
    transpose_kernel<0><<<dim3(DD / 32, 4 * DD / 32), 256>>>(W2, w2t, nullptr, 4 * DD, DD);

    // 1. LN1 -> bf16 hi/lo
    ln_bf16_kernel<1><<<MTOK, 256>>>(x, ln1_g, ln1_b, zh, zl);
    // 2. QKV = z @ Wqkv  (3-pass split bf16)
    hmma_gemm<3, 0, 0><<<dim3(3 * DD / 128, MTOK / 128), 256, GEMM_SMEM>>>(
        zh, zl, wqh, wql, nullptr, nullptr, qkv, nullptr, MTOK, 3 * DD, DD);
    // 3. attention (fp32)
    flash_kernel<<<dim3(TT / 64, NB * HH), 256, fa_smem_bytes>>>(qkv, mask, ctx);
    // 4. ctx -> bf16 hi/lo
    split_kernel<<<(MTOK * DD / 2 + 255) / 256, 256>>>(
        (const float2*)ctx, (__nv_bfloat162*)ch, (__nv_bfloat162*)cl, MTOK * DD / 2);
    // 5. x1 = x + ctx @ Wout  (3-pass split)
    hmma_gemm<3, 1, 0><<<dim3(DD / 128, MTOK / 128), 256, GEMM_SMEM>>>(
        ch, cl, woh, wol, x, nullptr, x1, nullptr, MTOK, DD, DD);
    // 6. LN2 -> bf16 hi
    ln_bf16_kernel<0><<<MTOK, 256>>>(x1, ln2_g, ln2_b, zh, nullptr);
    // 7. h = gelu(z2 @ W1 + b1) -> bf16
    hmma_gemm<1, 2, 1><<<dim3(4 * DD / 128, MTOK / 128), 256, GEMM_SMEM>>>(
        zh, nullptr, w1t, nullptr, nullptr, b1, nullptr, hb, MTOK, 4 * DD, DD);
    // 8. out = x1 + h @ W2 + b2
    hmma_gemm<1, 3, 0><<<dim3(DD / 128, MTOK / 128), 256, GEMM_SMEM>>>(
        hb, nullptr, w2t, nullptr, x1, b2, out, nullptr, MTOK, DD, 4 * DD);
}

// round 10
// speedup vs baseline: 6.5551x; 1.9121x over previous
#include <cuda_runtime.h>
#include <cuda_bf16.h>
#include <math.h>

// Problem constants
#define NB 4
#define TT 2048
#define DD 1024
#define HH 16
#define DKK 64
#define MTOK (NB*TT)          // 8192 tokens

// ---------------- scratch (device globals; no allocation allowed) -----------
__device__ float g_x1 [MTOK * DD];               // 32 MB fp32
__device__ __nv_bfloat16 g_qh [MTOK * 3 * DD];   // qkv hi (48 MB)
__device__ __nv_bfloat16 g_ql [MTOK * 3 * DD];   // qkv lo
__device__ __nv_bfloat16 g_zh [MTOK * DD];       // LN out hi
__device__ __nv_bfloat16 g_zl [MTOK * DD];       // LN out lo
__device__ __nv_bfloat16 g_ch [MTOK * DD];       // ctx hi
__device__ __nv_bfloat16 g_cl [MTOK * DD];       // ctx lo
__device__ __nv_bfloat16 g_hb [MTOK * 4 * DD];   // FFN hidden (bf16)
__device__ __nv_bfloat16 g_wqh[3 * DD * DD];     // Wqkv^T hi  [3072,1024]
__device__ __nv_bfloat16 g_wql[3 * DD * DD];
__device__ __nv_bfloat16 g_woh[DD * DD];         // Wout^T hi  [1024,1024]
__device__ __nv_bfloat16 g_wol[DD * DD];
__device__ __nv_bfloat16 g_w1t[4 * DD * DD];     // W1^T [4096,1024]
__device__ __nv_bfloat16 g_w2t[DD * 4 * DD];     // W2^T [1024,4096]

// ---------------- PTX helpers ------------------------------------------------
__device__ __forceinline__ unsigned smem_u32(const void* p) {
    unsigned a;
    asm("{ .reg .u64 t; cvta.to.shared.u64 t, %1; cvt.u32.u64 %0, t; }"
        : "=r"(a) : "l"(p));
    return a;
}
__device__ __forceinline__ void cp16(unsigned dst, const void* src) {
    asm volatile("cp.async.cg.shared.global [%0], [%1], 16;"
                 :: "r"(dst), "l"(src) : "memory");
}
__device__ __forceinline__ void cpcommit() {
    asm volatile("cp.async.commit_group;" ::: "memory");
}
template <int N> __device__ __forceinline__ void cpwait() {
    asm volatile("cp.async.wait_group %0;" :: "n"(N) : "memory");
}
__device__ __forceinline__ void ldsm4(unsigned* r, unsigned addr) {
    asm volatile("ldmatrix.sync.aligned.m8n8.x4.shared.b16 {%0,%1,%2,%3}, [%4];"
                 : "=r"(r[0]), "=r"(r[1]), "=r"(r[2]), "=r"(r[3]) : "r"(addr));
}
__device__ __forceinline__ void ldsm4t(unsigned* r, unsigned addr) {
    asm volatile("ldmatrix.sync.aligned.m8n8.x4.trans.shared.b16 {%0,%1,%2,%3}, [%4];"
                 : "=r"(r[0]), "=r"(r[1]), "=r"(r[2]), "=r"(r[3]) : "r"(addr));
}
__device__ __forceinline__ void mma16816(float* d, const unsigned* a,
                                         const unsigned* b) {
    asm volatile(
        "mma.sync.aligned.m16n8k16.row.col.f32.bf16.bf16.f32 "
        "{%0,%1,%2,%3}, {%4,%5,%6,%7}, {%8,%9}, {%0,%1,%2,%3};"
        : "+f"(d[0]), "+f"(d[1]), "+f"(d[2]), "+f"(d[3])
        : "r"(a[0]), "r"(a[1]), "r"(a[2]), "r"(a[3]), "r"(b[0]), "r"(b[1]));
}
__device__ __forceinline__ unsigned bf2u(__nv_bfloat162 v) {
    union { __nv_bfloat162 b; unsigned u; } c; c.b = v; return c.u;
}

#define GSW(off) ((off) ^ ((((unsigned)(off)) >> 3) & 0x70u))

// ---------------- HMMA bf16 GEMM: C[M,N] = sum_passes A@B^T  -----------------
// A[M,K], B[N,K] K-major bf16. Tile 128x128, K-chunk 64, double-buffered.
// EPI: 0 none, 1 +R, 2 +bias,gelu, 3 +bias+R.
// OUTB: 0 fp32 Cf, 1 bf16 Cb, 2 bf16 hi->Cb + lo->Cb2.
#define GEMM_SMEM (65536 + 1024)

template <int NPASS, int EPI, int OUTB>
__global__ __launch_bounds__(256) void hmma_gemm(
    const __nv_bfloat16* __restrict__ Ah, const __nv_bfloat16* __restrict__ Al,
    const __nv_bfloat16* __restrict__ Bh, const __nv_bfloat16* __restrict__ Bl,
    const float* __restrict__ R, const float* __restrict__ bias,
    float* __restrict__ Cf, __nv_bfloat16* __restrict__ Cb,
    __nv_bfloat16* __restrict__ Cb2,
    int M, int N, int K)
{
    extern __shared__ char dsm[];
    unsigned smb    = smem_u32(dsm);
    unsigned tile_u = (smb + 1023u) & ~1023u;

    int tid = threadIdx.x, wid = tid >> 5, lane = tid & 31;
    int wm = wid & 3, wn = wid >> 2;
    int bm = blockIdx.y << 7, bn = blockIdx.x << 7;

    const int nk = K >> 6;
    const int total = NPASS * nk;

    int li  = lane & 7, sub = lane >> 3;
    unsigned aoff[2];
#pragma unroll
    for (int mt = 0; mt < 2; mt++) {
        unsigned r = (unsigned)(wm * 32 + mt * 16 + (sub & 1) * 8 + li);
        aoff[mt] = (r << 7) + (unsigned)((sub >> 1) << 4);
        aoff[mt] ^= (r & 7u) << 4;
    }
    unsigned boff[4];
#pragma unroll
    for (int ng = 0; ng < 4; ng++) {
        unsigned r = (unsigned)(wn * 64 + ng * 16 + (sub >> 1) * 8 + li);
        boff[ng] = (r << 7) + (unsigned)((sub & 1) << 4);
        boff[ng] ^= (r & 7u) << 4;
    }

    int ld_row = tid >> 3;
    int ld_kb  = (tid & 7) << 4;

    float d[2][8][4];
#pragma unroll
    for (int mt = 0; mt < 2; mt++)
#pragma unroll
        for (int nt = 0; nt < 8; nt++)
#pragma unroll
            for (int j = 0; j < 4; j++) d[mt][nt][j] = 0.f;

#define ISSUE(it_) do {                                                        \
    int p_  = (it_) / nk, kc_ = (it_) - p_ * nk;                               \
    const __nv_bfloat16* Ap_ = (p_ >= 2) ? Al : Ah;                            \
    const __nv_bfloat16* Bp_ = (p_ & 1)  ? Bl : Bh;                            \
    unsigned ab_ = tile_u + (unsigned)((it_) & 1) * 32768u;                    \
    unsigned bb_ = ab_ + 16384u;                                               \
    const __nv_bfloat16* As_ = Ap_ + (size_t)bm * K + (kc_ << 6);              \
    const __nv_bfloat16* Bs_ = Bp_ + (size_t)bn * K + (kc_ << 6);              \
    _Pragma("unroll")                                                          \
    for (int i_ = 0; i_ < 4; i_++) {                                           \
        int row_ = ld_row + i_ * 32;                                           \
        unsigned so_ = GSW((unsigned)((row_ << 7) | ld_kb));                   \
        cp16(ab_ + so_, (const char*)(As_ + (size_t)row_ * K) + ld_kb);        \
        cp16(bb_ + so_, (const char*)(Bs_ + (size_t)row_ * K) + ld_kb);        \
    }                                                                          \
    cpcommit();                                                                \
} while (0)

    ISSUE(0);
    if (total > 1) ISSUE(1);

    for (int it = 0; it < total; ++it) {
        if (it + 1 < total) cpwait<1>(); else cpwait<0>();
        __syncthreads();
        unsigned ab = tile_u + (unsigned)(it & 1) * 32768u;
        unsigned bb = ab + 16384u;
#pragma unroll
        for (int ks = 0; ks < 4; ks++) {
            unsigned kx = (unsigned)(ks << 5);
            unsigned a[2][4], b[4][4];
#pragma unroll
            for (int mt = 0; mt < 2; mt++) ldsm4(a[mt], ab + (aoff[mt] ^ kx));
#pragma unroll
            for (int ng = 0; ng < 4; ng++) ldsm4(b[ng], bb + (boff[ng] ^ kx));
#pragma unroll
            for (int mt = 0; mt < 2; mt++)
#pragma unroll
                for (int ng = 0; ng < 4; ng++) {
                    mma16816(d[mt][2 * ng + 0], a[mt], &b[ng][0]);
                    mma16816(d[mt][2 * ng + 1], a[mt], &b[ng][2]);
                }
        }
        __syncthreads();
        if (it + 2 < total) ISSUE(it + 2);
    }
#undef ISSUE

    int qr = lane >> 2;
    int qc = (lane & 3) << 1;
#pragma unroll
    for (int mt = 0; mt < 2; mt++) {
#pragma unroll
        for (int nt = 0; nt < 8; nt++) {
            int r0 = bm + wm * 32 + mt * 16 + qr;
            int c  = bn + wn * 64 + nt * 8 + qc;
            float v[4];
#pragma unroll
            for (int j = 0; j < 4; j++) v[j] = d[mt][nt][j];
            if (EPI == 2 || EPI == 3) {
                float2 bv = *(const float2*)(bias + c);
                v[0] += bv.x; v[1] += bv.y; v[2] += bv.x; v[3] += bv.y;
            }
            if (EPI == 2) {
#pragma unroll
                for (int j = 0; j < 4; j++)
                    v[j] = 0.5f * v[j] * (1.0f + erff(v[j] * 0.7071067811865475f));
            }
            if (EPI == 1 || EPI == 3) {
                float2 r1 = *(const float2*)(R + (size_t)r0 * N + c);
                float2 r2 = *(const float2*)(R + (size_t)(r0 + 8) * N + c);
                v[0] += r1.x; v[1] += r1.y; v[2] += r2.x; v[3] += r2.y;
            }
            if (OUTB == 1) {
                *(__nv_bfloat162*)(Cb + (size_t)r0 * N + c) =
                    __floats2bfloat162_rn(v[0], v[1]);
                *(__nv_bfloat162*)(Cb + (size_t)(r0 + 8) * N + c) =
                    __floats2bfloat162_rn(v[2], v[3]);
            } else if (OUTB == 2) {
                __nv_bfloat162 h0 = __floats2bfloat162_rn(v[0], v[1]);
                __nv_bfloat162 h1 = __floats2bfloat162_rn(v[2], v[3]);
                *(__nv_bfloat162*)(Cb + (size_t)r0 * N + c) = h0;
                *(__nv_bfloat162*)(Cb + (size_t)(r0 + 8) * N + c) = h1;
                *(__nv_bfloat162*)(Cb2 + (size_t)r0 * N + c) =
                    __floats2bfloat162_rn(v[0] - __bfloat162float(h0.x),
                                          v[1] - __bfloat162float(h0.y));
                *(__nv_bfloat162*)(Cb2 + (size_t)(r0 + 8) * N + c) =
                    __floats2bfloat162_rn(v[2] - __bfloat162float(h1.x),
                                          v[3] - __bfloat162float(h1.y));
            } else {
                *(float2*)(Cf + (size_t)r0 * N + c) = make_float2(v[0], v[1]);
                *(float2*)(Cf + (size_t)(r0 + 8) * N + c) = make_float2(v[2], v[3]);
            }
        }
    }
}

// ---------------- HMMA flash attention --------------------------------------
// CTA: 128 q-rows of one (n,h); iterate 32 s-blocks of 64. 8 warps x 16 rows.
// QK^T 3-pass split bf16, online softmax fp32, PV 3-pass split bf16.
// SMEM: QH 0 (16K), QL 16K, buf b at 32K+b*32K: {KH,KL,VH,VL} 8K each,
//       mask at 96K + b*256. Total 98816 B.
#define FK_QH   0u
#define FK_QL   16384u
#define FK_KV   32768u
#define FK_MASK 98304u
#define FK_SMEM 98816

__global__ __launch_bounds__(256) void flash_hmma(
    const __nv_bfloat16* __restrict__ qh, const __nv_bfloat16* __restrict__ ql,
    const float* __restrict__ mask,
    __nv_bfloat16* __restrict__ ch, __nv_bfloat16* __restrict__ cl)
{
    extern __shared__ char fsm[];
    unsigned sb = smem_u32(fsm);

    int tid = threadIdx.x, wid = tid >> 5, lane = tid & 31;
    int qr = lane >> 2, tig = lane & 3;
    int bh = blockIdx.y, n = bh >> 4, h = bh & 15;
    int q0 = blockIdx.x << 7;
    const float* maskp = mask + (size_t)n * TT;

    // byte base of row r of Q/K/V slice inside qkv row (6144 B per token)
    const char* qbH = (const char*)(qh + (size_t)(n * TT + q0) * 3072) + h * 128;
    const char* qbL = (const char*)(ql + (size_t)(n * TT + q0) * 3072) + h * 128;
    const char* kvH = (const char*)(qh + (size_t)n * TT * 3072) + h * 128;
    const char* kvL = (const char*)(ql + (size_t)n * TT * 3072) + h * 128;

#define FK_ISSUE(it_) do {                                                     \
    int s0_ = (it_) << 6;                                                      \
    unsigned kb_ = sb + FK_KV + (unsigned)((it_) & 1) * 32768u;                \
    _Pragma("unroll")                                                          \
    for (int i_ = 0; i_ < 2; i_++) {                                           \
        int v_ = tid + (i_ << 8);                                              \
        int row_ = v_ >> 3; int kb2_ = (v_ & 7) << 4;                          \
        unsigned so_ = GSW((unsigned)((row_ << 7) | kb2_));                    \
        size_t gb_ = (size_t)(s0_ + row_) * 6144 + kb2_;                       \
        cp16(kb_ + so_,          kvH + gb_ + 2048);                            \
        cp16(kb_ + 8192u + so_,  kvL + gb_ + 2048);                            \
        cp16(kb_ + 16384u + so_, kvH + gb_ + 4096);                            \
        cp16(kb_ + 24576u + so_, kvL + gb_ + 4096);                            \
    }                                                                          \
    if (tid < 16)                                                              \
        cp16(sb + FK_MASK + (unsigned)((it_) & 1) * 256u + (tid << 4),         \
             maskp + s0_ + tid * 4);                                           \
    cpcommit();                                                                \
} while (0)

    // prologue: Q + first KV block in group 0, second KV block in group 1
#pragma unroll
    for (int i = 0; i < 4; i++) {
        int v = tid + (i << 8);
        int row = v >> 3; int kb = (v & 7) << 4;
        unsigned so = GSW((unsigned)((row << 7) | kb));
        cp16(sb + FK_QH + so, qbH + (size_t)row * 6144 + kb);
        cp16(sb + FK_QL + so, qbL + (size_t)row * 6144 + kb);
    }
    FK_ISSUE(0);
    FK_ISSUE(1);

    // fragment offsets
    int li = lane & 7, sub = lane >> 3;
    unsigned m4 = (unsigned)li << 4;
    unsigned qoff;
    {
        unsigned r = (unsigned)(wid * 16 + (sub & 1) * 8 + li);
        qoff = (r << 7) + ((unsigned)((sub >> 1) << 4) ^ m4);
    }
    unsigned koff[4];
#pragma unroll
    for (int ng = 0; ng < 4; ng++) {
        unsigned r = (unsigned)(ng * 16 + (sub >> 1) * 8 + li);
        koff[ng] = (r << 7) + ((unsigned)((sub & 1) << 4) ^ m4);
    }
    unsigned vrow = (unsigned)((sub & 1) * 8 + li) << 7;
    unsigned vb[4];
#pragma unroll
    for (int dt = 0; dt < 4; dt++)
        vb[dt] = ((unsigned)((sub >> 1) << 4) + (unsigned)(dt << 5)) ^ m4;

    float sS[8][4], oO[8][4];
    float mM[2] = {-1e30f, -1e30f}, lL[2] = {0.f, 0.f};
#pragma unroll
    for (int nt = 0; nt < 8; nt++)
#pragma unroll
        for (int j = 0; j < 4; j++) oO[nt][j] = 0.f;

    for (int it = 0; it < TT / 64; ++it) {
        if (it == TT / 64 - 1) cpwait<0>(); else cpwait<1>();
        __syncthreads();
        unsigned kb0 = sb + FK_KV + (unsigned)(it & 1) * 32768u;

        // ---- S = Q@K^T (3-pass) ----
#pragma unroll
        for (int nt = 0; nt < 8; nt++)
#pragma unroll
            for (int j = 0; j < 4; j++) sS[nt][j] = 0.f;
#pragma unroll
        for (int ks = 0; ks < 4; ks++) {
            unsigned kx = (unsigned)(ks << 5);
            unsigned aH[4], aL[4];
            ldsm4(aH, sb + FK_QH + (qoff ^ kx));
            ldsm4(aL, sb + FK_QL + (qoff ^ kx));
#pragma unroll
            for (int ng = 0; ng < 4; ng++) {
                unsigned bH[4], bL[4];
                ldsm4(bH, kb0 + (koff[ng] ^ kx));
                ldsm4(bL, kb0 + 8192u + (koff[ng] ^ kx));
                mma16816(sS[2 * ng + 0], aH, &bH[0]);
                mma16816(sS[2 * ng + 1], aH, &bH[2]);
                mma16816(sS[2 * ng + 0], aH, &bL[0]);
                mma16816(sS[2 * ng + 1], aH, &bL[2]);
                mma16816(sS[2 * ng + 0], aL, &bH[0]);
                mma16816(sS[2 * ng + 1], aL, &bH[2]);
            }
        }

        // ---- scale + mask ----
        const float* mbuf = (const float*)(fsm + FK_MASK + (it & 1) * 256);
#pragma unroll
        for (int nt = 0; nt < 8; nt++) {
            float2 mv = *(const float2*)(mbuf + nt * 8 + 2 * tig);
            sS[nt][0] = fmaf(sS[nt][0], 0.125f, mv.x);
            sS[nt][1] = fmaf(sS[nt][1], 0.125f, mv.y);
            sS[nt][2] = fmaf(sS[nt][2], 0.125f, mv.x);
            sS[nt][3] = fmaf(sS[nt][3], 0.125f, mv.y);
        }

        // ---- online softmax (2 rows/thread: regs {0,1} row qr, {2,3} qr+8) --
#pragma unroll
        for (int i = 0; i < 2; i++) {
            int ib = 2 * i;
            float mx = -1e30f;
#pragma unroll
            for (int nt = 0; nt < 8; nt++)
                mx = fmaxf(mx, fmaxf(sS[nt][ib], sS[nt][ib + 1]));
            mx = fmaxf(mx, __shfl_xor_sync(0xffffffffu, mx, 1));
            mx = fmaxf(mx, __shfl_xor_sync(0xffffffffu, mx, 2));
            float mnew  = fmaxf(mM[i], mx);
            float alpha = __expf(mM[i] - mnew);
            float rsum = 0.f;
#pragma unroll
            for (int nt = 0; nt < 8; nt++) {
                float p0 = __expf(sS[nt][ib]     - mnew);
                float p1 = __expf(sS[nt][ib + 1] - mnew);
                sS[nt][ib] = p0; sS[nt][ib + 1] = p1;
                rsum += p0 + p1;
            }
            rsum += __shfl_xor_sync(0xffffffffu, rsum, 1);
            rsum += __shfl_xor_sync(0xffffffffu, rsum, 2);
            lL[i] = lL[i] * alpha + rsum;
            mM[i] = mnew;
#pragma unroll
            for (int nt = 0; nt < 8; nt++) {
                oO[nt][ib] *= alpha; oO[nt][ib + 1] *= alpha;
            }
        }

        // ---- O += P@V (3-pass, P from S regs) ----
#pragma unroll
        for (int kt = 0; kt < 4; kt++) {
            unsigned ah[4], al[4];
#pragma unroll
            for (int half = 0; half < 2; half++) {
                int nt = 2 * kt + half;
                __nv_bfloat162 h0 = __floats2bfloat162_rn(sS[nt][0], sS[nt][1]);
                __nv_bfloat162 h1 = __floats2bfloat162_rn(sS[nt][2], sS[nt][3]);
                ah[2 * half + 0] = bf2u(h0);
                ah[2 * half + 1] = bf2u(h1);
                al[2 * half + 0] = bf2u(__floats2bfloat162_rn(
                    sS[nt][0] - __bfloat162float(h0.x),
                    sS[nt][1] - __bfloat162float(h0.y)));
                al[2 * half + 1] = bf2u(__floats2bfloat162_rn(
                    sS[nt][2] - __bfloat162float(h1.x),
                    sS[nt][3] - __bfloat162float(h1.y)));
            }
            unsigned vkb = kb0 + 16384u + (unsigned)(kt << 11) + vrow;
#pragma unroll
            for (int dt = 0; dt < 4; dt++) {
                unsigned bv[4], bw[4];
                ldsm4t(bv, vkb + vb[dt]);
                ldsm4t(bw, vkb + 8192u + vb[dt]);
                mma16816(oO[2 * dt + 0], ah, &bv[0]);
                mma16816(oO[2 * dt + 1], ah, &bv[2]);
                mma16816(oO[2 * dt + 0], ah, &bw[0]);
                mma16816(oO[2 * dt + 1], ah, &bw[2]);
                mma16816(oO[2 * dt + 0], al, &bv[0]);
                mma16816(oO[2 * dt + 1], al, &bv[2]);
            }
        }
        __syncthreads();
        if (it + 2 < TT / 64) FK_ISSUE(it + 2);
    }
#undef FK_ISSUE

    // ---- write ctx hi/lo ----
#pragma unroll
    for (int i = 0; i < 2; i++) {
        float inv = 1.f / lL[i];
        int ib = 2 * i;
        size_t tok = (size_t)(n * TT + q0 + wid * 16 + qr + i * 8);
#pragma unroll
        for (int nt = 0; nt < 8; nt++) {
            float v0 = oO[nt][ib] * inv, v1 = oO[nt][ib + 1] * inv;
            int col = h * 64 + nt * 8 + 2 * tig;
            __nv_bfloat162 h2 = __floats2bfloat162_rn(v0, v1);
            *(__nv_bfloat162*)(ch + tok * DD + col) = h2;
            *(__nv_bfloat162*)(cl + tok * DD + col) =
                __floats2bfloat162_rn(v0 - __bfloat162float(h2.x),
                                      v1 - __bfloat162float(h2.y));
        }
    }
}

// ---------------- LayerNorm -> bf16 hi(/lo) ----------------------------------
template <int WLO>
__global__ __launch_bounds__(256) void ln_bf16_kernel(
    const float* __restrict__ x, const float* __restrict__ g,
    const float* __restrict__ b,
    __nv_bfloat16* __restrict__ zh, __nv_bfloat16* __restrict__ zl)
{
    int row = blockIdx.x;
    const float* xr = x + (size_t)row * DD;
    int tid = threadIdx.x;
    float v[4];
    float sum = 0.f, sq = 0.f;
#pragma unroll
    for (int i = 0; i < 4; i++) {
        v[i] = xr[tid + i * 256];
        sum += v[i]; sq += v[i] * v[i];
    }
#pragma unroll
    for (int o = 16; o > 0; o >>= 1) {
        sum += __shfl_xor_sync(0xffffffffu, sum, o);
        sq  += __shfl_xor_sync(0xffffffffu, sq,  o);
    }
    __shared__ float red[2][8];
    int w = tid >> 5, l = tid & 31;
    if (l == 0) { red[0][w] = sum; red[1][w] = sq; }
    __syncthreads();
    if (tid < 32) {
        float s = (tid < 8) ? red[0][tid] : 0.f;
        float q = (tid < 8) ? red[1][tid] : 0.f;
#pragma unroll
        for (int o = 4; o > 0; o >>= 1) {
            s += __shfl_xor_sync(0xffffffffu, s, o);
            q += __shfl_xor_sync(0xffffffffu, q, o);
        }
        if (tid == 0) { red[0][0] = s; red[1][0] = q; }
    }
    __syncthreads();
    float mu   = red[0][0] * (1.f / DD);
    float var  = red[1][0] * (1.f / DD) - mu * mu;
    float rstd = rsqrtf(var + 1e-5f);
#pragma unroll
    for (int i = 0; i < 4; i++) {
        int c = tid + i * 256;
        float y = (v[i] - mu) * rstd * g[c] + b[c];
        __nv_bfloat16 hh = __float2bfloat16(y);
        zh[(size_t)row * DD + c] = hh;
        if (WLO)
            zl[(size_t)row * DD + c] = __float2bfloat16(y - __bfloat162float(hh));
    }
}

// ---------------- weight transpose W[K,N] -> T[N,K] bf16 hi(/lo) -------------
template <int SPLIT>
__global__ __launch_bounds__(256) void transpose_kernel(
    const float* __restrict__ W, __nv_bfloat16* __restrict__ Th,
    __nv_bfloat16* __restrict__ Tl, int K, int N)
{
    __shared__ float t[32][33];
    int tx = threadIdx.x & 31, ty0 = threadIdx.x >> 5;
    int k0 = blockIdx.y * 32, n0 = blockIdx.x * 32;
#pragma unroll
    for (int i = 0; i < 4; i++) {
        int ty = ty0 + i * 8;
        t[ty][tx] = W[(size_t)(k0 + ty) * N + n0 + tx];
    }
    __syncthreads();
#pragma unroll
    for (int i = 0; i < 4; i++) {
        int ty = ty0 + i * 8;
        float v = t[tx][ty];
        __nv_bfloat16 hh = __float2bfloat16(v);
        Th[(size_t)(n0 + ty) * K + k0 + tx] = hh;
        if (SPLIT)
            Tl[(size_t)(n0 + ty) * K + k0 + tx] =
                __float2bfloat16(v - __bfloat162float(hh));
    }
}

// ---------------- launch -----------------------------------------------------
extern "C" void kernel_launch(void* const* d_in, const int* in_sizes, int n_in,
                              void* d_out, int out_size)
{
    const float* x     = (const float*)d_in[0];
    const float* mask  = (const float*)d_in[1];
    const float* Wqkv  = (const float*)d_in[2];
    const float* Wout  = (const float*)d_in[3];
    const float* ln1_g = (const float*)d_in[4];
    const float* ln1_b = (const float*)d_in[5];
    const float* ln2_g = (const float*)d_in[6];
    const float* ln2_b = (const float*)d_in[7];
    const float* W1    = (const float*)d_in[8];
    const float* b1    = (const float*)d_in[9];
    const float* W2    = (const float*)d_in[10];
    const float* b2    = (const float*)d_in[11];
    float* out = (float*)d_out;

    float *x1;
    __nv_bfloat16 *qh, *ql, *zh, *zl, *ch, *cl, *hb;
    __nv_bfloat16 *wqh, *wql, *woh, *wol, *w1t, *w2t;
    cudaGetSymbolAddress((void**)&x1,  g_x1);
    cudaGetSymbolAddress((void**)&qh,  g_qh);
    cudaGetSymbolAddress((void**)&ql,  g_ql);
    cudaGetSymbolAddress((void**)&zh,  g_zh);
    cudaGetSymbolAddress((void**)&zl,  g_zl);
    cudaGetSymbolAddress((void**)&ch,  g_ch);
    cudaGetSymbolAddress((void**)&cl,  g_cl);
    cudaGetSymbolAddress((void**)&hb,  g_hb);
    cudaGetSymbolAddress((void**)&wqh, g_wqh);
    cudaGetSymbolAddress((void**)&wql, g_wql);
    cudaGetSymbolAddress((void**)&woh, g_woh);
    cudaGetSymbolAddress((void**)&wol, g_wol);
    cudaGetSymbolAddress((void**)&w1t, g_w1t);
    cudaGetSymbolAddress((void**)&w2t, g_w2t);

    cudaFuncSetAttribute(flash_hmma,
                         cudaFuncAttributeMaxDynamicSharedMemorySize, FK_SMEM);
    cudaFuncSetAttribute(hmma_gemm<3, 0, 2>,
                         cudaFuncAttributeMaxDynamicSharedMemorySize, GEMM_SMEM);
    cudaFuncSetAttribute(hmma_gemm<3, 1, 0>,
                         cudaFuncAttributeMaxDynamicSharedMemorySize, GEMM_SMEM);
    cudaFuncSetAttribute(hmma_gemm<1, 2, 1>,
                         cudaFuncAttributeMaxDynamicSharedMemorySize, GEMM_SMEM);
    cudaFuncSetAttribute(hmma_gemm<1, 3, 0>,
                         cudaFuncAttributeMaxDynamicSharedMemorySize, GEMM_SMEM);

    // 0. weight transposes + bf16 split
    transpose_kernel<1><<<dim3(3 * DD / 32, DD / 32), 256>>>(Wqkv, wqh, wql, DD, 3 * DD);
    transpose_kernel<1><<<dim3(DD / 32, DD / 32),     256>>>(Wout, woh, wol, DD, DD);
    transpose_kernel<0><<<dim3(4 * DD / 32, DD / 32), 256>>>(W1, w1t, nullptr, DD, 4 * DD);
    transpose_kernel<0><<<dim3(DD / 32, 4 * DD / 32), 256>>>(W2, w2t, nullptr, 4 * DD, DD);

    // 1. LN1 -> bf16 hi/lo
    ln_bf16_kernel<1><<<MTOK, 256>>>(x, ln1_g, ln1_b, zh, zl);
    // 2. QKV = z @ Wqkv  (3-pass split bf16) -> bf16 hi/lo directly
    hmma_gemm<3, 0, 2><<<dim3(3 * DD / 128, MTOK / 128), 256, GEMM_SMEM>>>(
        zh, zl, wqh, wql, nullptr, nullptr, nullptr, qh, ql, MTOK, 3 * DD, DD);
    // 3. attention (HMMA, 3-pass QK / 3-pass PV) -> ctx hi/lo
    flash_hmma<<<dim3(TT / 128, NB * HH), 256, FK_SMEM>>>(qh, ql, mask, ch, cl);
    // 4. x1 = x + ctx @ Wout  (3-pass split)
    hmma_gemm<3, 1, 0><<<dim3(DD / 128, MTOK / 128), 256, GEMM_SMEM>>>(
        ch, cl, woh, wol, x, nullptr, x1, nullptr, nullptr, MTOK, DD, DD);
    // 5. LN2 -> bf16 hi
    ln_bf16_kernel<0><<<MTOK, 256>>>(x1, ln2_g, ln2_b, zh, nullptr);
    // 6. h = gelu(z2 @ W1 + b1) -> bf16
    hmma_gemm<1, 2, 1><<<dim3(4 * DD / 128, MTOK / 128), 256, GEMM_SMEM>>>(
        zh, nullptr, w1t, nullptr, nullptr, b1, nullptr, hb, nullptr, MTOK, 4 * DD, DD);
    // 7. out = x1 + h @ W2 + b2
    hmma_gemm<1, 3, 0><<<dim3(DD / 128, MTOK / 128), 256, GEMM_SMEM>>>(
        hb, nullptr, w2t, nullptr, x1, b2, out, nullptr, nullptr, MTOK, DD, 4 * DD);
}

// round 12
// speedup vs baseline: 6.8827x; 1.0500x over previous
#include <cuda_runtime.h>
#include <cuda_fp16.h>
#include <math.h>

// Problem constants
#define NB 4
#define TT 2048
#define DD 1024
#define HH 16
#define DKK 64
#define MTOK (NB*TT)          // 8192 tokens

// ---------------- scratch (device globals; no allocation allowed) -----------
__device__ float g_x1 [MTOK * DD];        // 32 MB fp32
__device__ __half g_qh [MTOK * 3 * DD];   // qkv hi (48 MB)
__device__ __half g_ql [MTOK * 3 * DD];   // qkv lo
__device__ __half g_zh [MTOK * DD];       // LN out hi
__device__ __half g_zl [MTOK * DD];       // LN out lo
__device__ __half g_ch [MTOK * DD];       // ctx hi
__device__ __half g_cl [MTOK * DD];       // ctx lo
__device__ __half g_hb [MTOK * 4 * DD];   // FFN hidden (fp16)
__device__ __half g_wqh[3 * DD * DD];     // Wqkv^T hi  [3072,1024]
__device__ __half g_wql[3 * DD * DD];
__device__ __half g_woh[DD * DD];         // Wout^T hi  [1024,1024]
__device__ __half g_wol[DD * DD];
__device__ __half g_w1t[4 * DD * DD];     // W1^T [4096,1024]
__device__ __half g_w2t[DD * 4 * DD];     // W2^T [1024,4096]

// ---------------- PTX helpers ------------------------------------------------
__device__ __forceinline__ unsigned smem_u32(const void* p) {
    unsigned a;
    asm("{ .reg .u64 t; cvta.to.shared.u64 t, %1; cvt.u32.u64 %0, t; }"
        : "=r"(a) : "l"(p));
    return a;
}
__device__ __forceinline__ void cp16(unsigned dst, const void* src) {
    asm volatile("cp.async.cg.shared.global [%0], [%1], 16;"
                 :: "r"(dst), "l"(src) : "memory");
}
__device__ __forceinline__ void cpcommit() {
    asm volatile("cp.async.commit_group;" ::: "memory");
}
template <int N> __device__ __forceinline__ void cpwait() {
    asm volatile("cp.async.wait_group %0;" :: "n"(N) : "memory");
}
__device__ __forceinline__ void ldsm4(unsigned* r, unsigned addr) {
    asm volatile("ldmatrix.sync.aligned.m8n8.x4.shared.b16 {%0,%1,%2,%3}, [%4];"
                 : "=r"(r[0]), "=r"(r[1]), "=r"(r[2]), "=r"(r[3]) : "r"(addr));
}
__device__ __forceinline__ void ldsm4t(unsigned* r, unsigned addr) {
    asm volatile("ldmatrix.sync.aligned.m8n8.x4.trans.shared.b16 {%0,%1,%2,%3}, [%4];"
                 : "=r"(r[0]), "=r"(r[1]), "=r"(r[2]), "=r"(r[3]) : "r"(addr));
}
__device__ __forceinline__ void mma16816(float* d, const unsigned* a,
                                         const unsigned* b) {
    asm volatile(
        "mma.sync.aligned.m16n8k16.row.col.f32.f16.f16.f32 "
        "{%0,%1,%2,%3}, {%4,%5,%6,%7}, {%8,%9}, {%0,%1,%2,%3};"
        : "+f"(d[0]), "+f"(d[1]), "+f"(d[2]), "+f"(d[3])
        : "r"(a[0]), "r"(a[1]), "r"(a[2]), "r"(a[3]), "r"(b[0]), "r"(b[1]));
}
__device__ __forceinline__ unsigned h2u(__half2 v) {
    union { __half2 h; unsigned u; } c; c.h = v; return c.u;
}

#define GSW(off) ((off) ^ ((((unsigned)(off)) >> 3) & 0x70u))

// ---------------- HMMA fp16 GEMM: C[M,N] = sum_passes A@B^T  -----------------
// A[M,K], B[N,K] K-major fp16. Tile 128x128, K-chunk 64, double-buffered.
// EPI: 0 none, 1 +R, 2 +bias,gelu, 3 +bias+R.
// OUTB: 0 fp32 Cf, 1 fp16 Cb, 2 fp16 hi->Cb + lo->Cb2.
#define GEMM_SMEM (65536 + 1024)

template <int NPASS, int EPI, int OUTB>
__global__ __launch_bounds__(256) void hmma_gemm(
    const __half* __restrict__ Ah, const __half* __restrict__ Al,
    const __half* __restrict__ Bh, const __half* __restrict__ Bl,
    const float* __restrict__ R, const float* __restrict__ bias,
    float* __restrict__ Cf, __half* __restrict__ Cb,
    __half* __restrict__ Cb2,
    int M, int N, int K)
{
    extern __shared__ char dsm[];
    unsigned smb    = smem_u32(dsm);
    unsigned tile_u = (smb + 1023u) & ~1023u;

    int tid = threadIdx.x, wid = tid >> 5, lane = tid & 31;
    int wm = wid & 3, wn = wid >> 2;
    int bm = blockIdx.y << 7, bn = blockIdx.x << 7;

    const int nk = K >> 6;
    const int total = NPASS * nk;

    int li  = lane & 7, sub = lane >> 3;
    unsigned aoff[2];
#pragma unroll
    for (int mt = 0; mt < 2; mt++) {
        unsigned r = (unsigned)(wm * 32 + mt * 16 + (sub & 1) * 8 + li);
        aoff[mt] = (r << 7) + (unsigned)((sub >> 1) << 4);
        aoff[mt] ^= (r & 7u) << 4;
    }
    unsigned boff[4];
#pragma unroll
    for (int ng = 0; ng < 4; ng++) {
        unsigned r = (unsigned)(wn * 64 + ng * 16 + (sub >> 1) * 8 + li);
        boff[ng] = (r << 7) + (unsigned)((sub & 1) << 4);
        boff[ng] ^= (r & 7u) << 4;
    }

    int ld_row = tid >> 3;
    int ld_kb  = (tid & 7) << 4;

    float d[2][8][4];
#pragma unroll
    for (int mt = 0; mt < 2; mt++)
#pragma unroll
        for (int nt = 0; nt < 8; nt++)
#pragma unroll
            for (int j = 0; j < 4; j++) d[mt][nt][j] = 0.f;

#define ISSUE(it_) do {                                                        \
    int p_  = (it_) / nk, kc_ = (it_) - p_ * nk;                               \
    const __half* Ap_ = (p_ >= 2) ? Al : Ah;                                   \
    const __half* Bp_ = (p_ & 1)  ? Bl : Bh;                                   \
    unsigned ab_ = tile_u + (unsigned)((it_) & 1) * 32768u;                    \
    unsigned bb_ = ab_ + 16384u;                                               \
    const __half* As_ = Ap_ + (size_t)bm * K + (kc_ << 6);                     \
    const __half* Bs_ = Bp_ + (size_t)bn * K + (kc_ << 6);                     \
    _Pragma("unroll")                                                          \
    for (int i_ = 0; i_ < 4; i_++) {                                           \
        int row_ = ld_row + i_ * 32;                                           \
        unsigned so_ = GSW((unsigned)((row_ << 7) | ld_kb));                   \
        cp16(ab_ + so_, (const char*)(As_ + (size_t)row_ * K) + ld_kb);        \
        cp16(bb_ + so_, (const char*)(Bs_ + (size_t)row_ * K) + ld_kb);        \
    }                                                                          \
    cpcommit();                                                                \
} while (0)

    ISSUE(0);
    if (total > 1) ISSUE(1);

    for (int it = 0; it < total; ++it) {
        if (it + 1 < total) cpwait<1>(); else cpwait<0>();
        __syncthreads();
        unsigned ab = tile_u + (unsigned)(it & 1) * 32768u;
        unsigned bb = ab + 16384u;
#pragma unroll
        for (int ks = 0; ks < 4; ks++) {
            unsigned kx = (unsigned)(ks << 5);
            unsigned a[2][4], b[4][4];
#pragma unroll
            for (int mt = 0; mt < 2; mt++) ldsm4(a[mt], ab + (aoff[mt] ^ kx));
#pragma unroll
            for (int ng = 0; ng < 4; ng++) ldsm4(b[ng], bb + (boff[ng] ^ kx));
#pragma unroll
            for (int mt = 0; mt < 2; mt++)
#pragma unroll
                for (int ng = 0; ng < 4; ng++) {
                    mma16816(d[mt][2 * ng + 0], a[mt], &b[ng][0]);
                    mma16816(d[mt][2 * ng + 1], a[mt], &b[ng][2]);
                }
        }
        __syncthreads();
        if (it + 2 < total) ISSUE(it + 2);
    }
#undef ISSUE

    int qr = lane >> 2;
    int qc = (lane & 3) << 1;
#pragma unroll
    for (int mt = 0; mt < 2; mt++) {
#pragma unroll
        for (int nt = 0; nt < 8; nt++) {
            int r0 = bm + wm * 32 + mt * 16 + qr;
            int c  = bn + wn * 64 + nt * 8 + qc;
            float v[4];
#pragma unroll
            for (int j = 0; j < 4; j++) v[j] = d[mt][nt][j];
            if (EPI == 2 || EPI == 3) {
                float2 bv = *(const float2*)(bias + c);
                v[0] += bv.x; v[1] += bv.y; v[2] += bv.x; v[3] += bv.y;
            }
            if (EPI == 2) {
#pragma unroll
                for (int j = 0; j < 4; j++)
                    v[j] = 0.5f * v[j] * (1.0f + erff(v[j] * 0.7071067811865475f));
            }
            if (EPI == 1 || EPI == 3) {
                float2 r1 = *(const float2*)(R + (size_t)r0 * N + c);
                float2 r2 = *(const float2*)(R + (size_t)(r0 + 8) * N + c);
                v[0] += r1.x; v[1] += r1.y; v[2] += r2.x; v[3] += r2.y;
            }
            if (OUTB == 1) {
                *(__half2*)(Cb + (size_t)r0 * N + c) =
                    __floats2half2_rn(v[0], v[1]);
                *(__half2*)(Cb + (size_t)(r0 + 8) * N + c) =
                    __floats2half2_rn(v[2], v[3]);
            } else if (OUTB == 2) {
                __half2 h0 = __floats2half2_rn(v[0], v[1]);
                __half2 h1 = __floats2half2_rn(v[2], v[3]);
                *(__half2*)(Cb + (size_t)r0 * N + c) = h0;
                *(__half2*)(Cb + (size_t)(r0 + 8) * N + c) = h1;
                *(__half2*)(Cb2 + (size_t)r0 * N + c) =
                    __floats2half2_rn(v[0] - __half2float(__low2half(h0)),
                                      v[1] - __half2float(__high2half(h0)));
                *(__half2*)(Cb2 + (size_t)(r0 + 8) * N + c) =
                    __floats2half2_rn(v[2] - __half2float(__low2half(h1)),
                                      v[3] - __half2float(__high2half(h1)));
            } else {
                *(float2*)(Cf + (size_t)r0 * N + c) = make_float2(v[0], v[1]);
                *(float2*)(Cf + (size_t)(r0 + 8) * N + c) = make_float2(v[2], v[3]);
            }
        }
    }
}

// ---------------- HMMA flash attention --------------------------------------
// CTA: 128 q-rows of one (n,h); iterate 32 s-blocks of 64. 8 warps x 16 rows.
// QK^T 3-pass split fp16, online softmax fp32, PV 2-pass fp16 (Ph*Vh + Ph*Vl).
// SMEM: QH 0 (16K), QL 16K, buf b at 32K+b*32K: {KH,KL,VH,VL} 8K each,
//       mask at 96K + b*256. Total 98816 B.
#define FK_QH   0u
#define FK_QL   16384u
#define FK_KV   32768u
#define FK_MASK 98304u
#define FK_SMEM 98816

__global__ __launch_bounds__(256) void flash_hmma(
    const __half* __restrict__ qh, const __half* __restrict__ ql,
    const float* __restrict__ mask,
    __half* __restrict__ ch, __half* __restrict__ cl)
{
    extern __shared__ char fsm[];
    unsigned sb = smem_u32(fsm);

    int tid = threadIdx.x, wid = tid >> 5, lane = tid & 31;
    int qr = lane >> 2, tig = lane & 3;
    int bh = blockIdx.y, n = bh >> 4, h = bh & 15;
    int q0 = blockIdx.x << 7;
    const float* maskp = mask + (size_t)n * TT;

    const char* qbH = (const char*)(qh + (size_t)(n * TT + q0) * 3072) + h * 128;
    const char* qbL = (const char*)(ql + (size_t)(n * TT + q0) * 3072) + h * 128;
    const char* kvH = (const char*)(qh + (size_t)n * TT * 3072) + h * 128;
    const char* kvL = (const char*)(ql + (size_t)n * TT * 3072) + h * 128;

#define FK_ISSUE(it_) do {                                                     \
    int s0_ = (it_) << 6;                                                      \
    unsigned kb_ = sb + FK_KV + (unsigned)((it_) & 1) * 32768u;                \
    _Pragma("unroll")                                                          \
    for (int i_ = 0; i_ < 2; i_++) {                                           \
        int v_ = tid + (i_ << 8);                                              \
        int row_ = v_ >> 3; int kb2_ = (v_ & 7) << 4;                          \
        unsigned so_ = GSW((unsigned)((row_ << 7) | kb2_));                    \
        size_t gb_ = (size_t)(s0_ + row_) * 6144 + kb2_;                       \
        cp16(kb_ + so_,          kvH + gb_ + 2048);                            \
        cp16(kb_ + 8192u + so_,  kvL + gb_ + 2048);                            \
        cp16(kb_ + 16384u + so_, kvH + gb_ + 4096);                            \
        cp16(kb_ + 24576u + so_, kvL + gb_ + 4096);                            \
    }                                                                          \
    if (tid < 16)                                                              \
        cp16(sb + FK_MASK + (unsigned)((it_) & 1) * 256u + (tid << 4),         \
             maskp + s0_ + tid * 4);                                           \
    cpcommit();                                                                \
} while (0)

    // prologue: Q + first KV block in group 0, second KV block in group 1
#pragma unroll
    for (int i = 0; i < 4; i++) {
        int v = tid + (i << 8);
        int row = v >> 3; int kb = (v & 7) << 4;
        unsigned so = GSW((unsigned)((row << 7) | kb));
        cp16(sb + FK_QH + so, qbH + (size_t)row * 6144 + kb);
        cp16(sb + FK_QL + so, qbL + (size_t)row * 6144 + kb);
    }
    FK_ISSUE(0);
    FK_ISSUE(1);

    // fragment offsets
    int li = lane & 7, sub = lane >> 3;
    unsigned m4 = (unsigned)li << 4;
    unsigned qoff;
    {
        unsigned r = (unsigned)(wid * 16 + (sub & 1) * 8 + li);
        qoff = (r << 7) + ((unsigned)((sub >> 1) << 4) ^ m4);
    }
    unsigned koff[4];
#pragma unroll
    for (int ng = 0; ng < 4; ng++) {
        unsigned r = (unsigned)(ng * 16 + (sub >> 1) * 8 + li);
        koff[ng] = (r << 7) + ((unsigned)((sub & 1) << 4) ^ m4);
    }
    unsigned vrow = (unsigned)((sub & 1) * 8 + li) << 7;
    unsigned vb[4];
#pragma unroll
    for (int dt = 0; dt < 4; dt++)
        vb[dt] = ((unsigned)((sub >> 1) << 4) + (unsigned)(dt << 5)) ^ m4;

    unsigned qHf[4][4], qLf[4][4];     // hoisted Q fragments (loop-invariant)
    float sS[8][4], oO[8][4];
    float mM[2] = {-1e30f, -1e30f}, lL[2] = {0.f, 0.f};
#pragma unroll
    for (int nt = 0; nt < 8; nt++)
#pragma unroll
        for (int j = 0; j < 4; j++) oO[nt][j] = 0.f;

    for (int it = 0; it < TT / 64; ++it) {
        if (it == TT / 64 - 1) cpwait<0>(); else cpwait<1>();
        __syncthreads();
        unsigned kb0 = sb + FK_KV + (unsigned)(it & 1) * 32768u;

        if (it == 0) {
#pragma unroll
            for (int ks = 0; ks < 4; ks++) {
                unsigned kx = (unsigned)(ks << 5);
                ldsm4(qHf[ks], sb + FK_QH + (qoff ^ kx));
                ldsm4(qLf[ks], sb + FK_QL + (qoff ^ kx));
            }
        }

        // ---- S = Q@K^T (3-pass fp16) ----
#pragma unroll
        for (int nt = 0; nt < 8; nt++)
#pragma unroll
            for (int j = 0; j < 4; j++) sS[nt][j] = 0.f;
#pragma unroll
        for (int ks = 0; ks < 4; ks++) {
            unsigned kx = (unsigned)(ks << 5);
#pragma unroll
            for (int ng = 0; ng < 4; ng++) {
                unsigned bH[4], bL[4];
                ldsm4(bH, kb0 + (koff[ng] ^ kx));
                ldsm4(bL, kb0 + 8192u + (koff[ng] ^ kx));
                mma16816(sS[2 * ng + 0], qHf[ks], &bH[0]);
                mma16816(sS[2 * ng + 1], qHf[ks], &bH[2]);
                mma16816(sS[2 * ng + 0], qHf[ks], &bL[0]);
                mma16816(sS[2 * ng + 1], qHf[ks], &bL[2]);
                mma16816(sS[2 * ng + 0], qLf[ks], &bH[0]);
                mma16816(sS[2 * ng + 1], qLf[ks], &bH[2]);
            }
        }

        // ---- scale + mask ----
        const float* mbuf = (const float*)(fsm + FK_MASK + (it & 1) * 256);
#pragma unroll
        for (int nt = 0; nt < 8; nt++) {
            float2 mv = *(const float2*)(mbuf + nt * 8 + 2 * tig);
            sS[nt][0] = fmaf(sS[nt][0], 0.125f, mv.x);
            sS[nt][1] = fmaf(sS[nt][1], 0.125f, mv.y);
            sS[nt][2] = fmaf(sS[nt][2], 0.125f, mv.x);
            sS[nt][3] = fmaf(sS[nt][3], 0.125f, mv.y);
        }

        // ---- online softmax (2 rows/thread) ----
#pragma unroll
        for (int i = 0; i < 2; i++) {
            int ib = 2 * i;
            float mx = -1e30f;
#pragma unroll
            for (int nt = 0; nt < 8; nt++)
                mx = fmaxf(mx, fmaxf(sS[nt][ib], sS[nt][ib + 1]));
            mx = fmaxf(mx, __shfl_xor_sync(0xffffffffu, mx, 1));
            mx = fmaxf(mx, __shfl_xor_sync(0xffffffffu, mx, 2));
            float mnew  = fmaxf(mM[i], mx);
            float alpha = __expf(mM[i] - mnew);
            float rsum = 0.f;
#pragma unroll
            for (int nt = 0; nt < 8; nt++) {
                float p0 = __expf(sS[nt][ib]     - mnew);
                float p1 = __expf(sS[nt][ib + 1] - mnew);
                sS[nt][ib] = p0; sS[nt][ib + 1] = p1;
                rsum += p0 + p1;
            }
            rsum += __shfl_xor_sync(0xffffffffu, rsum, 1);
            rsum += __shfl_xor_sync(0xffffffffu, rsum, 2);
            lL[i] = lL[i] * alpha + rsum;
            mM[i] = mnew;
#pragma unroll
            for (int nt = 0; nt < 8; nt++) {
                oO[nt][ib] *= alpha; oO[nt][ib + 1] *= alpha;
            }
        }

        // ---- O += P@V (2-pass fp16: Ph*Vh + Ph*Vl) ----
#pragma unroll
        for (int kt = 0; kt < 4; kt++) {
            unsigned ah[4];
#pragma unroll
            for (int half = 0; half < 2; half++) {
                int nt = 2 * kt + half;
                ah[2 * half + 0] = h2u(__floats2half2_rn(sS[nt][0], sS[nt][1]));
                ah[2 * half + 1] = h2u(__floats2half2_rn(sS[nt][2], sS[nt][3]));
            }
            unsigned vkb = kb0 + 16384u + (unsigned)(kt << 11) + vrow;
#pragma unroll
            for (int dt = 0; dt < 4; dt++) {
                unsigned bv[4], bw[4];
                ldsm4t(bv, vkb + vb[dt]);
                ldsm4t(bw, vkb + 8192u + vb[dt]);
                mma16816(oO[2 * dt + 0], ah, &bv[0]);
                mma16816(oO[2 * dt + 1], ah, &bv[2]);
                mma16816(oO[2 * dt + 0], ah, &bw[0]);
                mma16816(oO[2 * dt + 1], ah, &bw[2]);
            }
        }
        __syncthreads();
        if (it + 2 < TT / 64) FK_ISSUE(it + 2);
    }
#undef FK_ISSUE

    // ---- write ctx hi/lo ----
#pragma unroll
    for (int i = 0; i < 2; i++) {
        float inv = 1.f / lL[i];
        int ib = 2 * i;
        size_t tok = (size_t)(n * TT + q0 + wid * 16 + qr + i * 8);
#pragma unroll
        for (int nt = 0; nt < 8; nt++) {
            float v0 = oO[nt][ib] * inv, v1 = oO[nt][ib + 1] * inv;
            int col = h * 64 + nt * 8 + 2 * tig;
            __half2 h2 = __floats2half2_rn(v0, v1);
            *(__half2*)(ch + tok * DD + col) = h2;
            *(__half2*)(cl + tok * DD + col) =
                __floats2half2_rn(v0 - __half2float(__low2half(h2)),
                                  v1 - __half2float(__high2half(h2)));
        }
    }
}

// ---------------- LayerNorm -> fp16 hi(/lo) ----------------------------------
template <int WLO>
__global__ __launch_bounds__(256) void ln_fp16_kernel(
    const float* __restrict__ x, const float* __restrict__ g,
    const float* __restrict__ b,
    __half* __restrict__ zh, __half* __restrict__ zl)
{
    int row = blockIdx.x;
    const float* xr = x + (size_t)row * DD;
    int tid = threadIdx.x;
    float v[4];
    float sum = 0.f, sq = 0.f;
#pragma unroll
    for (int i = 0; i < 4; i++) {
        v[i] = xr[tid + i * 256];
        sum += v[i]; sq += v[i] * v[i];
    }
#pragma unroll
    for (int o = 16; o > 0; o >>= 1) {
        sum += __shfl_xor_sync(0xffffffffu, sum, o);
        sq  += __shfl_xor_sync(0xffffffffu, sq,  o);
    }
    __shared__ float red[2][8];
    int w = tid >> 5, l = tid & 31;
    if (l == 0) { red[0][w] = sum; red[1][w] = sq; }
    __syncthreads();
    if (tid < 32) {
        float s = (tid < 8) ? red[0][tid] : 0.f;
        float q = (tid < 8) ? red[1][tid] : 0.f;
#pragma unroll
        for (int o = 4; o > 0; o >>= 1) {
            s += __shfl_xor_sync(0xffffffffu, s, o);
            q += __shfl_xor_sync(0xffffffffu, q, o);
        }
        if (tid == 0) { red[0][0] = s; red[1][0] = q; }
    }
    __syncthreads();
    float mu   = red[0][0] * (1.f / DD);
    float var  = red[1][0] * (1.f / DD) - mu * mu;
    float rstd = rsqrtf(var + 1e-5f);
#pragma unroll
    for (int i = 0; i < 4; i++) {
        int c = tid + i * 256;
        float y = (v[i] - mu) * rstd * g[c] + b[c];
        __half hh = __float2half_rn(y);
        zh[(size_t)row * DD + c] = hh;
        if (WLO)
            zl[(size_t)row * DD + c] = __float2half_rn(y - __half2float(hh));
    }
}

// ---------------- weight transpose W[K,N] -> T[N,K] fp16 hi(/lo) -------------
template <int SPLIT>
__global__ __launch_bounds__(256) void transpose_kernel(
    const float* __restrict__ W, __half* __restrict__ Th,
    __half* __restrict__ Tl, int K, int N)
{
    __shared__ float t[32][33];
    int tx = threadIdx.x & 31, ty0 = threadIdx.x >> 5;
    int k0 = blockIdx.y * 32, n0 = blockIdx.x * 32;
#pragma unroll
    for (int i = 0; i < 4; i++) {
        int ty = ty0 + i * 8;
        t[ty][tx] = W[(size_t)(k0 + ty) * N + n0 + tx];
    }
    __syncthreads();
#pragma unroll
    for (int i = 0; i < 4; i++) {
        int ty = ty0 + i * 8;
        float v = t[tx][ty];
        __half hh = __float2half_rn(v);
        Th[(size_t)(n0 + ty) * K + k0 + tx] = hh;
        if (SPLIT)
            Tl[(size_t)(n0 + ty) * K + k0 + tx] =
                __float2half_rn(v - __half2float(hh));
    }
}

// ---------------- launch -----------------------------------------------------
extern "C" void kernel_launch(void* const* d_in, const int* in_sizes, int n_in,
                              void* d_out, int out_size)
{
    const float* x     = (const float*)d_in[0];
    const float* mask  = (const float*)d_in[1];
    const float* Wqkv  = (const float*)d_in[2];
    const float* Wout  = (const float*)d_in[3];
    const float* ln1_g = (const float*)d_in[4];
    const float* ln1_b = (const float*)d_in[5];
    const float* ln2_g = (const float*)d_in[6];
    const float* ln2_b = (const float*)d_in[7];
    const float* W1    = (const float*)d_in[8];
    const float* b1    = (const float*)d_in[9];
    const float* W2    = (const float*)d_in[10];
    const float* b2    = (const float*)d_in[11];
    float* out = (float*)d_out;

    float *x1;
    __half *qh, *ql, *zh, *zl, *ch, *cl, *hb;
    __half *wqh, *wql, *woh, *wol, *w1t, *w2t;
    cudaGetSymbolAddress((void**)&x1,  g_x1);
    cudaGetSymbolAddress((void**)&qh,  g_qh);
    cudaGetSymbolAddress((void**)&ql,  g_ql);
    cudaGetSymbolAddress((void**)&zh,  g_zh);
    cudaGetSymbolAddress((void**)&zl,  g_zl);
    cudaGetSymbolAddress((void**)&ch,  g_ch);
    cudaGetSymbolAddress((void**)&cl,  g_cl);
    cudaGetSymbolAddress((void**)&hb,  g_hb);
    cudaGetSymbolAddress((void**)&wqh, g_wqh);
    cudaGetSymbolAddress((void**)&wql, g_wql);
    cudaGetSymbolAddress((void**)&woh, g_woh);
    cudaGetSymbolAddress((void**)&wol, g_wol);
    cudaGetSymbolAddress((void**)&w1t, g_w1t);
    cudaGetSymbolAddress((void**)&w2t, g_w2t);

    cudaFuncSetAttribute(flash_hmma,
                         cudaFuncAttributeMaxDynamicSharedMemorySize, FK_SMEM);
    cudaFuncSetAttribute(hmma_gemm<3, 0, 2>,
                         cudaFuncAttributeMaxDynamicSharedMemorySize, GEMM_SMEM);
    cudaFuncSetAttribute(hmma_gemm<3, 1, 0>,
                         cudaFuncAttributeMaxDynamicSharedMemorySize, GEMM_SMEM);
    cudaFuncSetAttribute(hmma_gemm<1, 2, 1>,
                         cudaFuncAttributeMaxDynamicSharedMemorySize, GEMM_SMEM);
    cudaFuncSetAttribute(hmma_gemm<1, 3, 0>,
                         cudaFuncAttributeMaxDynamicSharedMemorySize, GEMM_SMEM);

    // 0. weight transposes + fp16 split
    transpose_kernel<1><<<dim3(3 * DD / 32, DD / 32), 256>>>(Wqkv, wqh, wql, DD, 3 * DD);
    transpose_kernel<1><<<dim3(DD / 32, DD / 32),     256>>>(Wout, woh, wol, DD, DD);
    transpose_kernel<0><<<dim3(4 * DD / 32, DD / 32), 256>>>(W1, w1t, nullptr, DD, 4 * DD);
    transpose_kernel<0><<<dim3(DD / 32, 4 * DD / 32), 256>>>(W2, w2t, nullptr, 4 * DD, DD);

    // 1. LN1 -> fp16 hi/lo
    ln_fp16_kernel<1><<<MTOK, 256>>>(x, ln1_g, ln1_b, zh, zl);
    // 2. QKV = z @ Wqkv  (3-pass split fp16) -> fp16 hi/lo directly
    hmma_gemm<3, 0, 2><<<dim3(3 * DD / 128, MTOK / 128), 256, GEMM_SMEM>>>(
        zh, zl, wqh, wql, nullptr, nullptr, nullptr, qh, ql, MTOK, 3 * DD, DD);
    // 3. attention (HMMA, 3-pass QK / 2-pass PV) -> ctx hi/lo
    flash_hmma<<<dim3(TT / 128, NB * HH), 256, FK_SMEM>>>(qh, ql, mask, ch, cl);
    // 4. x1 = x + ctx @ Wout  (3-pass split)
    hmma_gemm<3, 1, 0><<<dim3(DD / 128, MTOK / 128), 256, GEMM_SMEM>>>(
        ch, cl, woh, wol, x, nullptr, x1, nullptr, nullptr, MTOK, DD, DD);
    // 5. LN2 -> fp16 hi
    ln_fp16_kernel<0><<<MTOK, 256>>>(x1, ln2_g, ln2_b, zh, nullptr);
    // 6. h = gelu(z2 @ W1 + b1) -> fp16
    hmma_gemm<1, 2, 1><<<dim3(4 * DD / 128, MTOK / 128), 256, GEMM_SMEM>>>(
        zh, nullptr, w1t, nullptr, nullptr, b1, nullptr, hb, nullptr, MTOK, 4 * DD, DD);
    // 7. out = x1 + h @ W2 + b2
    hmma_gemm<1, 3, 0><<<dim3(DD / 128, MTOK / 128), 256, GEMM_SMEM>>>(
        hb, nullptr, w2t, nullptr, x1, b2, out, nullptr, nullptr, MTOK, DD, 4 * DD);
}

// round 13
// speedup vs baseline: 7.4455x; 1.0818x over previous
#include <cuda_runtime.h>
#include <cuda_fp16.h>
#include <math.h>

// Problem constants
#define NB 4
#define TT 2048
#define DD 1024
#define HH 16
#define DKK 64
#define MTOK (NB*TT)          // 8192 tokens

// ---------------- scratch (device globals; no allocation allowed) -----------
__device__ float g_x1 [MTOK * DD];        // 32 MB fp32
__device__ __half g_qh [MTOK * 3 * DD];   // qkv hi (48 MB)
__device__ __half g_ql [MTOK * 3 * DD];   // qkv lo
__device__ __half g_zh [MTOK * DD];       // LN out hi
__device__ __half g_zl [MTOK * DD];       // LN out lo
__device__ __half g_ch [MTOK * DD];       // ctx hi
__device__ __half g_cl [MTOK * DD];       // ctx lo
__device__ __half g_hb [MTOK * 4 * DD];   // FFN hidden (fp16)
__device__ __half g_wqh[3 * DD * DD];     // Wqkv^T hi  [3072,1024]
__device__ __half g_wql[3 * DD * DD];
__device__ __half g_woh[DD * DD];         // Wout^T hi  [1024,1024]
__device__ __half g_wol[DD * DD];
__device__ __half g_w1t[4 * DD * DD];     // W1^T [4096,1024]
__device__ __half g_w2t[DD * 4 * DD];     // W2^T [1024,4096]

// ---------------- PTX helpers ------------------------------------------------
__device__ __forceinline__ unsigned smem_u32(const void* p) {
    unsigned a;
    asm("{ .reg .u64 t; cvta.to.shared.u64 t, %1; cvt.u32.u64 %0, t; }"
        : "=r"(a) : "l"(p));
    return a;
}
__device__ __forceinline__ void cp16(unsigned dst, const void* src) {
    asm volatile("cp.async.cg.shared.global [%0], [%1], 16;"
                 :: "r"(dst), "l"(src) : "memory");
}
__device__ __forceinline__ void cpcommit() {
    asm volatile("cp.async.commit_group;" ::: "memory");
}
template <int N> __device__ __forceinline__ void cpwait() {
    asm volatile("cp.async.wait_group %0;" :: "n"(N) : "memory");
}
__device__ __forceinline__ void ldsm4(unsigned* r, unsigned addr) {
    asm volatile("ldmatrix.sync.aligned.m8n8.x4.shared.b16 {%0,%1,%2,%3}, [%4];"
                 : "=r"(r[0]), "=r"(r[1]), "=r"(r[2]), "=r"(r[3]) : "r"(addr));
}
__device__ __forceinline__ void ldsm4t(unsigned* r, unsigned addr) {
    asm volatile("ldmatrix.sync.aligned.m8n8.x4.trans.shared.b16 {%0,%1,%2,%3}, [%4];"
                 : "=r"(r[0]), "=r"(r[1]), "=r"(r[2]), "=r"(r[3]) : "r"(addr));
}
__device__ __forceinline__ void mma16816(float* d, const unsigned* a,
                                         const unsigned* b) {
    asm volatile(
        "mma.sync.aligned.m16n8k16.row.col.f32.f16.f16.f32 "
        "{%0,%1,%2,%3}, {%4,%5,%6,%7}, {%8,%9}, {%0,%1,%2,%3};"
        : "+f"(d[0]), "+f"(d[1]), "+f"(d[2]), "+f"(d[3])
        : "r"(a[0]), "r"(a[1]), "r"(a[2]), "r"(a[3]), "r"(b[0]), "r"(b[1]));
}
__device__ __forceinline__ unsigned h2u(__half2 v) {
    union { __half2 h; unsigned u; } c; c.h = v; return c.u;
}

#define GSW(off) ((off) ^ ((((unsigned)(off)) >> 3) & 0x70u))

// ---------------- fused multi-pass HMMA fp16 GEMM ----------------------------
// C[M,N] = A@B^T with A=Ah+Al, B=Bh+Bl (NPASS=3: Ah*Bh+Ah*Bl+Al*Bh in ONE
// k-loop with fragment reuse; NPASS=1: plain Ah*Bh).
// A[M,K], B[N,K] K-major fp16. Tile 128x128, k-chunk 64, double-buffered.
// EPI: 0 none, 1 +R, 2 +bias,gelu, 3 +bias+R.
// OUTB: 0 fp32 Cf, 1 fp16 Cb, 2 fp16 hi->Cb + lo->Cb2.
#define GEMM_SMEM3 (131072 + 1024)
#define GEMM_SMEM1 (65536 + 1024)

template <int NPASS, int EPI, int OUTB>
__global__ __launch_bounds__(256) void hmma_gemm(
    const __half* __restrict__ Ah, const __half* __restrict__ Al,
    const __half* __restrict__ Bh, const __half* __restrict__ Bl,
    const float* __restrict__ R, const float* __restrict__ bias,
    float* __restrict__ Cf, __half* __restrict__ Cb,
    __half* __restrict__ Cb2,
    int M, int N, int K)
{
    constexpr unsigned TS  = (NPASS == 3) ? 65536u : 32768u;  // stage size
    constexpr unsigned BOF = (NPASS == 3) ? 32768u : 16384u;  // B offset in stage

    extern __shared__ char dsm[];
    unsigned smb    = smem_u32(dsm);
    unsigned tile_u = (smb + 1023u) & ~1023u;

    int tid = threadIdx.x, wid = tid >> 5, lane = tid & 31;
    int wm = wid & 3, wn = wid >> 2;
    int bm = blockIdx.y << 7, bn = blockIdx.x << 7;

    const int nk = K >> 6;

    int li  = lane & 7, sub = lane >> 3;
    unsigned aoff[2];
#pragma unroll
    for (int mt = 0; mt < 2; mt++) {
        unsigned r = (unsigned)(wm * 32 + mt * 16 + (sub & 1) * 8 + li);
        aoff[mt] = (r << 7) + (unsigned)((sub >> 1) << 4);
        aoff[mt] ^= (r & 7u) << 4;
    }
    unsigned boff[4];
#pragma unroll
    for (int ng = 0; ng < 4; ng++) {
        unsigned r = (unsigned)(wn * 64 + ng * 16 + (sub >> 1) * 8 + li);
        boff[ng] = (r << 7) + (unsigned)((sub & 1) << 4);
        boff[ng] ^= (r & 7u) << 4;
    }

    int ld_row = tid >> 3;
    int ld_kb  = (tid & 7) << 4;

    float d[2][8][4];
#pragma unroll
    for (int mt = 0; mt < 2; mt++)
#pragma unroll
        for (int nt = 0; nt < 8; nt++)
#pragma unroll
            for (int j = 0; j < 4; j++) d[mt][nt][j] = 0.f;

#define ISSUE(it_) do {                                                        \
    unsigned base_ = tile_u + (unsigned)((it_) & 1) * TS;                      \
    const __half* AsH_ = Ah + (size_t)bm * K + ((it_) << 6);                   \
    const __half* BsH_ = Bh + (size_t)bn * K + ((it_) << 6);                   \
    const __half* AsL_ = (NPASS == 3) ? Al + (size_t)bm * K + ((it_) << 6) : nullptr; \
    const __half* BsL_ = (NPASS == 3) ? Bl + (size_t)bn * K + ((it_) << 6) : nullptr; \
    _Pragma("unroll")                                                          \
    for (int i_ = 0; i_ < 4; i_++) {                                           \
        int row_ = ld_row + i_ * 32;                                           \
        unsigned so_ = GSW((unsigned)((row_ << 7) | ld_kb));                   \
        cp16(base_ + so_, (const char*)(AsH_ + (size_t)row_ * K) + ld_kb);     \
        cp16(base_ + BOF + so_, (const char*)(BsH_ + (size_t)row_ * K) + ld_kb); \
        if (NPASS == 3) {                                                      \
            cp16(base_ + 16384u + so_,                                         \
                 (const char*)(AsL_ + (size_t)row_ * K) + ld_kb);              \
            cp16(base_ + BOF + 16384u + so_,                                   \
                 (const char*)(BsL_ + (size_t)row_ * K) + ld_kb);              \
        }                                                                      \
    }                                                                          \
    cpcommit();                                                                \
} while (0)

    ISSUE(0);
    if (nk > 1) ISSUE(1);

    for (int it = 0; it < nk; ++it) {
        if (it + 1 < nk) cpwait<1>(); else cpwait<0>();
        __syncthreads();
        unsigned ab = tile_u + (unsigned)(it & 1) * TS;
        unsigned bb = ab + BOF;
#pragma unroll
        for (int ks = 0; ks < 4; ks++) {
            unsigned kx = (unsigned)(ks << 5);
            unsigned aH[2][4], aL[2][4];
#pragma unroll
            for (int mt = 0; mt < 2; mt++) ldsm4(aH[mt], ab + (aoff[mt] ^ kx));
            if (NPASS == 3) {
#pragma unroll
                for (int mt = 0; mt < 2; mt++)
                    ldsm4(aL[mt], ab + 16384u + (aoff[mt] ^ kx));
            }
#pragma unroll
            for (int ng = 0; ng < 4; ng++) {
                unsigned bH[4];
                ldsm4(bH, bb + (boff[ng] ^ kx));
#pragma unroll
                for (int mt = 0; mt < 2; mt++) {
                    mma16816(d[mt][2 * ng + 0], aH[mt], &bH[0]);
                    mma16816(d[mt][2 * ng + 1], aH[mt], &bH[2]);
                }
                if (NPASS == 3) {
                    unsigned bL[4];
                    ldsm4(bL, bb + 16384u + (boff[ng] ^ kx));
#pragma unroll
                    for (int mt = 0; mt < 2; mt++) {
                        mma16816(d[mt][2 * ng + 0], aH[mt], &bL[0]);
                        mma16816(d[mt][2 * ng + 1], aH[mt], &bL[2]);
                    }
#pragma unroll
                    for (int mt = 0; mt < 2; mt++) {
                        mma16816(d[mt][2 * ng + 0], aL[mt], &bH[0]);
                        mma16816(d[mt][2 * ng + 1], aL[mt], &bH[2]);
                    }
                }
            }
        }
        __syncthreads();
        if (it + 2 < nk) ISSUE(it + 2);
    }
#undef ISSUE

    int qr = lane >> 2;
    int qc = (lane & 3) << 1;
#pragma unroll
    for (int mt = 0; mt < 2; mt++) {
#pragma unroll
        for (int nt = 0; nt < 8; nt++) {
            int r0 = bm + wm * 32 + mt * 16 + qr;
            int c  = bn + wn * 64 + nt * 8 + qc;
            float v[4];
#pragma unroll
            for (int j = 0; j < 4; j++) v[j] = d[mt][nt][j];
            if (EPI == 2 || EPI == 3) {
                float2 bv = *(const float2*)(bias + c);
                v[0] += bv.x; v[1] += bv.y; v[2] += bv.x; v[3] += bv.y;
            }
            if (EPI == 2) {
#pragma unroll
                for (int j = 0; j < 4; j++)
                    v[j] = 0.5f * v[j] * (1.0f + erff(v[j] * 0.7071067811865475f));
            }
            if (EPI == 1 || EPI == 3) {
                float2 r1 = *(const float2*)(R + (size_t)r0 * N + c);
                float2 r2 = *(const float2*)(R + (size_t)(r0 + 8) * N + c);
                v[0] += r1.x; v[1] += r1.y; v[2] += r2.x; v[3] += r2.y;
            }
            if (OUTB == 1) {
                *(__half2*)(Cb + (size_t)r0 * N + c) =
                    __floats2half2_rn(v[0], v[1]);
                *(__half2*)(Cb + (size_t)(r0 + 8) * N + c) =
                    __floats2half2_rn(v[2], v[3]);
            } else if (OUTB == 2) {
                __half2 h0 = __floats2half2_rn(v[0], v[1]);
                __half2 h1 = __floats2half2_rn(v[2], v[3]);
                *(__half2*)(Cb + (size_t)r0 * N + c) = h0;
                *(__half2*)(Cb + (size_t)(r0 + 8) * N + c) = h1;
                *(__half2*)(Cb2 + (size_t)r0 * N + c) =
                    __floats2half2_rn(v[0] - __half2float(__low2half(h0)),
                                      v[1] - __half2float(__high2half(h0)));
                *(__half2*)(Cb2 + (size_t)(r0 + 8) * N + c) =
                    __floats2half2_rn(v[2] - __half2float(__low2half(h1)),
                                      v[3] - __half2float(__high2half(h1)));
            } else {
                *(float2*)(Cf + (size_t)r0 * N + c) = make_float2(v[0], v[1]);
                *(float2*)(Cf + (size_t)(r0 + 8) * N + c) = make_float2(v[2], v[3]);
            }
        }
    }
}

// ---------------- HMMA flash attention --------------------------------------
// CTA: 128 q-rows of one (n,h); iterate 32 s-blocks of 64. 8 warps x 16 rows.
// QK^T 3-pass split fp16, online softmax fp32, PV 1-pass fp16 (Ph*Vh).
// SMEM: QH 0 (16K), QL 16K, buf b at 32K+b*24K: {KH,KL,VH} 8K each,
//       mask at 80K(81920) + b*256. Total 82432 B.
#define FK_QH   0u
#define FK_QL   16384u
#define FK_KV   32768u
#define FK_BUF  24576u
#define FK_MASK 81920u
#define FK_SMEM 82432

__global__ __launch_bounds__(256) void flash_hmma(
    const __half* __restrict__ qh, const __half* __restrict__ ql,
    const float* __restrict__ mask,
    __half* __restrict__ ch, __half* __restrict__ cl)
{
    extern __shared__ char fsm[];
    unsigned sb = smem_u32(fsm);

    int tid = threadIdx.x, wid = tid >> 5, lane = tid & 31;
    int qr = lane >> 2, tig = lane & 3;
    int bh = blockIdx.y, n = bh >> 4, h = bh & 15;
    int q0 = blockIdx.x << 7;
    const float* maskp = mask + (size_t)n * TT;

    const char* qbH = (const char*)(qh + (size_t)(n * TT + q0) * 3072) + h * 128;
    const char* qbL = (const char*)(ql + (size_t)(n * TT + q0) * 3072) + h * 128;
    const char* kvH = (const char*)(qh + (size_t)n * TT * 3072) + h * 128;
    const char* kvL = (const char*)(ql + (size_t)n * TT * 3072) + h * 128;

#define FK_ISSUE(it_) do {                                                     \
    int s0_ = (it_) << 6;                                                      \
    unsigned kb_ = sb + FK_KV + (unsigned)((it_) & 1) * FK_BUF;                \
    _Pragma("unroll")                                                          \
    for (int i_ = 0; i_ < 2; i_++) {                                           \
        int v_ = tid + (i_ << 8);                                              \
        int row_ = v_ >> 3; int kb2_ = (v_ & 7) << 4;                          \
        unsigned so_ = GSW((unsigned)((row_ << 7) | kb2_));                    \
        size_t gb_ = (size_t)(s0_ + row_) * 6144 + kb2_;                       \
        cp16(kb_ + so_,          kvH + gb_ + 2048);                            \
        cp16(kb_ + 8192u + so_,  kvL + gb_ + 2048);                            \
        cp16(kb_ + 16384u + so_, kvH + gb_ + 4096);                            \
    }                                                                          \
    if (tid < 16)                                                              \
        cp16(sb + FK_MASK + (unsigned)((it_) & 1) * 256u + (tid << 4),         \
             maskp + s0_ + tid * 4);                                           \
    cpcommit();                                                                \
} while (0)

    // prologue: Q + first KV block in group 0, second KV block in group 1
#pragma unroll
    for (int i = 0; i < 4; i++) {
        int v = tid + (i << 8);
        int row = v >> 3; int kb = (v & 7) << 4;
        unsigned so = GSW((unsigned)((row << 7) | kb));
        cp16(sb + FK_QH + so, qbH + (size_t)row * 6144 + kb);
        cp16(sb + FK_QL + so, qbL + (size_t)row * 6144 + kb);
    }
    FK_ISSUE(0);
    FK_ISSUE(1);

    // fragment offsets
    int li = lane & 7, sub = lane >> 3;
    unsigned m4 = (unsigned)li << 4;
    unsigned qoff;
    {
        unsigned r = (unsigned)(wid * 16 + (sub & 1) * 8 + li);
        qoff = (r << 7) + ((unsigned)((sub >> 1) << 4) ^ m4);
    }
    unsigned koff[4];
#pragma unroll
    for (int ng = 0; ng < 4; ng++) {
        unsigned r = (unsigned)(ng * 16 + (sub >> 1) * 8 + li);
        koff[ng] = (r << 7) + ((unsigned)((sub & 1) << 4) ^ m4);
    }
    unsigned vrow = (unsigned)((sub & 1) * 8 + li) << 7;
    unsigned vb[4];
#pragma unroll
    for (int dt = 0; dt < 4; dt++)
        vb[dt] = ((unsigned)((sub >> 1) << 4) + (unsigned)(dt << 5)) ^ m4;

    unsigned qHf[4][4], qLf[4][4];     // hoisted Q fragments (loop-invariant)
    float sS[8][4], oO[8][4];
    float mM[2] = {-1e30f, -1e30f}, lL[2] = {0.f, 0.f};
#pragma unroll
    for (int nt = 0; nt < 8; nt++)
#pragma unroll
        for (int j = 0; j < 4; j++) oO[nt][j] = 0.f;

    for (int it = 0; it < TT / 64; ++it) {
        if (it == TT / 64 - 1) cpwait<0>(); else cpwait<1>();
        __syncthreads();
        unsigned kb0 = sb + FK_KV + (unsigned)(it & 1) * FK_BUF;

        if (it == 0) {
#pragma unroll
            for (int ks = 0; ks < 4; ks++) {
                unsigned kx = (unsigned)(ks << 5);
                ldsm4(qHf[ks], sb + FK_QH + (qoff ^ kx));
                ldsm4(qLf[ks], sb + FK_QL + (qoff ^ kx));
            }
        }

        // ---- S = Q@K^T (3-pass fp16) ----
#pragma unroll
        for (int nt = 0; nt < 8; nt++)
#pragma unroll
            for (int j = 0; j < 4; j++) sS[nt][j] = 0.f;
#pragma unroll
        for (int ks = 0; ks < 4; ks++) {
            unsigned kx = (unsigned)(ks << 5);
#pragma unroll
            for (int ng = 0; ng < 4; ng++) {
                unsigned bH[4], bL[4];
                ldsm4(bH, kb0 + (koff[ng] ^ kx));
                ldsm4(bL, kb0 + 8192u + (koff[ng] ^ kx));
                mma16816(sS[2 * ng + 0], qHf[ks], &bH[0]);
                mma16816(sS[2 * ng + 1], qHf[ks], &bH[2]);
                mma16816(sS[2 * ng + 0], qHf[ks], &bL[0]);
                mma16816(sS[2 * ng + 1], qHf[ks], &bL[2]);
                mma16816(sS[2 * ng + 0], qLf[ks], &bH[0]);
                mma16816(sS[2 * ng + 1], qLf[ks], &bH[2]);
            }
        }

        // ---- scale + mask ----
        const float* mbuf = (const float*)(fsm + FK_MASK + (it & 1) * 256);
#pragma unroll
        for (int nt = 0; nt < 8; nt++) {
            float2 mv = *(const float2*)(mbuf + nt * 8 + 2 * tig);
            sS[nt][0] = fmaf(sS[nt][0], 0.125f, mv.x);
            sS[nt][1] = fmaf(sS[nt][1], 0.125f, mv.y);
            sS[nt][2] = fmaf(sS[nt][2], 0.125f, mv.x);
            sS[nt][3] = fmaf(sS[nt][3], 0.125f, mv.y);
        }

        // ---- online softmax (2 rows/thread) ----
#pragma unroll
        for (int i = 0; i < 2; i++) {
            int ib = 2 * i;
            float mx = -1e30f;
#pragma unroll
            for (int nt = 0; nt < 8; nt++)
                mx = fmaxf(mx, fmaxf(sS[nt][ib], sS[nt][ib + 1]));
            mx = fmaxf(mx, __shfl_xor_sync(0xffffffffu, mx, 1));
            mx = fmaxf(mx, __shfl_xor_sync(0xffffffffu, mx, 2));
            float mnew  = fmaxf(mM[i], mx);
            float alpha = __expf(mM[i] - mnew);
            float rsum = 0.f;
#pragma unroll
            for (int nt = 0; nt < 8; nt++) {
                float p0 = __expf(sS[nt][ib]     - mnew);
                float p1 = __expf(sS[nt][ib + 1] - mnew);
                sS[nt][ib] = p0; sS[nt][ib + 1] = p1;
                rsum += p0 + p1;
            }
            rsum += __shfl_xor_sync(0xffffffffu, rsum, 1);
            rsum += __shfl_xor_sync(0xffffffffu, rsum, 2);
            lL[i] = lL[i] * alpha + rsum;
            mM[i] = mnew;
#pragma unroll
            for (int nt = 0; nt < 8; nt++) {
                oO[nt][ib] *= alpha; oO[nt][ib + 1] *= alpha;
            }
        }

        // ---- O += P@V (1-pass fp16: Ph*Vh) ----
#pragma unroll
        for (int kt = 0; kt < 4; kt++) {
            unsigned ah[4];
#pragma unroll
            for (int half = 0; half < 2; half++) {
                int nt = 2 * kt + half;
                ah[2 * half + 0] = h2u(__floats2half2_rn(sS[nt][0], sS[nt][1]));
                ah[2 * half + 1] = h2u(__floats2half2_rn(sS[nt][2], sS[nt][3]));
            }
            unsigned vkb = kb0 + 16384u + (unsigned)(kt << 11) + vrow;
#pragma unroll
            for (int dt = 0; dt < 4; dt++) {
                unsigned bv[4];
                ldsm4t(bv, vkb + vb[dt]);
                mma16816(oO[2 * dt + 0], ah, &bv[0]);
                mma16816(oO[2 * dt + 1], ah, &bv[2]);
            }
        }
        __syncthreads();
        if (it + 2 < TT / 64) FK_ISSUE(it + 2);
    }
#undef FK_ISSUE

    // ---- write ctx hi/lo ----
#pragma unroll
    for (int i = 0; i < 2; i++) {
        float inv = 1.f / lL[i];
        int ib = 2 * i;
        size_t tok = (size_t)(n * TT + q0 + wid * 16 + qr + i * 8);
#pragma unroll
        for (int nt = 0; nt < 8; nt++) {
            float v0 = oO[nt][ib] * inv, v1 = oO[nt][ib + 1] * inv;
            int col = h * 64 + nt * 8 + 2 * tig;
            __half2 h2 = __floats2half2_rn(v0, v1);
            *(__half2*)(ch + tok * DD + col) = h2;
            *(__half2*)(cl + tok * DD + col) =
                __floats2half2_rn(v0 - __half2float(__low2half(h2)),
                                  v1 - __half2float(__high2half(h2)));
        }
    }
}

// ---------------- LayerNorm -> fp16 hi(/lo) ----------------------------------
template <int WLO>
__global__ __launch_bounds__(256) void ln_fp16_kernel(
    const float* __restrict__ x, const float* __restrict__ g,
    const float* __restrict__ b,
    __half* __restrict__ zh, __half* __restrict__ zl)
{
    int row = blockIdx.x;
    const float* xr = x + (size_t)row * DD;
    int tid = threadIdx.x;
    float v[4];
    float sum = 0.f, sq = 0.f;
#pragma unroll
    for (int i = 0; i < 4; i++) {
        v[i] = xr[tid + i * 256];
        sum += v[i]; sq += v[i] * v[i];
    }
#pragma unroll
    for (int o = 16; o > 0; o >>= 1) {
        sum += __shfl_xor_sync(0xffffffffu, sum, o);
        sq  += __shfl_xor_sync(0xffffffffu, sq,  o);
    }
    __shared__ float red[2][8];
    int w = tid >> 5, l = tid & 31;
    if (l == 0) { red[0][w] = sum; red[1][w] = sq; }
    __syncthreads();
    if (tid < 32) {
        float s = (tid < 8) ? red[0][tid] : 0.f;
        float q = (tid < 8) ? red[1][tid] : 0.f;
#pragma unroll
        for (int o = 4; o > 0; o >>= 1) {
            s += __shfl_xor_sync(0xffffffffu, s, o);
            q += __shfl_xor_sync(0xffffffffu, q, o);
        }
        if (tid == 0) { red[0][0] = s; red[1][0] = q; }
    }
    __syncthreads();
    float mu   = red[0][0] * (1.f / DD);
    float var  = red[1][0] * (1.f / DD) - mu * mu;
    float rstd = rsqrtf(var + 1e-5f);
#pragma unroll
    for (int i = 0; i < 4; i++) {
        int c = tid + i * 256;
        float y = (v[i] - mu) * rstd * g[c] + b[c];
        __half hh = __float2half_rn(y);
        zh[(size_t)row * DD + c] = hh;
        if (WLO)
            zl[(size_t)row * DD + c] = __float2half_rn(y - __half2float(hh));
    }
}

// ---------------- weight transpose W[K,N] -> T[N,K] fp16 hi(/lo) -------------
template <int SPLIT>
__global__ __launch_bounds__(256) void transpose_kernel(
    const float* __restrict__ W, __half* __restrict__ Th,
    __half* __restrict__ Tl, int K, int N)
{
    __shared__ float t[32][33];
    int tx = threadIdx.x & 31, ty0 = threadIdx.x >> 5;
    int k0 = blockIdx.y * 32, n0 = blockIdx.x * 32;
#pragma unroll
    for (int i = 0; i < 4; i++) {
        int ty = ty0 + i * 8;
        t[ty][tx] = W[(size_t)(k0 + ty) * N + n0 + tx];
    }
    __syncthreads();
#pragma unroll
    for (int i = 0; i < 4; i++) {
        int ty = ty0 + i * 8;
        float v = t[tx][ty];
        __half hh = __float2half_rn(v);
        Th[(size_t)(n0 + ty) * K + k0 + tx] = hh;
        if (SPLIT)
            Tl[(size_t)(n0 + ty) * K + k0 + tx] =
                __float2half_rn(v - __half2float(hh));
    }
}

// ---------------- launch -----------------------------------------------------
extern "C" void kernel_launch(void* const* d_in, const int* in_sizes, int n_in,
                              void* d_out, int out_size)
{
    const float* x     = (const float*)d_in[0];
    const float* mask  = (const float*)d_in[1];
    const float* Wqkv  = (const float*)d_in[2];
    const float* Wout  = (const float*)d_in[3];
    const float* ln1_g = (const float*)d_in[4];
    const float* ln1_b = (const float*)d_in[5];
    const float* ln2_g = (const float*)d_in[6];
    const float* ln2_b = (const float*)d_in[7];
    const float* W1    = (const float*)d_in[8];
    const float* b1    = (const float*)d_in[9];
    const float* W2    = (const float*)d_in[10];
    const float* b2    = (const float*)d_in[11];
    float* out = (float*)d_out;

    float *x1;
    __half *qh, *ql, *zh, *zl, *ch, *cl, *hb;
    __half *wqh, *wql, *woh, *wol, *w1t, *w2t;
    cudaGetSymbolAddress((void**)&x1,  g_x1);
    cudaGetSymbolAddress((void**)&qh,  g_qh);
    cudaGetSymbolAddress((void**)&ql,  g_ql);
    cudaGetSymbolAddress((void**)&zh,  g_zh);
    cudaGetSymbolAddress((void**)&zl,  g_zl);
    cudaGetSymbolAddress((void**)&ch,  g_ch);
    cudaGetSymbolAddress((void**)&cl,  g_cl);
    cudaGetSymbolAddress((void**)&hb,  g_hb);
    cudaGetSymbolAddress((void**)&wqh, g_wqh);
    cudaGetSymbolAddress((void**)&wql, g_wql);
    cudaGetSymbolAddress((void**)&woh, g_woh);
    cudaGetSymbolAddress((void**)&wol, g_wol);
    cudaGetSymbolAddress((void**)&w1t, g_w1t);
    cudaGetSymbolAddress((void**)&w2t, g_w2t);

    cudaFuncSetAttribute(flash_hmma,
                         cudaFuncAttributeMaxDynamicSharedMemorySize, FK_SMEM);
    cudaFuncSetAttribute(hmma_gemm<3, 0, 2>,
                         cudaFuncAttributeMaxDynamicSharedMemorySize, GEMM_SMEM3);
    cudaFuncSetAttribute(hmma_gemm<3, 1, 0>,
                         cudaFuncAttributeMaxDynamicSharedMemorySize, GEMM_SMEM3);
    cudaFuncSetAttribute(hmma_gemm<1, 2, 1>,
                         cudaFuncAttributeMaxDynamicSharedMemorySize, GEMM_SMEM1);
    cudaFuncSetAttribute(hmma_gemm<1, 3, 0>,
                         cudaFuncAttributeMaxDynamicSharedMemorySize, GEMM_SMEM1);

    // 0. weight transposes + fp16 split
    transpose_kernel<1><<<dim3(3 * DD / 32, DD / 32), 256>>>(Wqkv, wqh, wql, DD, 3 * DD);
    transpose_kernel<1><<<dim3(DD / 32, DD / 32),     256>>>(Wout, woh, wol, DD, DD);
    transpose_kernel<0><<<dim3(4 * DD / 32, DD / 32), 256>>>(W1, w1t, nullptr, DD, 4 * DD);
    transpose_kernel<0><<<dim3(DD / 32, 4 * DD / 32), 256>>>(W2, w2t, nullptr, 4 * DD, DD);

    // 1. LN1 -> fp16 hi/lo
    ln_fp16_kernel<1><<<MTOK, 256>>>(x, ln1_g, ln1_b, zh, zl);
    // 2. QKV = z @ Wqkv  (fused 3-pass fp16) -> fp16 hi/lo directly
    hmma_gemm<3, 0, 2><<<dim3(3 * DD / 128, MTOK / 128), 256, GEMM_SMEM3>>>(
        zh, zl, wqh, wql, nullptr, nullptr, nullptr, qh, ql, MTOK, 3 * DD, DD);
    // 3. attention (HMMA, 3-pass QK / 1-pass PV) -> ctx hi/lo
    flash_hmma<<<dim3(TT / 128, NB * HH), 256, FK_SMEM>>>(qh, ql, mask, ch, cl);
    // 4. x1 = x + ctx @ Wout  (fused 3-pass)
    hmma_gemm<3, 1, 0><<<dim3(DD / 128, MTOK / 128), 256, GEMM_SMEM3>>>(
        ch, cl, woh, wol, x, nullptr, x1, nullptr, nullptr, MTOK, DD, DD);
    // 5. LN2 -> fp16 hi
    ln_fp16_kernel<0><<<MTOK, 256>>>(x1, ln2_g, ln2_b, zh, nullptr);
    // 6. h = gelu(z2 @ W1 + b1) -> fp16
    hmma_gemm<1, 2, 1><<<dim3(4 * DD / 128, MTOK / 128), 256, GEMM_SMEM1>>>(
        zh, nullptr, w1t, nullptr, nullptr, b1, nullptr, hb, nullptr, MTOK, 4 * DD, DD);
    // 7. out = x1 + h @ W2 + b2
    hmma_gemm<1, 3, 0><<<dim3(DD / 128, MTOK / 128), 256, GEMM_SMEM1>>>(
        hb, nullptr, w2t, nullptr, x1, b2, out, nullptr, nullptr, MTOK, DD, 4 * DD);
}

// round 14
// speedup vs baseline: 7.6998x; 1.0342x over previous
#include <cuda_runtime.h>
#include <cuda_fp16.h>
#include <math.h>

// Problem constants
#define NB 4
#define TT 2048
#define DD 1024
#define HH 16
#define DKK 64
#define MTOK (NB*TT)          // 8192 tokens

// ---------------- scratch (device globals; no allocation allowed) -----------
__device__ float g_x1 [MTOK * DD];        // 32 MB fp32
__device__ __half g_qh [MTOK * 3 * DD];   // qkv hi (48 MB)
__device__ __half g_ql [MTOK * 3 * DD];   // qkv lo
__device__ __half g_zh [MTOK * DD];       // LN out hi
__device__ __half g_zl [MTOK * DD];       // LN out lo
__device__ __half g_ch [MTOK * DD];       // ctx hi
__device__ __half g_hb [MTOK * 4 * DD];   // FFN hidden (fp16)
__device__ __half g_wqh[3 * DD * DD];     // Wqkv^T hi  [3072,1024]
__device__ __half g_wql[3 * DD * DD];
__device__ __half g_woh[DD * DD];         // Wout^T hi  [1024,1024]
__device__ __half g_wol[DD * DD];
__device__ __half g_w1t[4 * DD * DD];     // W1^T [4096,1024]
__device__ __half g_w2t[DD * 4 * DD];     // W2^T [1024,4096]

// ---------------- PTX helpers ------------------------------------------------
__device__ __forceinline__ unsigned smem_u32(const void* p) {
    unsigned a;
    asm("{ .reg .u64 t; cvta.to.shared.u64 t, %1; cvt.u32.u64 %0, t; }"
        : "=r"(a) : "l"(p));
    return a;
}
__device__ __forceinline__ void cp16(unsigned dst, const void* src) {
    asm volatile("cp.async.cg.shared.global [%0], [%1], 16;"
                 :: "r"(dst), "l"(src) : "memory");
}
__device__ __forceinline__ void cpcommit() {
    asm volatile("cp.async.commit_group;" ::: "memory");
}
template <int N> __device__ __forceinline__ void cpwait() {
    asm volatile("cp.async.wait_group %0;" :: "n"(N) : "memory");
}
__device__ __forceinline__ void ldsm4(unsigned* r, unsigned addr) {
    asm volatile("ldmatrix.sync.aligned.m8n8.x4.shared.b16 {%0,%1,%2,%3}, [%4];"
                 : "=r"(r[0]), "=r"(r[1]), "=r"(r[2]), "=r"(r[3]) : "r"(addr));
}
__device__ __forceinline__ void ldsm4t(unsigned* r, unsigned addr) {
    asm volatile("ldmatrix.sync.aligned.m8n8.x4.trans.shared.b16 {%0,%1,%2,%3}, [%4];"
                 : "=r"(r[0]), "=r"(r[1]), "=r"(r[2]), "=r"(r[3]) : "r"(addr));
}
__device__ __forceinline__ void mma16816(float* d, const unsigned* a,
                                         const unsigned* b) {
    asm volatile(
        "mma.sync.aligned.m16n8k16.row.col.f32.f16.f16.f32 "
        "{%0,%1,%2,%3}, {%4,%5,%6,%7}, {%8,%9}, {%0,%1,%2,%3};"
        : "+f"(d[0]), "+f"(d[1]), "+f"(d[2]), "+f"(d[3])
        : "r"(a[0]), "r"(a[1]), "r"(a[2]), "r"(a[3]), "r"(b[0]), "r"(b[1]));
}
__device__ __forceinline__ unsigned h2u(__half2 v) {
    union { __half2 h; unsigned u; } c; c.h = v; return c.u;
}

#define GSW(off) ((off) ^ ((((unsigned)(off)) >> 3) & 0x70u))

// ---------------- fused multi-pass HMMA fp16 GEMM ----------------------------
// C[M,N] = A@B^T. NPASS=3: (Ah+Al)@(Bh+Bl) minus lo*lo, fused in one k-loop.
// NPASS=2: Ah@(Bh+Bl).  NPASS=1: Ah@Bh.
// A[M,K], B[N,K] K-major fp16. Tile 128x128, k-chunk 64, 3-stage pipeline,
// single __syncthreads per k-iteration.
// EPI: 0 none, 1 +R, 2 +bias,gelu, 3 +bias+R.
// OUTB: 0 fp32 Cf, 1 fp16 Cb, 2 fp16 hi->Cb + lo->Cb2.
#define GEMM_SMEM3 (3 * 65536 + 1024)
#define GEMM_SMEM2 (3 * 49152 + 1024)
#define GEMM_SMEM1 (3 * 32768 + 1024)

template <int NPASS, int EPI, int OUTB>
__global__ __launch_bounds__(256) void hmma_gemm(
    const __half* __restrict__ Ah, const __half* __restrict__ Al,
    const __half* __restrict__ Bh, const __half* __restrict__ Bl,
    const float* __restrict__ R, const float* __restrict__ bias,
    float* __restrict__ Cf, __half* __restrict__ Cb,
    __half* __restrict__ Cb2,
    int M, int N, int K)
{
    constexpr unsigned TS  = (NPASS == 3) ? 65536u : ((NPASS == 2) ? 49152u : 32768u);
    constexpr unsigned BOF = (NPASS == 3) ? 32768u : 16384u;   // B-hi offset

    extern __shared__ char dsm[];
    unsigned smb    = smem_u32(dsm);
    unsigned tile_u = (smb + 1023u) & ~1023u;

    int tid = threadIdx.x, wid = tid >> 5, lane = tid & 31;
    int wm = wid & 3, wn = wid >> 2;
    int bm = blockIdx.y << 7, bn = blockIdx.x << 7;

    const int nk = K >> 6;

    int li  = lane & 7, sub = lane >> 3;
    unsigned aoff[2];
#pragma unroll
    for (int mt = 0; mt < 2; mt++) {
        unsigned r = (unsigned)(wm * 32 + mt * 16 + (sub & 1) * 8 + li);
        aoff[mt] = (r << 7) + (unsigned)((sub >> 1) << 4);
        aoff[mt] ^= (r & 7u) << 4;
    }
    unsigned boff[4];
#pragma unroll
    for (int ng = 0; ng < 4; ng++) {
        unsigned r = (unsigned)(wn * 64 + ng * 16 + (sub >> 1) * 8 + li);
        boff[ng] = (r << 7) + (unsigned)((sub & 1) << 4);
        boff[ng] ^= (r & 7u) << 4;
    }

    int ld_row = tid >> 3;
    int ld_kb  = (tid & 7) << 4;

    float d[2][8][4];
#pragma unroll
    for (int mt = 0; mt < 2; mt++)
#pragma unroll
        for (int nt = 0; nt < 8; nt++)
#pragma unroll
            for (int j = 0; j < 4; j++) d[mt][nt][j] = 0.f;

#define ISSUE(it_) do {                                                        \
    unsigned base_ = tile_u + (unsigned)((it_) % 3) * TS;                      \
    const __half* AsH_ = Ah + (size_t)bm * K + ((it_) << 6);                   \
    const __half* BsH_ = Bh + (size_t)bn * K + ((it_) << 6);                   \
    _Pragma("unroll")                                                          \
    for (int i_ = 0; i_ < 4; i_++) {                                           \
        int row_ = ld_row + i_ * 32;                                           \
        unsigned so_ = GSW((unsigned)((row_ << 7) | ld_kb));                   \
        cp16(base_ + so_, (const char*)(AsH_ + (size_t)row_ * K) + ld_kb);     \
        cp16(base_ + BOF + so_, (const char*)(BsH_ + (size_t)row_ * K) + ld_kb); \
        if (NPASS >= 2) {                                                      \
            const __half* BsL_ = Bl + (size_t)bn * K + ((it_) << 6);           \
            cp16(base_ + BOF + 16384u + so_,                                   \
                 (const char*)(BsL_ + (size_t)row_ * K) + ld_kb);              \
        }                                                                      \
        if (NPASS == 3) {                                                      \
            const __half* AsL_ = Al + (size_t)bm * K + ((it_) << 6);           \
            cp16(base_ + 16384u + so_,                                         \
                 (const char*)(AsL_ + (size_t)row_ * K) + ld_kb);              \
        }                                                                      \
    }                                                                          \
    cpcommit();                                                                \
} while (0)

    ISSUE(0);
    if (nk > 1) ISSUE(1);

    for (int it = 0; it < nk; ++it) {
        if (it + 1 < nk) cpwait<1>(); else cpwait<0>();
        __syncthreads();
        if (it + 2 < nk) ISSUE(it + 2);
        unsigned ab = tile_u + (unsigned)(it % 3) * TS;
        unsigned bb = ab + BOF;
#pragma unroll
        for (int ks = 0; ks < 4; ks++) {
            unsigned kx = (unsigned)(ks << 5);
            unsigned aH[2][4], aL[2][4];
#pragma unroll
            for (int mt = 0; mt < 2; mt++) ldsm4(aH[mt], ab + (aoff[mt] ^ kx));
            if (NPASS == 3) {
#pragma unroll
                for (int mt = 0; mt < 2; mt++)
                    ldsm4(aL[mt], ab + 16384u + (aoff[mt] ^ kx));
            }
#pragma unroll
            for (int ng = 0; ng < 4; ng++) {
                unsigned bH[4];
                ldsm4(bH, bb + (boff[ng] ^ kx));
#pragma unroll
                for (int mt = 0; mt < 2; mt++) {
                    mma16816(d[mt][2 * ng + 0], aH[mt], &bH[0]);
                    mma16816(d[mt][2 * ng + 1], aH[mt], &bH[2]);
                }
                if (NPASS >= 2) {
                    unsigned bL[4];
                    ldsm4(bL, bb + 16384u + (boff[ng] ^ kx));
#pragma unroll
                    for (int mt = 0; mt < 2; mt++) {
                        mma16816(d[mt][2 * ng + 0], aH[mt], &bL[0]);
                        mma16816(d[mt][2 * ng + 1], aH[mt], &bL[2]);
                    }
                }
                if (NPASS == 3) {
#pragma unroll
                    for (int mt = 0; mt < 2; mt++) {
                        mma16816(d[mt][2 * ng + 0], aL[mt], &bH[0]);
                        mma16816(d[mt][2 * ng + 1], aL[mt], &bH[2]);
                    }
                }
            }
        }
    }
#undef ISSUE

    int qr = lane >> 2;
    int qc = (lane & 3) << 1;
#pragma unroll
    for (int mt = 0; mt < 2; mt++) {
#pragma unroll
        for (int nt = 0; nt < 8; nt++) {
            int r0 = bm + wm * 32 + mt * 16 + qr;
            int c  = bn + wn * 64 + nt * 8 + qc;
            float v[4];
#pragma unroll
            for (int j = 0; j < 4; j++) v[j] = d[mt][nt][j];
            if (EPI == 2 || EPI == 3) {
                float2 bv = *(const float2*)(bias + c);
                v[0] += bv.x; v[1] += bv.y; v[2] += bv.x; v[3] += bv.y;
            }
            if (EPI == 2) {
#pragma unroll
                for (int j = 0; j < 4; j++)
                    v[j] = 0.5f * v[j] * (1.0f + erff(v[j] * 0.7071067811865475f));
            }
            if (EPI == 1 || EPI == 3) {
                float2 r1 = *(const float2*)(R + (size_t)r0 * N + c);
                float2 r2 = *(const float2*)(R + (size_t)(r0 + 8) * N + c);
                v[0] += r1.x; v[1] += r1.y; v[2] += r2.x; v[3] += r2.y;
            }
            if (OUTB == 1) {
                *(__half2*)(Cb + (size_t)r0 * N + c) =
                    __floats2half2_rn(v[0], v[1]);
                *(__half2*)(Cb + (size_t)(r0 + 8) * N + c) =
                    __floats2half2_rn(v[2], v[3]);
            } else if (OUTB == 2) {
                __half2 h0 = __floats2half2_rn(v[0], v[1]);
                __half2 h1 = __floats2half2_rn(v[2], v[3]);
                *(__half2*)(Cb + (size_t)r0 * N + c) = h0;
                *(__half2*)(Cb + (size_t)(r0 + 8) * N + c) = h1;
                *(__half2*)(Cb2 + (size_t)r0 * N + c) =
                    __floats2half2_rn(v[0] - __half2float(__low2half(h0)),
                                      v[1] - __half2float(__high2half(h0)));
                *(__half2*)(Cb2 + (size_t)(r0 + 8) * N + c) =
                    __floats2half2_rn(v[2] - __half2float(__low2half(h1)),
                                      v[3] - __half2float(__high2half(h1)));
            } else {
                *(float2*)(Cf + (size_t)r0 * N + c) = make_float2(v[0], v[1]);
                *(float2*)(Cf + (size_t)(r0 + 8) * N + c) = make_float2(v[2], v[3]);
            }
        }
    }
}

// ---------------- HMMA flash attention --------------------------------------
// CTA: 128 q-rows of one (n,h); iterate 32 s-blocks of 64. 8 warps x 16 rows.
// QK^T 3-pass split fp16, online softmax fp32, PV 1-pass fp16 (Ph*Vh).
// 3-stage pipeline, single __syncthreads per iteration.
// SMEM: QH 0 (16K), QL 16K, buf b at 32K+(it%3)*24K: {KH,KL,VH} 8K each,
//       mask at 106496 + (it%3)*256. Total 107264 B.
#define FK_QH   0u
#define FK_QL   16384u
#define FK_KV   32768u
#define FK_BUF  24576u
#define FK_MASK 106496u
#define FK_SMEM 107264

__global__ __launch_bounds__(256) void flash_hmma(
    const __half* __restrict__ qh, const __half* __restrict__ ql,
    const float* __restrict__ mask,
    __half* __restrict__ ch)
{
    extern __shared__ char fsm[];
    unsigned sb = smem_u32(fsm);

    int tid = threadIdx.x, wid = tid >> 5, lane = tid & 31;
    int qr = lane >> 2, tig = lane & 3;
    int bh = blockIdx.y, n = bh >> 4, h = bh & 15;
    int q0 = blockIdx.x << 7;
    const float* maskp = mask + (size_t)n * TT;

    const char* qbH = (const char*)(qh + (size_t)(n * TT + q0) * 3072) + h * 128;
    const char* qbL = (const char*)(ql + (size_t)(n * TT + q0) * 3072) + h * 128;
    const char* kvH = (const char*)(qh + (size_t)n * TT * 3072) + h * 128;
    const char* kvL = (const char*)(ql + (size_t)n * TT * 3072) + h * 128;

#define FK_ISSUE(it_) do {                                                     \
    int s0_ = (it_) << 6;                                                      \
    unsigned kb_ = sb + FK_KV + (unsigned)((it_) % 3) * FK_BUF;                \
    _Pragma("unroll")                                                          \
    for (int i_ = 0; i_ < 2; i_++) {                                           \
        int v_ = tid + (i_ << 8);                                              \
        int row_ = v_ >> 3; int kb2_ = (v_ & 7) << 4;                          \
        unsigned so_ = GSW((unsigned)((row_ << 7) | kb2_));                    \
        size_t gb_ = (size_t)(s0_ + row_) * 6144 + kb2_;                       \
        cp16(kb_ + so_,          kvH + gb_ + 2048);                            \
        cp16(kb_ + 8192u + so_,  kvL + gb_ + 2048);                            \
        cp16(kb_ + 16384u + so_, kvH + gb_ + 4096);                            \
    }                                                                          \
    if (tid < 16)                                                              \
        cp16(sb + FK_MASK + (unsigned)((it_) % 3) * 256u + (tid << 4),         \
             maskp + s0_ + tid * 4);                                           \
    cpcommit();                                                                \
} while (0)

    // prologue: Q + first KV block in group 0, second KV block in group 1
#pragma unroll
    for (int i = 0; i < 4; i++) {
        int v = tid + (i << 8);
        int row = v >> 3; int kb = (v & 7) << 4;
        unsigned so = GSW((unsigned)((row << 7) | kb));
        cp16(sb + FK_QH + so, qbH + (size_t)row * 6144 + kb);
        cp16(sb + FK_QL + so, qbL + (size_t)row * 6144 + kb);
    }
    FK_ISSUE(0);
    FK_ISSUE(1);

    // fragment offsets
    int li = lane & 7, sub = lane >> 3;
    unsigned m4 = (unsigned)li << 4;
    unsigned qoff;
    {
        unsigned r = (unsigned)(wid * 16 + (sub & 1) * 8 + li);
        qoff = (r << 7) + ((unsigned)((sub >> 1) << 4) ^ m4);
    }
    unsigned koff[4];
#pragma unroll
    for (int ng = 0; ng < 4; ng++) {
        unsigned r = (unsigned)(ng * 16 + (sub >> 1) * 8 + li);
        koff[ng] = (r << 7) + ((unsigned)((sub & 1) << 4) ^ m4);
    }
    unsigned vrow = (unsigned)((sub & 1) * 8 + li) << 7;
    unsigned vb[4];
#pragma unroll
    for (int dt = 0; dt < 4; dt++)
        vb[dt] = ((unsigned)((sub >> 1) << 4) + (unsigned)(dt << 5)) ^ m4;

    unsigned qHf[4][4], qLf[4][4];     // hoisted Q fragments (loop-invariant)
    float sS[8][4], oO[8][4];
    float mM[2] = {-1e30f, -1e30f}, lL[2] = {0.f, 0.f};
#pragma unroll
    for (int nt = 0; nt < 8; nt++)
#pragma unroll
        for (int j = 0; j < 4; j++) oO[nt][j] = 0.f;

    for (int it = 0; it < TT / 64; ++it) {
        if (it == TT / 64 - 1) cpwait<0>(); else cpwait<1>();
        __syncthreads();
        if (it + 2 < TT / 64) FK_ISSUE(it + 2);
        unsigned kb0 = sb + FK_KV + (unsigned)(it % 3) * FK_BUF;

        if (it == 0) {
#pragma unroll
            for (int ks = 0; ks < 4; ks++) {
                unsigned kx = (unsigned)(ks << 5);
                ldsm4(qHf[ks], sb + FK_QH + (qoff ^ kx));
                ldsm4(qLf[ks], sb + FK_QL + (qoff ^ kx));
            }
        }

        // ---- S = Q@K^T (3-pass fp16) ----
#pragma unroll
        for (int nt = 0; nt < 8; nt++)
#pragma unroll
            for (int j = 0; j < 4; j++) sS[nt][j] = 0.f;
#pragma unroll
        for (int ks = 0; ks < 4; ks++) {
            unsigned kx = (unsigned)(ks << 5);
#pragma unroll
            for (int ng = 0; ng < 4; ng++) {
                unsigned bH[4], bL[4];
                ldsm4(bH, kb0 + (koff[ng] ^ kx));
                ldsm4(bL, kb0 + 8192u + (koff[ng] ^ kx));
                mma16816(sS[2 * ng + 0], qHf[ks], &bH[0]);
                mma16816(sS[2 * ng + 1], qHf[ks], &bH[2]);
                mma16816(sS[2 * ng + 0], qHf[ks], &bL[0]);
                mma16816(sS[2 * ng + 1], qHf[ks], &bL[2]);
                mma16816(sS[2 * ng + 0], qLf[ks], &bH[0]);
                mma16816(sS[2 * ng + 1], qLf[ks], &bH[2]);
            }
        }

        // ---- scale + mask ----
        const float* mbuf = (const float*)(fsm + FK_MASK + (it % 3) * 256);
#pragma unroll
        for (int nt = 0; nt < 8; nt++) {
            float2 mv = *(const float2*)(mbuf + nt * 8 + 2 * tig);
            sS[nt][0] = fmaf(sS[nt][0], 0.125f, mv.x);
            sS[nt][1] = fmaf(sS[nt][1], 0.125f, mv.y);
            sS[nt][2] = fmaf(sS[nt][2], 0.125f, mv.x);
            sS[nt][3] = fmaf(sS[nt][3], 0.125f, mv.y);
        }

        // ---- online softmax (2 rows/thread) ----
#pragma unroll
        for (int i = 0; i < 2; i++) {
            int ib = 2 * i;
            float mx = -1e30f;
#pragma unroll
            for (int nt = 0; nt < 8; nt++)
                mx = fmaxf(mx, fmaxf(sS[nt][ib], sS[nt][ib + 1]));
            mx = fmaxf(mx, __shfl_xor_sync(0xffffffffu, mx, 1));
            mx = fmaxf(mx, __shfl_xor_sync(0xffffffffu, mx, 2));
            float mnew  = fmaxf(mM[i], mx);
            float alpha = __expf(mM[i] - mnew);
            float rsum = 0.f;
#pragma unroll
            for (int nt = 0; nt < 8; nt++) {
                float p0 = __expf(sS[nt][ib]     - mnew);
                float p1 = __expf(sS[nt][ib + 1] - mnew);
                sS[nt][ib] = p0; sS[nt][ib + 1] = p1;
                rsum += p0 + p1;
            }
            rsum += __shfl_xor_sync(0xffffffffu, rsum, 1);
            rsum += __shfl_xor_sync(0xffffffffu, rsum, 2);
            lL[i] = lL[i] * alpha + rsum;
            mM[i] = mnew;
#pragma unroll
            for (int nt = 0; nt < 8; nt++) {
                oO[nt][ib] *= alpha; oO[nt][ib + 1] *= alpha;
            }
        }

        // ---- O += P@V (1-pass fp16: Ph*Vh) ----
#pragma unroll
        for (int kt = 0; kt < 4; kt++) {
            unsigned ah[4];
#pragma unroll
            for (int half = 0; half < 2; half++) {
                int nt = 2 * kt + half;
                ah[2 * half + 0] = h2u(__floats2half2_rn(sS[nt][0], sS[nt][1]));
                ah[2 * half + 1] = h2u(__floats2half2_rn(sS[nt][2], sS[nt][3]));
            }
            unsigned vkb = kb0 + 16384u + (unsigned)(kt << 11) + vrow;
#pragma unroll
            for (int dt = 0; dt < 4; dt++) {
                unsigned bv[4];
                ldsm4t(bv, vkb + vb[dt]);
                mma16816(oO[2 * dt + 0], ah, &bv[0]);
                mma16816(oO[2 * dt + 1], ah, &bv[2]);
            }
        }
    }
#undef FK_ISSUE

    // ---- write ctx hi ----
#pragma unroll
    for (int i = 0; i < 2; i++) {
        float inv = 1.f / lL[i];
        int ib = 2 * i;
        size_t tok = (size_t)(n * TT + q0 + wid * 16 + qr + i * 8);
#pragma unroll
        for (int nt = 0; nt < 8; nt++) {
            float v0 = oO[nt][ib] * inv, v1 = oO[nt][ib + 1] * inv;
            int col = h * 64 + nt * 8 + 2 * tig;
            *(__half2*)(ch + tok * DD + col) = __floats2half2_rn(v0, v1);
        }
    }
}

// ---------------- LayerNorm -> fp16 hi(/lo) ----------------------------------
template <int WLO>
__global__ __launch_bounds__(256) void ln_fp16_kernel(
    const float* __restrict__ x, const float* __restrict__ g,
    const float* __restrict__ b,
    __half* __restrict__ zh, __half* __restrict__ zl)
{
    int row = blockIdx.x;
    const float* xr = x + (size_t)row * DD;
    int tid = threadIdx.x;
    float v[4];
    float sum = 0.f, sq = 0.f;
#pragma unroll
    for (int i = 0; i < 4; i++) {
        v[i] = xr[tid + i * 256];
        sum += v[i]; sq += v[i] * v[i];
    }
#pragma unroll
    for (int o = 16; o > 0; o >>= 1) {
        sum += __shfl_xor_sync(0xffffffffu, sum, o);
        sq  += __shfl_xor_sync(0xffffffffu, sq,  o);
    }
    __shared__ float red[2][8];
    int w = tid >> 5, l = tid & 31;
    if (l == 0) { red[0][w] = sum; red[1][w] = sq; }
    __syncthreads();
    if (tid < 32) {
        float s = (tid < 8) ? red[0][tid] : 0.f;
        float q = (tid < 8) ? red[1][tid] : 0.f;
#pragma unroll
        for (int o = 4; o > 0; o >>= 1) {
            s += __shfl_xor_sync(0xffffffffu, s, o);
            q += __shfl_xor_sync(0xffffffffu, q, o);
        }
        if (tid == 0) { red[0][0] = s; red[1][0] = q; }
    }
    __syncthreads();
    float mu   = red[0][0] * (1.f / DD);
    float var  = red[1][0] * (1.f / DD) - mu * mu;
    float rstd = rsqrtf(var + 1e-5f);
#pragma unroll
    for (int i = 0; i < 4; i++) {
        int c = tid + i * 256;
        float y = (v[i] - mu) * rstd * g[c] + b[c];
        __half hh = __float2half_rn(y);
        zh[(size_t)row * DD + c] = hh;
        if (WLO)
            zl[(size_t)row * DD + c] = __float2half_rn(y - __half2float(hh));
    }
}

// ---------------- weight transpose W[K,N] -> T[N,K] fp16 hi(/lo) -------------
// tile: 32 (K) x 128 (N). float4 loads, warp-per-row half2 stores.
template <int SPLIT>
__global__ __launch_bounds__(256) void transpose_kernel(
    const float* __restrict__ W, __half* __restrict__ Th,
    __half* __restrict__ Tl, int K, int N)
{
    __shared__ float t[32][129];
    int tid = threadIdx.x;
    int k0 = blockIdx.y * 32, n0 = blockIdx.x * 128;
    int kk = tid >> 3, nn = (tid & 7) * 4;
#pragma unroll
    for (int i = 0; i < 4; i++) {
        float4 v = *(const float4*)(W + (size_t)(k0 + kk) * N + n0 + i * 32 + nn);
        t[kk][i * 32 + nn + 0] = v.x; t[kk][i * 32 + nn + 1] = v.y;
        t[kk][i * 32 + nn + 2] = v.z; t[kk][i * 32 + nn + 3] = v.w;
    }
    __syncthreads();
    int wid = tid >> 5, lane = tid & 31;
    int k2 = (lane & 15) * 2;
#pragma unroll
    for (int i = 0; i < 8; i++) {
        int nrow = wid * 16 + i * 2 + (lane >> 4);
        float a = t[k2][nrow], b = t[k2 + 1][nrow];
        __half ha = __float2half_rn(a), hb = __float2half_rn(b);
        *(__half2*)(Th + (size_t)(n0 + nrow) * K + k0 + k2) = __halves2half2(ha, hb);
        if (SPLIT)
            *(__half2*)(Tl + (size_t)(n0 + nrow) * K + k0 + k2) =
                __halves2half2(__float2half_rn(a - __half2float(ha)),
                               __float2half_rn(b - __half2float(hb)));
    }
}

// ---------------- launch -----------------------------------------------------
extern "C" void kernel_launch(void* const* d_in, const int* in_sizes, int n_in,
                              void* d_out, int out_size)
{
    const float* x     = (const float*)d_in[0];
    const float* mask  = (const float*)d_in[1];
    const float* Wqkv  = (const float*)d_in[2];
    const float* Wout  = (const float*)d_in[3];
    const float* ln1_g = (const float*)d_in[4];
    const float* ln1_b = (const float*)d_in[5];
    const float* ln2_g = (const float*)d_in[6];
    const float* ln2_b = (const float*)d_in[7];
    const float* W1    = (const float*)d_in[8];
    const float* b1    = (const float*)d_in[9];
    const float* W2    = (const float*)d_in[10];
    const float* b2    = (const float*)d_in[11];
    float* out = (float*)d_out;

    float *x1;
    __half *qh, *ql, *zh, *zl, *ch, *hb;
    __half *wqh, *wql, *woh, *wol, *w1t, *w2t;
    cudaGetSymbolAddress((void**)&x1,  g_x1);
    cudaGetSymbolAddress((void**)&qh,  g_qh);
    cudaGetSymbolAddress((void**)&ql,  g_ql);
    cudaGetSymbolAddress((void**)&zh,  g_zh);
    cudaGetSymbolAddress((void**)&zl,  g_zl);
    cudaGetSymbolAddress((void**)&ch,  g_ch);
    cudaGetSymbolAddress((void**)&hb,  g_hb);
    cudaGetSymbolAddress((void**)&wqh, g_wqh);
    cudaGetSymbolAddress((void**)&wql, g_wql);
    cudaGetSymbolAddress((void**)&woh, g_woh);
    cudaGetSymbolAddress((void**)&wol, g_wol);
    cudaGetSymbolAddress((void**)&w1t, g_w1t);
    cudaGetSymbolAddress((void**)&w2t, g_w2t);

    cudaFuncSetAttribute(flash_hmma,
                         cudaFuncAttributeMaxDynamicSharedMemorySize, FK_SMEM);
    cudaFuncSetAttribute(hmma_gemm<3, 0, 2>,
                         cudaFuncAttributeMaxDynamicSharedMemorySize, GEMM_SMEM3);
    cudaFuncSetAttribute(hmma_gemm<2, 1, 0>,
                         cudaFuncAttributeMaxDynamicSharedMemorySize, GEMM_SMEM2);
    cudaFuncSetAttribute(hmma_gemm<1, 2, 1>,
                         cudaFuncAttributeMaxDynamicSharedMemorySize, GEMM_SMEM1);
    cudaFuncSetAttribute(hmma_gemm<1, 3, 0>,
                         cudaFuncAttributeMaxDynamicSharedMemorySize, GEMM_SMEM1);

    // 0. weight transposes + fp16 split
    transpose_kernel<1><<<dim3(3 * DD / 128, DD / 32), 256>>>(Wqkv, wqh, wql, DD, 3 * DD);
    transpose_kernel<1><<<dim3(DD / 128, DD / 32),     256>>>(Wout, woh, wol, DD, DD);
    transpose_kernel<0><<<dim3(4 * DD / 128, DD / 32), 256>>>(W1, w1t, nullptr, DD, 4 * DD);
    transpose_kernel<0><<<dim3(DD / 128, 4 * DD / 32), 256>>>(W2, w2t, nullptr, 4 * DD, DD);

    // 1. LN1 -> fp16 hi/lo
    ln_fp16_kernel<1><<<MTOK, 256>>>(x, ln1_g, ln1_b, zh, zl);
    // 2. QKV = z @ Wqkv  (fused 3-pass fp16) -> fp16 hi/lo directly
    hmma_gemm<3, 0, 2><<<dim3(3 * DD / 128, MTOK / 128), 256, GEMM_SMEM3>>>(
        zh, zl, wqh, wql, nullptr, nullptr, nullptr, qh, ql, MTOK, 3 * DD, DD);
    // 3. attention (HMMA, 3-pass QK / 1-pass PV) -> ctx hi
    flash_hmma<<<dim3(TT / 128, NB * HH), 256, FK_SMEM>>>(qh, ql, mask, ch);
    // 4. x1 = x + ctx @ Wout  (fused 2-pass: ch*Wh + ch*Wl)
    hmma_gemm<2, 1, 0><<<dim3(DD / 128, MTOK / 128), 256, GEMM_SMEM2>>>(
        ch, nullptr, woh, wol, x, nullptr, x1, nullptr, nullptr, MTOK, DD, DD);
    // 5. LN2 -> fp16 hi
    ln_fp16_kernel<0><<<MTOK, 256>>>(x1, ln2_g, ln2_b, zh, nullptr);
    // 6. h = gelu(z2 @ W1 + b1) -> fp16
    hmma_gemm<1, 2, 1><<<dim3(4 * DD / 128, MTOK / 128), 256, GEMM_SMEM1>>>(
        zh, nullptr, w1t, nullptr, nullptr, b1, nullptr, hb, nullptr, MTOK, 4 * DD, DD);
    // 7. out = x1 + h @ W2 + b2
    hmma_gemm<1, 3, 0><<<dim3(DD / 128, MTOK / 128), 256, GEMM_SMEM1>>>(
        hb, nullptr, w2t, nullptr, x1, b2, out, nullptr, nullptr, MTOK, DD, 4 * DD);
}

// round 15
// speedup vs baseline: 8.2447x; 1.0708x over previous
#include <cuda_runtime.h>
#include <cuda_fp16.h>
#include <math.h>

// Problem constants
#define NB 4
#define TT 2048
#define DD 1024
#define HH 16
#define DKK 64
#define MTOK (NB*TT)          // 8192 tokens

// ---------------- scratch (device globals; no allocation allowed) -----------
__device__ float g_x1 [MTOK * DD];        // 32 MB fp32
__device__ __half g_qh [MTOK * 3 * DD];   // qkv hi (48 MB)
__device__ __half g_ql [MTOK * 3 * DD];   // qkv lo (Q,K regions used)
__device__ __half g_zh [MTOK * DD];       // LN out hi
__device__ __half g_zl [MTOK * DD];       // LN out lo
__device__ __half g_ch [MTOK * DD];       // ctx hi
__device__ __half g_hb [MTOK * 4 * DD];   // FFN hidden (fp16)
__device__ __half g_wqh[3 * DD * DD];     // Wqkv^T hi  [3072,1024]
__device__ __half g_wql[3 * DD * DD];
__device__ __half g_woh[DD * DD];         // Wout^T hi  [1024,1024]
__device__ __half g_wol[DD * DD];
__device__ __half g_w1t[4 * DD * DD];     // W1^T [4096,1024]
__device__ __half g_w2t[DD * 4 * DD];     // W2^T [1024,4096]

// ---------------- PTX helpers ------------------------------------------------
__device__ __forceinline__ unsigned smem_u32(const void* p) {
    unsigned a;
    asm("{ .reg .u64 t; cvta.to.shared.u64 t, %1; cvt.u32.u64 %0, t; }"
        : "=r"(a) : "l"(p));
    return a;
}
__device__ __forceinline__ void cp16(unsigned dst, const void* src) {
    asm volatile("cp.async.cg.shared.global [%0], [%1], 16;"
                 :: "r"(dst), "l"(src) : "memory");
}
__device__ __forceinline__ void cpcommit() {
    asm volatile("cp.async.commit_group;" ::: "memory");
}
template <int N> __device__ __forceinline__ void cpwait() {
    asm volatile("cp.async.wait_group %0;" :: "n"(N) : "memory");
}
__device__ __forceinline__ void ldsm4(unsigned* r, unsigned addr) {
    asm volatile("ldmatrix.sync.aligned.m8n8.x4.shared.b16 {%0,%1,%2,%3}, [%4];"
                 : "=r"(r[0]), "=r"(r[1]), "=r"(r[2]), "=r"(r[3]) : "r"(addr));
}
__device__ __forceinline__ void ldsm4t(unsigned* r, unsigned addr) {
    asm volatile("ldmatrix.sync.aligned.m8n8.x4.trans.shared.b16 {%0,%1,%2,%3}, [%4];"
                 : "=r"(r[0]), "=r"(r[1]), "=r"(r[2]), "=r"(r[3]) : "r"(addr));
}
__device__ __forceinline__ void mma16816(float* d, const unsigned* a,
                                         const unsigned* b) {
    asm volatile(
        "mma.sync.aligned.m16n8k16.row.col.f32.f16.f16.f32 "
        "{%0,%1,%2,%3}, {%4,%5,%6,%7}, {%8,%9}, {%0,%1,%2,%3};"
        : "+f"(d[0]), "+f"(d[1]), "+f"(d[2]), "+f"(d[3])
        : "r"(a[0]), "r"(a[1]), "r"(a[2]), "r"(a[3]), "r"(b[0]), "r"(b[1]));
}
__device__ __forceinline__ unsigned h2u(__half2 v) {
    union { __half2 h; unsigned u; } c; c.h = v; return c.u;
}

#define GSW(off) ((off) ^ ((((unsigned)(off)) >> 3) & 0x70u))

// ---------------- fused multi-pass HMMA fp16 GEMM ----------------------------
// C[M,N] = A@B^T. NPASS=3: Ah*Bh+Ah*Bl+Al*Bh fused. NPASS=2: Ah*(Bh+Bl).
// NPASS=1: Ah*Bh.  A[M,K], B[N,K] K-major fp16. Tile 128x128, k-chunk 64,
// 3-stage pipeline, single __syncthreads per k-iteration.
// ldc: row stride of C (and R). N is the GEMM width (B rows).
// EPI: 0 none, 1 +R, 2 +bias,gelu, 3 +bias+R.
// OUTB: 0 fp32 Cf, 1 fp16 Cb, 2 fp16 hi->Cb + lo->Cb2.
#define GEMM_SMEM3 (3 * 65536 + 1024)
#define GEMM_SMEM2 (3 * 49152 + 1024)
#define GEMM_SMEM1 (3 * 32768 + 1024)

template <int NPASS, int EPI, int OUTB>
__global__ __launch_bounds__(256) void hmma_gemm(
    const __half* __restrict__ Ah, const __half* __restrict__ Al,
    const __half* __restrict__ Bh, const __half* __restrict__ Bl,
    const float* __restrict__ R, const float* __restrict__ bias,
    float* __restrict__ Cf, __half* __restrict__ Cb,
    __half* __restrict__ Cb2,
    int M, int N, int K, int ldc)
{
    constexpr unsigned TS  = (NPASS == 3) ? 65536u : ((NPASS == 2) ? 49152u : 32768u);
    constexpr unsigned BOF = (NPASS == 3) ? 32768u : 16384u;   // B-hi offset

    extern __shared__ char dsm[];
    unsigned smb    = smem_u32(dsm);
    unsigned tile_u = (smb + 1023u) & ~1023u;

    int tid = threadIdx.x, wid = tid >> 5, lane = tid & 31;
    int wm = wid & 3, wn = wid >> 2;
    int bm = blockIdx.y << 7, bn = blockIdx.x << 7;

    const int nk = K >> 6;

    int li  = lane & 7, sub = lane >> 3;
    unsigned aoff[2];
#pragma unroll
    for (int mt = 0; mt < 2; mt++) {
        unsigned r = (unsigned)(wm * 32 + mt * 16 + (sub & 1) * 8 + li);
        aoff[mt] = (r << 7) + (unsigned)((sub >> 1) << 4);
        aoff[mt] ^= (r & 7u) << 4;
    }
    unsigned boff[4];
#pragma unroll
    for (int ng = 0; ng < 4; ng++) {
        unsigned r = (unsigned)(wn * 64 + ng * 16 + (sub >> 1) * 8 + li);
        boff[ng] = (r << 7) + (unsigned)((sub & 1) << 4);
        boff[ng] ^= (r & 7u) << 4;
    }

    int ld_row = tid >> 3;
    int ld_kb  = (tid & 7) << 4;

    float d[2][8][4];
#pragma unroll
    for (int mt = 0; mt < 2; mt++)
#pragma unroll
        for (int nt = 0; nt < 8; nt++)
#pragma unroll
            for (int j = 0; j < 4; j++) d[mt][nt][j] = 0.f;

#define ISSUE(it_) do {                                                        \
    unsigned base_ = tile_u + (unsigned)((it_) % 3) * TS;                      \
    const __half* AsH_ = Ah + (size_t)bm * K + ((it_) << 6);                   \
    const __half* BsH_ = Bh + (size_t)bn * K + ((it_) << 6);                   \
    _Pragma("unroll")                                                          \
    for (int i_ = 0; i_ < 4; i_++) {                                           \
        int row_ = ld_row + i_ * 32;                                           \
        unsigned so_ = GSW((unsigned)((row_ << 7) | ld_kb));                   \
        cp16(base_ + so_, (const char*)(AsH_ + (size_t)row_ * K) + ld_kb);     \
        cp16(base_ + BOF + so_, (const char*)(BsH_ + (size_t)row_ * K) + ld_kb); \
        if (NPASS >= 2) {                                                      \
            const __half* BsL_ = Bl + (size_t)bn * K + ((it_) << 6);           \
            cp16(base_ + BOF + 16384u + so_,                                   \
                 (const char*)(BsL_ + (size_t)row_ * K) + ld_kb);              \
        }                                                                      \
        if (NPASS == 3) {                                                      \
            const __half* AsL_ = Al + (size_t)bm * K + ((it_) << 6);           \
            cp16(base_ + 16384u + so_,                                         \
                 (const char*)(AsL_ + (size_t)row_ * K) + ld_kb);              \
        }                                                                      \
    }                                                                          \
    cpcommit();                                                                \
} while (0)

    ISSUE(0);
    if (nk > 1) ISSUE(1);

    for (int it = 0; it < nk; ++it) {
        if (it + 1 < nk) cpwait<1>(); else cpwait<0>();
        __syncthreads();
        if (it + 2 < nk) ISSUE(it + 2);
        unsigned ab = tile_u + (unsigned)(it % 3) * TS;
        unsigned bb = ab + BOF;
#pragma unroll
        for (int ks = 0; ks < 4; ks++) {
            unsigned kx = (unsigned)(ks << 5);
            unsigned aH[2][4], aL[2][4];
#pragma unroll
            for (int mt = 0; mt < 2; mt++) ldsm4(aH[mt], ab + (aoff[mt] ^ kx));
            if (NPASS == 3) {
#pragma unroll
                for (int mt = 0; mt < 2; mt++)
                    ldsm4(aL[mt], ab + 16384u + (aoff[mt] ^ kx));
            }
#pragma unroll
            for (int ng = 0; ng < 4; ng++) {
                unsigned bH[4];
                ldsm4(bH, bb + (boff[ng] ^ kx));
#pragma unroll
                for (int mt = 0; mt < 2; mt++) {
                    mma16816(d[mt][2 * ng + 0], aH[mt], &bH[0]);
                    mma16816(d[mt][2 * ng + 1], aH[mt], &bH[2]);
                }
                if (NPASS >= 2) {
                    unsigned bL[4];
                    ldsm4(bL, bb + 16384u + (boff[ng] ^ kx));
#pragma unroll
                    for (int mt = 0; mt < 2; mt++) {
                        mma16816(d[mt][2 * ng + 0], aH[mt], &bL[0]);
                        mma16816(d[mt][2 * ng + 1], aH[mt], &bL[2]);
                    }
                }
                if (NPASS == 3) {
#pragma unroll
                    for (int mt = 0; mt < 2; mt++) {
                        mma16816(d[mt][2 * ng + 0], aL[mt], &bH[0]);
                        mma16816(d[mt][2 * ng + 1], aL[mt], &bH[2]);
                    }
                }
            }
        }
    }
#undef ISSUE

    int qr = lane >> 2;
    int qc = (lane & 3) << 1;
#pragma unroll
    for (int mt = 0; mt < 2; mt++) {
#pragma unroll
        for (int nt = 0; nt < 8; nt++) {
            int r0 = bm + wm * 32 + mt * 16 + qr;
            int c  = bn + wn * 64 + nt * 8 + qc;
            float v[4];
#pragma unroll
            for (int j = 0; j < 4; j++) v[j] = d[mt][nt][j];
            if (EPI == 2 || EPI == 3) {
                float2 bv = *(const float2*)(bias + c);
                v[0] += bv.x; v[1] += bv.y; v[2] += bv.x; v[3] += bv.y;
            }
            if (EPI == 2) {
#pragma unroll
                for (int j = 0; j < 4; j++)
                    v[j] = 0.5f * v[j] * (1.0f + erff(v[j] * 0.7071067811865475f));
            }
            if (EPI == 1 || EPI == 3) {
                float2 r1 = *(const float2*)(R + (size_t)r0 * ldc + c);
                float2 r2 = *(const float2*)(R + (size_t)(r0 + 8) * ldc + c);
                v[0] += r1.x; v[1] += r1.y; v[2] += r2.x; v[3] += r2.y;
            }
            if (OUTB == 1) {
                *(__half2*)(Cb + (size_t)r0 * ldc + c) =
                    __floats2half2_rn(v[0], v[1]);
                *(__half2*)(Cb + (size_t)(r0 + 8) * ldc + c) =
                    __floats2half2_rn(v[2], v[3]);
            } else if (OUTB == 2) {
                __half2 h0 = __floats2half2_rn(v[0], v[1]);
                __half2 h1 = __floats2half2_rn(v[2], v[3]);
                *(__half2*)(Cb + (size_t)r0 * ldc + c) = h0;
                *(__half2*)(Cb + (size_t)(r0 + 8) * ldc + c) = h1;
                *(__half2*)(Cb2 + (size_t)r0 * ldc + c) =
                    __floats2half2_rn(v[0] - __half2float(__low2half(h0)),
                                      v[1] - __half2float(__high2half(h0)));
                *(__half2*)(Cb2 + (size_t)(r0 + 8) * ldc + c) =
                    __floats2half2_rn(v[2] - __half2float(__low2half(h1)),
                                      v[3] - __half2float(__high2half(h1)));
            } else {
                *(float2*)(Cf + (size_t)r0 * ldc + c) = make_float2(v[0], v[1]);
                *(float2*)(Cf + (size_t)(r0 + 8) * ldc + c) = make_float2(v[2], v[3]);
            }
        }
    }
}

// ---------------- HMMA flash attention --------------------------------------
// CTA: 128 q-rows of one (n,h); iterate 32 s-blocks of 64. 8 warps x 16 rows.
// QK^T 3-pass split fp16, online softmax fp32, PV 1-pass fp16 (Ph*Vh).
// 3-stage pipeline, single __syncthreads per iteration.
#define FK_QH   0u
#define FK_QL   16384u
#define FK_KV   32768u
#define FK_BUF  24576u
#define FK_MASK 106496u
#define FK_SMEM 107264

__global__ __launch_bounds__(256) void flash_hmma(
    const __half* __restrict__ qh, const __half* __restrict__ ql,
    const float* __restrict__ mask,
    __half* __restrict__ ch)
{
    extern __shared__ char fsm[];
    unsigned sb = smem_u32(fsm);

    int tid = threadIdx.x, wid = tid >> 5, lane = tid & 31;
    int qr = lane >> 2, tig = lane & 3;
    int bh = blockIdx.y, n = bh >> 4, h = bh & 15;
    int q0 = blockIdx.x << 7;
    const float* maskp = mask + (size_t)n * TT;

    const char* qbH = (const char*)(qh + (size_t)(n * TT + q0) * 3072) + h * 128;
    const char* qbL = (const char*)(ql + (size_t)(n * TT + q0) * 3072) + h * 128;
    const char* kvH = (const char*)(qh + (size_t)n * TT * 3072) + h * 128;
    const char* kvL = (const char*)(ql + (size_t)n * TT * 3072) + h * 128;

#define FK_ISSUE(it_) do {                                                     \
    int s0_ = (it_) << 6;                                                      \
    unsigned kb_ = sb + FK_KV + (unsigned)((it_) % 3) * FK_BUF;                \
    _Pragma("unroll")                                                          \
    for (int i_ = 0; i_ < 2; i_++) {                                           \
        int v_ = tid + (i_ << 8);                                              \
        int row_ = v_ >> 3; int kb2_ = (v_ & 7) << 4;                          \
        unsigned so_ = GSW((unsigned)((row_ << 7) | kb2_));                    \
        size_t gb_ = (size_t)(s0_ + row_) * 6144 + kb2_;                       \
        cp16(kb_ + so_,          kvH + gb_ + 2048);                            \
        cp16(kb_ + 8192u + so_,  kvL + gb_ + 2048);                            \
        cp16(kb_ + 16384u + so_, kvH + gb_ + 4096);                            \
    }                                                                          \
    if (tid < 16)                                                              \
        cp16(sb + FK_MASK + (unsigned)((it_) % 3) * 256u + (tid << 4),         \
             maskp + s0_ + tid * 4);                                           \
    cpcommit();                                                                \
} while (0)

    // prologue
#pragma unroll
    for (int i = 0; i < 4; i++) {
        int v = tid + (i << 8);
        int row = v >> 3; int kb = (v & 7) << 4;
        unsigned so = GSW((unsigned)((row << 7) | kb));
        cp16(sb + FK_QH + so, qbH + (size_t)row * 6144 + kb);
        cp16(sb + FK_QL + so, qbL + (size_t)row * 6144 + kb);
    }
    FK_ISSUE(0);
    FK_ISSUE(1);

    // fragment offsets
    int li = lane & 7, sub = lane >> 3;
    unsigned m4 = (unsigned)li << 4;
    unsigned qoff;
    {
        unsigned r = (unsigned)(wid * 16 + (sub & 1) * 8 + li);
        qoff = (r << 7) + ((unsigned)((sub >> 1) << 4) ^ m4);
    }
    unsigned koff[4];
#pragma unroll
    for (int ng = 0; ng < 4; ng++) {
        unsigned r = (unsigned)(ng * 16 + (sub >> 1) * 8 + li);
        koff[ng] = (r << 7) + ((unsigned)((sub & 1) << 4) ^ m4);
    }
    unsigned vrow = (unsigned)((sub & 1) * 8 + li) << 7;
    unsigned vb[4];
#pragma unroll
    for (int dt = 0; dt < 4; dt++)
        vb[dt] = ((unsigned)((sub >> 1) << 4) + (unsigned)(dt << 5)) ^ m4;

    unsigned qHf[4][4], qLf[4][4];
    float sS[8][4], oO[8][4];
    float mM[2] = {-1e30f, -1e30f}, lL[2] = {0.f, 0.f};
#pragma unroll
    for (int nt = 0; nt < 8; nt++)
#pragma unroll
        for (int j = 0; j < 4; j++) oO[nt][j] = 0.f;

    for (int it = 0; it < TT / 64; ++it) {
        if (it == TT / 64 - 1) cpwait<0>(); else cpwait<1>();
        __syncthreads();
        if (it + 2 < TT / 64) FK_ISSUE(it + 2);
        unsigned kb0 = sb + FK_KV + (unsigned)(it % 3) * FK_BUF;

        if (it == 0) {
#pragma unroll
            for (int ks = 0; ks < 4; ks++) {
                unsigned kx = (unsigned)(ks << 5);
                ldsm4(qHf[ks], sb + FK_QH + (qoff ^ kx));
                ldsm4(qLf[ks], sb + FK_QL + (qoff ^ kx));
            }
        }

        // ---- S = Q@K^T (3-pass fp16) ----
#pragma unroll
        for (int nt = 0; nt < 8; nt++)
#pragma unroll
            for (int j = 0; j < 4; j++) sS[nt][j] = 0.f;
#pragma unroll
        for (int ks = 0; ks < 4; ks++) {
            unsigned kx = (unsigned)(ks << 5);
#pragma unroll
            for (int ng = 0; ng < 4; ng++) {
                unsigned bH[4], bL[4];
                ldsm4(bH, kb0 + (koff[ng] ^ kx));
                ldsm4(bL, kb0 + 8192u + (koff[ng] ^ kx));
                mma16816(sS[2 * ng + 0], qHf[ks], &bH[0]);
                mma16816(sS[2 * ng + 1], qHf[ks], &bH[2]);
                mma16816(sS[2 * ng + 0], qHf[ks], &bL[0]);
                mma16816(sS[2 * ng + 1], qHf[ks], &bL[2]);
                mma16816(sS[2 * ng + 0], qLf[ks], &bH[0]);
                mma16816(sS[2 * ng + 1], qLf[ks], &bH[2]);
            }
        }

        // ---- scale + mask ----
        const float* mbuf = (const float*)(fsm + FK_MASK + (it % 3) * 256);
#pragma unroll
        for (int nt = 0; nt < 8; nt++) {
            float2 mv = *(const float2*)(mbuf + nt * 8 + 2 * tig);
            sS[nt][0] = fmaf(sS[nt][0], 0.125f, mv.x);
            sS[nt][1] = fmaf(sS[nt][1], 0.125f, mv.y);
            sS[nt][2] = fmaf(sS[nt][2], 0.125f, mv.x);
            sS[nt][3] = fmaf(sS[nt][3], 0.125f, mv.y);
        }

        // ---- online softmax (2 rows/thread) ----
#pragma unroll
        for (int i = 0; i < 2; i++) {
            int ib = 2 * i;
            float mx = -1e30f;
#pragma unroll
            for (int nt = 0; nt < 8; nt++)
                mx = fmaxf(mx, fmaxf(sS[nt][ib], sS[nt][ib + 1]));
            mx = fmaxf(mx, __shfl_xor_sync(0xffffffffu, mx, 1));
            mx = fmaxf(mx, __shfl_xor_sync(0xffffffffu, mx, 2));
            float mnew  = fmaxf(mM[i], mx);
            float alpha = __expf(mM[i] - mnew);
            float rsum = 0.f;
#pragma unroll
            for (int nt = 0; nt < 8; nt++) {
                float p0 = __expf(sS[nt][ib]     - mnew);
                float p1 = __expf(sS[nt][ib + 1] - mnew);
                sS[nt][ib] = p0; sS[nt][ib + 1] = p1;
                rsum += p0 + p1;
            }
            rsum += __shfl_xor_sync(0xffffffffu, rsum, 1);
            rsum += __shfl_xor_sync(0xffffffffu, rsum, 2);
            lL[i] = lL[i] * alpha + rsum;
            mM[i] = mnew;
#pragma unroll
            for (int nt = 0; nt < 8; nt++) {
                oO[nt][ib] *= alpha; oO[nt][ib + 1] *= alpha;
            }
        }

        // ---- O += P@V (1-pass fp16: Ph*Vh) ----
#pragma unroll
        for (int kt = 0; kt < 4; kt++) {
            unsigned ah[4];
#pragma unroll
            for (int half = 0; half < 2; half++) {
                int nt = 2 * kt + half;
                ah[2 * half + 0] = h2u(__floats2half2_rn(sS[nt][0], sS[nt][1]));
                ah[2 * half + 1] = h2u(__floats2half2_rn(sS[nt][2], sS[nt][3]));
            }
            unsigned vkb = kb0 + 16384u + (unsigned)(kt << 11) + vrow;
#pragma unroll
            for (int dt = 0; dt < 4; dt++) {
                unsigned bv[4];
                ldsm4t(bv, vkb + vb[dt]);
                mma16816(oO[2 * dt + 0], ah, &bv[0]);
                mma16816(oO[2 * dt + 1], ah, &bv[2]);
            }
        }
    }
#undef FK_ISSUE

    // ---- write ctx hi ----
#pragma unroll
    for (int i = 0; i < 2; i++) {
        float inv = 1.f / lL[i];
        int ib = 2 * i;
        size_t tok = (size_t)(n * TT + q0 + wid * 16 + qr + i * 8);
#pragma unroll
        for (int nt = 0; nt < 8; nt++) {
            float v0 = oO[nt][ib] * inv, v1 = oO[nt][ib + 1] * inv;
            int col = h * 64 + nt * 8 + 2 * tig;
            *(__half2*)(ch + tok * DD + col) = __floats2half2_rn(v0, v1);
        }
    }
}

// ---------------- LayerNorm -> fp16 hi(/lo) ----------------------------------
template <int WLO>
__global__ __launch_bounds__(256) void ln_fp16_kernel(
    const float* __restrict__ x, const float* __restrict__ g,
    const float* __restrict__ b,
    __half* __restrict__ zh, __half* __restrict__ zl)
{
    int row = blockIdx.x;
    const float* xr = x + (size_t)row * DD;
    int tid = threadIdx.x;
    float v[4];
    float sum = 0.f, sq = 0.f;
#pragma unroll
    for (int i = 0; i < 4; i++) {
        v[i] = xr[tid + i * 256];
        sum += v[i]; sq += v[i] * v[i];
    }
#pragma unroll
    for (int o = 16; o > 0; o >>= 1) {
        sum += __shfl_xor_sync(0xffffffffu, sum, o);
        sq  += __shfl_xor_sync(0xffffffffu, sq,  o);
    }
    __shared__ float red[2][8];
    int w = tid >> 5, l = tid & 31;
    if (l == 0) { red[0][w] = sum; red[1][w] = sq; }
    __syncthreads();
    if (tid < 32) {
        float s = (tid < 8) ? red[0][tid] : 0.f;
        float q = (tid < 8) ? red[1][tid] : 0.f;
#pragma unroll
        for (int o = 4; o > 0; o >>= 1) {
            s += __shfl_xor_sync(0xffffffffu, s, o);
            q += __shfl_xor_sync(0xffffffffu, q, o);
        }
        if (tid == 0) { red[0][0] = s; red[1][0] = q; }
    }
    __syncthreads();
    float mu   = red[0][0] * (1.f / DD);
    float var  = red[1][0] * (1.f / DD) - mu * mu;
    float rstd = rsqrtf(var + 1e-5f);
#pragma unroll
    for (int i = 0; i < 4; i++) {
        int c = tid + i * 256;
        float y = (v[i] - mu) * rstd * g[c] + b[c];
        __half hh = __float2half_rn(y);
        zh[(size_t)row * DD + c] = hh;
        if (WLO)
            zl[(size_t)row * DD + c] = __float2half_rn(y - __half2float(hh));
    }
}

// ---------------- weight transpose W[K,N] -> T[N,K] fp16 hi(/lo) -------------
template <int SPLIT>
__global__ __launch_bounds__(256) void transpose_kernel(
    const float* __restrict__ W, __half* __restrict__ Th,
    __half* __restrict__ Tl, int K, int N)
{
    __shared__ float t[32][129];
    int tid = threadIdx.x;
    int k0 = blockIdx.y * 32, n0 = blockIdx.x * 128;
    int kk = tid >> 3, nn = (tid & 7) * 4;
#pragma unroll
    for (int i = 0; i < 4; i++) {
        float4 v = *(const float4*)(W + (size_t)(k0 + kk) * N + n0 + i * 32 + nn);
        t[kk][i * 32 + nn + 0] = v.x; t[kk][i * 32 + nn + 1] = v.y;
        t[kk][i * 32 + nn + 2] = v.z; t[kk][i * 32 + nn + 3] = v.w;
    }
    __syncthreads();
    int wid = tid >> 5, lane = tid & 31;
    int k2 = (lane & 15) * 2;
#pragma unroll
    for (int i = 0; i < 8; i++) {
        int nrow = wid * 16 + i * 2 + (lane >> 4);
        float a = t[k2][nrow], b = t[k2 + 1][nrow];
        __half ha = __float2half_rn(a), hb = __float2half_rn(b);
        *(__half2*)(Th + (size_t)(n0 + nrow) * K + k0 + k2) = __halves2half2(ha, hb);
        if (SPLIT)
            *(__half2*)(Tl + (size_t)(n0 + nrow) * K + k0 + k2) =
                __halves2half2(__float2half_rn(a - __half2float(ha)),
                               __float2half_rn(b - __half2float(hb)));
    }
}

// ---------------- launch -----------------------------------------------------
extern "C" void kernel_launch(void* const* d_in, const int* in_sizes, int n_in,
                              void* d_out, int out_size)
{
    const float* x     = (const float*)d_in[0];
    const float* mask  = (const float*)d_in[1];
    const float* Wqkv  = (const float*)d_in[2];
    const float* Wout  = (const float*)d_in[3];
    const float* ln1_g = (const float*)d_in[4];
    const float* ln1_b = (const float*)d_in[5];
    const float* ln2_g = (const float*)d_in[6];
    const float* ln2_b = (const float*)d_in[7];
    const float* W1    = (const float*)d_in[8];
    const float* b1    = (const float*)d_in[9];
    const float* W2    = (const float*)d_in[10];
    const float* b2    = (const float*)d_in[11];
    float* out = (float*)d_out;

    float *x1;
    __half *qh, *ql, *zh, *zl, *ch, *hb;
    __half *wqh, *wql, *woh, *wol, *w1t, *w2t;
    cudaGetSymbolAddress((void**)&x1,  g_x1);
    cudaGetSymbolAddress((void**)&qh,  g_qh);
    cudaGetSymbolAddress((void**)&ql,  g_ql);
    cudaGetSymbolAddress((void**)&zh,  g_zh);
    cudaGetSymbolAddress((void**)&zl,  g_zl);
    cudaGetSymbolAddress((void**)&ch,  g_ch);
    cudaGetSymbolAddress((void**)&hb,  g_hb);
    cudaGetSymbolAddress((void**)&wqh, g_wqh);
    cudaGetSymbolAddress((void**)&wql, g_wql);
    cudaGetSymbolAddress((void**)&woh, g_woh);
    cudaGetSymbolAddress((void**)&wol, g_wol);
    cudaGetSymbolAddress((void**)&w1t, g_w1t);
    cudaGetSymbolAddress((void**)&w2t, g_w2t);

    cudaFuncSetAttribute(flash_hmma,
                         cudaFuncAttributeMaxDynamicSharedMemorySize, FK_SMEM);
    cudaFuncSetAttribute(hmma_gemm<3, 0, 2>,
                         cudaFuncAttributeMaxDynamicSharedMemorySize, GEMM_SMEM3);
    cudaFuncSetAttribute(hmma_gemm<1, 0, 1>,
                         cudaFuncAttributeMaxDynamicSharedMemorySize, GEMM_SMEM1);
    cudaFuncSetAttribute(hmma_gemm<2, 1, 0>,
                         cudaFuncAttributeMaxDynamicSharedMemorySize, GEMM_SMEM2);
    cudaFuncSetAttribute(hmma_gemm<1, 2, 1>,
                         cudaFuncAttributeMaxDynamicSharedMemorySize, GEMM_SMEM1);
    cudaFuncSetAttribute(hmma_gemm<1, 3, 0>,
                         cudaFuncAttributeMaxDynamicSharedMemorySize, GEMM_SMEM1);

    // 0. weight transposes + fp16 split
    transpose_kernel<1><<<dim3(3 * DD / 128, DD / 32), 256>>>(Wqkv, wqh, wql, DD, 3 * DD);
    transpose_kernel<1><<<dim3(DD / 128, DD / 32),     256>>>(Wout, woh, wol, DD, DD);
    transpose_kernel<0><<<dim3(4 * DD / 128, DD / 32), 256>>>(W1, w1t, nullptr, DD, 4 * DD);
    transpose_kernel<0><<<dim3(DD / 128, 4 * DD / 32), 256>>>(W2, w2t, nullptr, 4 * DD, DD);

    // 1. LN1 -> fp16 hi/lo
    ln_fp16_kernel<1><<<MTOK, 256>>>(x, ln1_g, ln1_b, zh, zl);
    // 2a. QK = z @ Wqkv[:, :2048]  (fused 3-pass) -> fp16 hi/lo, ldc=3072
    hmma_gemm<3, 0, 2><<<dim3(2 * DD / 128, MTOK / 128), 256, GEMM_SMEM3>>>(
        zh, zl, wqh, wql, nullptr, nullptr, nullptr, qh, ql,
        MTOK, 2 * DD, DD, 3 * DD);
    // 2b. V = z @ Wqkv[:, 2048:]  (1-pass) -> fp16 hi only, ldc=3072
    hmma_gemm<1, 0, 1><<<dim3(DD / 128, MTOK / 128), 256, GEMM_SMEM1>>>(
        zh, nullptr, wqh + (size_t)(2 * DD) * DD, nullptr, nullptr, nullptr,
        nullptr, qh + 2 * DD, nullptr, MTOK, DD, DD, 3 * DD);
    // 3. attention (HMMA, 3-pass QK / 1-pass PV) -> ctx hi
    flash_hmma<<<dim3(TT / 128, NB * HH), 256, FK_SMEM>>>(qh, ql, mask, ch);
    // 4. x1 = x + ctx @ Wout  (fused 2-pass: ch*Wh + ch*Wl)
    hmma_gemm<2, 1, 0><<<dim3(DD / 128, MTOK / 128), 256, GEMM_SMEM2>>>(
        ch, nullptr, woh, wol, x, nullptr, x1, nullptr, nullptr,
        MTOK, DD, DD, DD);
    // 5. LN2 -> fp16 hi
    ln_fp16_kernel<0><<<MTOK, 256>>>(x1, ln2_g, ln2_b, zh, nullptr);
    // 6. h = gelu(z2 @ W1 + b1) -> fp16
    hmma_gemm<1, 2, 1><<<dim3(4 * DD / 128, MTOK / 128), 256, GEMM_SMEM1>>>(
        zh, nullptr, w1t, nullptr, nullptr, b1, nullptr, hb, nullptr,
        MTOK, 4 * DD, DD, 4 * DD);
    // 7. out = x1 + h @ W2 + b2
    hmma_gemm<1, 3, 0><<<dim3(DD / 128, MTOK / 128), 256, GEMM_SMEM1>>>(
        hb, nullptr, w2t, nullptr, x1, b2, out, nullptr, nullptr,
        MTOK, DD, 4 * DD, DD);
}

// round 16
// speedup vs baseline: 8.6546x; 1.0497x over previous
#include <cuda_runtime.h>
#include <cuda_fp16.h>
#include <math.h>

// Problem constants
#define NB 4
#define TT 2048
#define DD 1024
#define HH 16
#define DKK 64
#define MTOK (NB*TT)          // 8192 tokens

// ---------------- scratch (device globals; no allocation allowed) -----------
__device__ float g_x1 [MTOK * DD];        // 32 MB fp32
__device__ float g_msc[NB * TT];          // mask * log2(e)
__device__ __half g_qh [MTOK * 3 * DD];   // qkv hi (48 MB)
__device__ __half g_ql [MTOK * 3 * DD];   // qkv lo (Q,K regions used)
__device__ __half g_zh [MTOK * DD];       // LN out hi
__device__ __half g_zl [MTOK * DD];       // LN out lo
__device__ __half g_ch [MTOK * DD];       // ctx hi
__device__ __half g_hb [MTOK * 4 * DD];   // FFN hidden (fp16)
__device__ __half g_wqh[3 * DD * DD];     // Wqkv^T hi  [3072,1024]
__device__ __half g_wql[3 * DD * DD];
__device__ __half g_woh[DD * DD];         // Wout^T hi  [1024,1024]
__device__ __half g_w1t[4 * DD * DD];     // W1^T [4096,1024]
__device__ __half g_w2t[DD * 4 * DD];     // W2^T [1024,4096]

// ---------------- PTX helpers ------------------------------------------------
__device__ __forceinline__ unsigned smem_u32(const void* p) {
    unsigned a;
    asm("{ .reg .u64 t; cvta.to.shared.u64 t, %1; cvt.u32.u64 %0, t; }"
        : "=r"(a) : "l"(p));
    return a;
}
__device__ __forceinline__ void cp16(unsigned dst, const void* src) {
    asm volatile("cp.async.cg.shared.global [%0], [%1], 16;"
                 :: "r"(dst), "l"(src) : "memory");
}
__device__ __forceinline__ void cpcommit() {
    asm volatile("cp.async.commit_group;" ::: "memory");
}
template <int N> __device__ __forceinline__ void cpwait() {
    asm volatile("cp.async.wait_group %0;" :: "n"(N) : "memory");
}
__device__ __forceinline__ void ldsm4(unsigned* r, unsigned addr) {
    asm volatile("ldmatrix.sync.aligned.m8n8.x4.shared.b16 {%0,%1,%2,%3}, [%4];"
                 : "=r"(r[0]), "=r"(r[1]), "=r"(r[2]), "=r"(r[3]) : "r"(addr));
}
__device__ __forceinline__ void ldsm4t(unsigned* r, unsigned addr) {
    asm volatile("ldmatrix.sync.aligned.m8n8.x4.trans.shared.b16 {%0,%1,%2,%3}, [%4];"
                 : "=r"(r[0]), "=r"(r[1]), "=r"(r[2]), "=r"(r[3]) : "r"(addr));
}
__device__ __forceinline__ void mma16816(float* d, const unsigned* a,
                                         const unsigned* b) {
    asm volatile(
        "mma.sync.aligned.m16n8k16.row.col.f32.f16.f16.f32 "
        "{%0,%1,%2,%3}, {%4,%5,%6,%7}, {%8,%9}, {%0,%1,%2,%3};"
        : "+f"(d[0]), "+f"(d[1]), "+f"(d[2]), "+f"(d[3])
        : "r"(a[0]), "r"(a[1]), "r"(a[2]), "r"(a[3]), "r"(b[0]), "r"(b[1]));
}
__device__ __forceinline__ unsigned h2u(__half2 v) {
    union { __half2 h; unsigned u; } c; c.h = v; return c.u;
}

#define GSW(off) ((off) ^ ((((unsigned)(off)) >> 3) & 0x70u))

// ---------------- fused multi-pass HMMA fp16 GEMM ----------------------------
// C[M,N] = A@B^T. NPASS=3: Ah*Bh+Ah*Bl+Al*Bh fused. NPASS=2: Ah*(Bh+Bl).
// NPASS=1: Ah*Bh.  A[M,K], B[N,K] K-major fp16. Tile 128x128, k-chunk 64,
// 3-stage pipeline, single __syncthreads per k-iteration.
// ldc: row stride of C (and R). N is the GEMM width (B rows).
// EPI: 0 none, 1 +R, 2 +bias,gelu, 3 +bias+R.
// OUTB: 0 fp32 Cf, 1 fp16 Cb, 2 fp16 hi->Cb + lo->Cb2.
#define GEMM_SMEM3 (3 * 65536 + 1024)
#define GEMM_SMEM2 (3 * 49152 + 1024)
#define GEMM_SMEM1 (3 * 32768 + 1024)

template <int NPASS, int EPI, int OUTB>
__global__ __launch_bounds__(256) void hmma_gemm(
    const __half* __restrict__ Ah, const __half* __restrict__ Al,
    const __half* __restrict__ Bh, const __half* __restrict__ Bl,
    const float* __restrict__ R, const float* __restrict__ bias,
    float* __restrict__ Cf, __half* __restrict__ Cb,
    __half* __restrict__ Cb2,
    int M, int N, int K, int ldc)
{
    constexpr unsigned TS  = (NPASS == 3) ? 65536u : ((NPASS == 2) ? 49152u : 32768u);
    constexpr unsigned BOF = (NPASS == 3) ? 32768u : 16384u;   // B-hi offset

    extern __shared__ char dsm[];
    unsigned smb    = smem_u32(dsm);
    unsigned tile_u = (smb + 1023u) & ~1023u;

    int tid = threadIdx.x, wid = tid >> 5, lane = tid & 31;
    int wm = wid & 3, wn = wid >> 2;
    int bm = blockIdx.y << 7, bn = blockIdx.x << 7;

    const int nk = K >> 6;

    int li  = lane & 7, sub = lane >> 3;
    unsigned aoff[2];
#pragma unroll
    for (int mt = 0; mt < 2; mt++) {
        unsigned r = (unsigned)(wm * 32 + mt * 16 + (sub & 1) * 8 + li);
        aoff[mt] = (r << 7) + (unsigned)((sub >> 1) << 4);
        aoff[mt] ^= (r & 7u) << 4;
    }
    unsigned boff[4];
#pragma unroll
    for (int ng = 0; ng < 4; ng++) {
        unsigned r = (unsigned)(wn * 64 + ng * 16 + (sub >> 1) * 8 + li);
        boff[ng] = (r << 7) + (unsigned)((sub & 1) << 4);
        boff[ng] ^= (r & 7u) << 4;
    }

    int ld_row = tid >> 3;
    int ld_kb  = (tid & 7) << 4;

    float d[2][8][4];
#pragma unroll
    for (int mt = 0; mt < 2; mt++)
#pragma unroll
        for (int nt = 0; nt < 8; nt++)
#pragma unroll
            for (int j = 0; j < 4; j++) d[mt][nt][j] = 0.f;

#define ISSUE(it_) do {                                                        \
    unsigned base_ = tile_u + (unsigned)((it_) % 3) * TS;                      \
    const __half* AsH_ = Ah + (size_t)bm * K + ((it_) << 6);                   \
    const __half* BsH_ = Bh + (size_t)bn * K + ((it_) << 6);                   \
    _Pragma("unroll")                                                          \
    for (int i_ = 0; i_ < 4; i_++) {                                           \
        int row_ = ld_row + i_ * 32;                                           \
        unsigned so_ = GSW((unsigned)((row_ << 7) | ld_kb));                   \
        cp16(base_ + so_, (const char*)(AsH_ + (size_t)row_ * K) + ld_kb);     \
        cp16(base_ + BOF + so_, (const char*)(BsH_ + (size_t)row_ * K) + ld_kb); \
        if (NPASS >= 2) {                                                      \
            const __half* BsL_ = Bl + (size_t)bn * K + ((it_) << 6);           \
            cp16(base_ + BOF + 16384u + so_,                                   \
                 (const char*)(BsL_ + (size_t)row_ * K) + ld_kb);              \
        }                                                                      \
        if (NPASS == 3) {                                                      \
            const __half* AsL_ = Al + (size_t)bm * K + ((it_) << 6);           \
            cp16(base_ + 16384u + so_,                                         \
                 (const char*)(AsL_ + (size_t)row_ * K) + ld_kb);              \
        }                                                                      \
    }                                                                          \
    cpcommit();                                                                \
} while (0)

    ISSUE(0);
    if (nk > 1) ISSUE(1);

    for (int it = 0; it < nk; ++it) {
        if (it + 1 < nk) cpwait<1>(); else cpwait<0>();
        __syncthreads();
        if (it + 2 < nk) ISSUE(it + 2);
        unsigned ab = tile_u + (unsigned)(it % 3) * TS;
        unsigned bb = ab + BOF;
#pragma unroll
        for (int ks = 0; ks < 4; ks++) {
            unsigned kx = (unsigned)(ks << 5);
            unsigned aH[2][4], aL[2][4];
#pragma unroll
            for (int mt = 0; mt < 2; mt++) ldsm4(aH[mt], ab + (aoff[mt] ^ kx));
            if (NPASS == 3) {
#pragma unroll
                for (int mt = 0; mt < 2; mt++)
                    ldsm4(aL[mt], ab + 16384u + (aoff[mt] ^ kx));
            }
#pragma unroll
            for (int ng = 0; ng < 4; ng++) {
                unsigned bH[4];
                ldsm4(bH, bb + (boff[ng] ^ kx));
#pragma unroll
                for (int mt = 0; mt < 2; mt++) {
                    mma16816(d[mt][2 * ng + 0], aH[mt], &bH[0]);
                    mma16816(d[mt][2 * ng + 1], aH[mt], &bH[2]);
                }
                if (NPASS >= 2) {
                    unsigned bL[4];
                    ldsm4(bL, bb + 16384u + (boff[ng] ^ kx));
#pragma unroll
                    for (int mt = 0; mt < 2; mt++) {
                        mma16816(d[mt][2 * ng + 0], aH[mt], &bL[0]);
                        mma16816(d[mt][2 * ng + 1], aH[mt], &bL[2]);
                    }
                }
                if (NPASS == 3) {
#pragma unroll
                    for (int mt = 0; mt < 2; mt++) {
                        mma16816(d[mt][2 * ng + 0], aL[mt], &bH[0]);
                        mma16816(d[mt][2 * ng + 1], aL[mt], &bH[2]);
                    }
                }
            }
        }
    }
#undef ISSUE

    int qr = lane >> 2;
    int qc = (lane & 3) << 1;
#pragma unroll
    for (int mt = 0; mt < 2; mt++) {
#pragma unroll
        for (int nt = 0; nt < 8; nt++) {
            int r0 = bm + wm * 32 + mt * 16 + qr;
            int c  = bn + wn * 64 + nt * 8 + qc;
            float v[4];
#pragma unroll
            for (int j = 0; j < 4; j++) v[j] = d[mt][nt][j];
            if (EPI == 2 || EPI == 3) {
                float2 bv = *(const float2*)(bias + c);
                v[0] += bv.x; v[1] += bv.y; v[2] += bv.x; v[3] += bv.y;
            }
            if (EPI == 2) {
#pragma unroll
                for (int j = 0; j < 4; j++)
                    v[j] = 0.5f * v[j] * (1.0f + erff(v[j] * 0.7071067811865475f));
            }
            if (EPI == 1 || EPI == 3) {
                float2 r1 = *(const float2*)(R + (size_t)r0 * ldc + c);
                float2 r2 = *(const float2*)(R + (size_t)(r0 + 8) * ldc + c);
                v[0] += r1.x; v[1] += r1.y; v[2] += r2.x; v[3] += r2.y;
            }
            if (OUTB == 1) {
                *(__half2*)(Cb + (size_t)r0 * ldc + c) =
                    __floats2half2_rn(v[0], v[1]);
                *(__half2*)(Cb + (size_t)(r0 + 8) * ldc + c) =
                    __floats2half2_rn(v[2], v[3]);
            } else if (OUTB == 2) {
                __half2 h0 = __floats2half2_rn(v[0], v[1]);
                __half2 h1 = __floats2half2_rn(v[2], v[3]);
                *(__half2*)(Cb + (size_t)r0 * ldc + c) = h0;
                *(__half2*)(Cb + (size_t)(r0 + 8) * ldc + c) = h1;
                *(__half2*)(Cb2 + (size_t)r0 * ldc + c) =
                    __floats2half2_rn(v[0] - __half2float(__low2half(h0)),
                                      v[1] - __half2float(__high2half(h0)));
                *(__half2*)(Cb2 + (size_t)(r0 + 8) * ldc + c) =
                    __floats2half2_rn(v[2] - __half2float(__low2half(h1)),
                                      v[3] - __half2float(__high2half(h1)));
            } else {
                *(float2*)(Cf + (size_t)r0 * ldc + c) = make_float2(v[0], v[1]);
                *(float2*)(Cf + (size_t)(r0 + 8) * ldc + c) = make_float2(v[2], v[3]);
            }
        }
    }
}

// ---------------- HMMA flash attention --------------------------------------
// CTA: 128 q-rows of one (n,h); iterate 32 s-blocks of 64. 8 warps x 16 rows.
// QK^T 3-pass split fp16, online softmax in base-2 (exp2f), PV 1-pass fp16.
// mask input is pre-scaled by log2(e); S scale folds 0.125*log2(e).
#define FK_QH   0u
#define FK_QL   16384u
#define FK_KV   32768u
#define FK_BUF  24576u
#define FK_MASK 106496u
#define FK_SMEM 107264
#define FK_SC   0.1803368801111244f   // 0.125 * log2(e)

__global__ __launch_bounds__(256) void flash_hmma(
    const __half* __restrict__ qh, const __half* __restrict__ ql,
    const float* __restrict__ mask2,
    __half* __restrict__ ch)
{
    extern __shared__ char fsm[];
    unsigned sb = smem_u32(fsm);

    int tid = threadIdx.x, wid = tid >> 5, lane = tid & 31;
    int qr = lane >> 2, tig = lane & 3;
    int bh = blockIdx.y, n = bh >> 4, h = bh & 15;
    int q0 = blockIdx.x << 7;
    const float* maskp = mask2 + (size_t)n * TT;

    const char* qbH = (const char*)(qh + (size_t)(n * TT + q0) * 3072) + h * 128;
    const char* qbL = (const char*)(ql + (size_t)(n * TT + q0) * 3072) + h * 128;
    const char* kvH = (const char*)(qh + (size_t)n * TT * 3072) + h * 128;
    const char* kvL = (const char*)(ql + (size_t)n * TT * 3072) + h * 128;

#define FK_ISSUE(it_) do {                                                     \
    int s0_ = (it_) << 6;                                                      \
    unsigned kb_ = sb + FK_KV + (unsigned)((it_) % 3) * FK_BUF;                \
    _Pragma("unroll")                                                          \
    for (int i_ = 0; i_ < 2; i_++) {                                           \
        int v_ = tid + (i_ << 8);                                              \
        int row_ = v_ >> 3; int kb2_ = (v_ & 7) << 4;                          \
        unsigned so_ = GSW((unsigned)((row_ << 7) | kb2_));                    \
        size_t gb_ = (size_t)(s0_ + row_) * 6144 + kb2_;                       \
        cp16(kb_ + so_,          kvH + gb_ + 2048);                            \
        cp16(kb_ + 8192u + so_,  kvL + gb_ + 2048);                            \
        cp16(kb_ + 16384u + so_, kvH + gb_ + 4096);                            \
    }                                                                          \
    if (tid < 16)                                                              \
        cp16(sb + FK_MASK + (unsigned)((it_) % 3) * 256u + (tid << 4),         \
             maskp + s0_ + tid * 4);                                           \
    cpcommit();                                                                \
} while (0)

    // prologue
#pragma unroll
    for (int i = 0; i < 4; i++) {
        int v = tid + (i << 8);
        int row = v >> 3; int kb = (v & 7) << 4;
        unsigned so = GSW((unsigned)((row << 7) | kb));
        cp16(sb + FK_QH + so, qbH + (size_t)row * 6144 + kb);
        cp16(sb + FK_QL + so, qbL + (size_t)row * 6144 + kb);
    }
    FK_ISSUE(0);
    FK_ISSUE(1);

    // fragment offsets
    int li = lane & 7, sub = lane >> 3;
    unsigned m4 = (unsigned)li << 4;
    unsigned qoff;
    {
        unsigned r = (unsigned)(wid * 16 + (sub & 1) * 8 + li);
        qoff = (r << 7) + ((unsigned)((sub >> 1) << 4) ^ m4);
    }
    unsigned koff[4];
#pragma unroll
    for (int ng = 0; ng < 4; ng++) {
        unsigned r = (unsigned)(ng * 16 + (sub >> 1) * 8 + li);
        koff[ng] = (r << 7) + ((unsigned)((sub & 1) << 4) ^ m4);
    }
    unsigned vrow = (unsigned)((sub & 1) * 8 + li) << 7;
    unsigned vb[4];
#pragma unroll
    for (int dt = 0; dt < 4; dt++)
        vb[dt] = ((unsigned)((sub >> 1) << 4) + (unsigned)(dt << 5)) ^ m4;

    unsigned qHf[4][4], qLf[4][4];
    float sS[8][4], oO[8][4];
    float mM[2] = {-1e30f, -1e30f}, lL[2] = {0.f, 0.f};
#pragma unroll
    for (int nt = 0; nt < 8; nt++)
#pragma unroll
        for (int j = 0; j < 4; j++) oO[nt][j] = 0.f;

    for (int it = 0; it < TT / 64; ++it) {
        if (it == TT / 64 - 1) cpwait<0>(); else cpwait<1>();
        __syncthreads();
        if (it + 2 < TT / 64) FK_ISSUE(it + 2);
        unsigned kb0 = sb + FK_KV + (unsigned)(it % 3) * FK_BUF;

        if (it == 0) {
#pragma unroll
            for (int ks = 0; ks < 4; ks++) {
                unsigned kx = (unsigned)(ks << 5);
                ldsm4(qHf[ks], sb + FK_QH + (qoff ^ kx));
                ldsm4(qLf[ks], sb + FK_QL + (qoff ^ kx));
            }
        }

        // ---- S = Q@K^T (3-pass fp16) ----
#pragma unroll
        for (int nt = 0; nt < 8; nt++)
#pragma unroll
            for (int j = 0; j < 4; j++) sS[nt][j] = 0.f;
#pragma unroll
        for (int ks = 0; ks < 4; ks++) {
            unsigned kx = (unsigned)(ks << 5);
#pragma unroll
            for (int ng = 0; ng < 4; ng++) {
                unsigned bH[4], bL[4];
                ldsm4(bH, kb0 + (koff[ng] ^ kx));
                ldsm4(bL, kb0 + 8192u + (koff[ng] ^ kx));
                mma16816(sS[2 * ng + 0], qHf[ks], &bH[0]);
                mma16816(sS[2 * ng + 1], qHf[ks], &bH[2]);
                mma16816(sS[2 * ng + 0], qHf[ks], &bL[0]);
                mma16816(sS[2 * ng + 1], qHf[ks], &bL[2]);
                mma16816(sS[2 * ng + 0], qLf[ks], &bH[0]);
                mma16816(sS[2 * ng + 1], qLf[ks], &bH[2]);
            }
        }

        // ---- scale (0.125*log2e) + mask (pre-scaled by log2e) ----
        const float* mbuf = (const float*)(fsm + FK_MASK + (it % 3) * 256);
#pragma unroll
        for (int nt = 0; nt < 8; nt++) {
            float2 mv = *(const float2*)(mbuf + nt * 8 + 2 * tig);
            sS[nt][0] = fmaf(sS[nt][0], FK_SC, mv.x);
            sS[nt][1] = fmaf(sS[nt][1], FK_SC, mv.y);
            sS[nt][2] = fmaf(sS[nt][2], FK_SC, mv.x);
            sS[nt][3] = fmaf(sS[nt][3], FK_SC, mv.y);
        }

        // ---- online softmax, base-2 (2 rows/thread) ----
#pragma unroll
        for (int i = 0; i < 2; i++) {
            int ib = 2 * i;
            float mx = -1e30f;
#pragma unroll
            for (int nt = 0; nt < 8; nt++)
                mx = fmaxf(mx, fmaxf(sS[nt][ib], sS[nt][ib + 1]));
            mx = fmaxf(mx, __shfl_xor_sync(0xffffffffu, mx, 1));
            mx = fmaxf(mx, __shfl_xor_sync(0xffffffffu, mx, 2));
            float mnew  = fmaxf(mM[i], mx);
            float alpha = exp2f(mM[i] - mnew);
            float rsum = 0.f;
#pragma unroll
            for (int nt = 0; nt < 8; nt++) {
                float p0 = exp2f(sS[nt][ib]     - mnew);
                float p1 = exp2f(sS[nt][ib + 1] - mnew);
                sS[nt][ib] = p0; sS[nt][ib + 1] = p1;
                rsum += p0 + p1;
            }
            rsum += __shfl_xor_sync(0xffffffffu, rsum, 1);
            rsum += __shfl_xor_sync(0xffffffffu, rsum, 2);
            lL[i] = lL[i] * alpha + rsum;
            mM[i] = mnew;
#pragma unroll
            for (int nt = 0; nt < 8; nt++) {
                oO[nt][ib] *= alpha; oO[nt][ib + 1] *= alpha;
            }
        }

        // ---- O += P@V (1-pass fp16: Ph*Vh) ----
#pragma unroll
        for (int kt = 0; kt < 4; kt++) {
            unsigned ah[4];
#pragma unroll
            for (int half = 0; half < 2; half++) {
                int nt = 2 * kt + half;
                ah[2 * half + 0] = h2u(__floats2half2_rn(sS[nt][0], sS[nt][1]));
                ah[2 * half + 1] = h2u(__floats2half2_rn(sS[nt][2], sS[nt][3]));
            }
            unsigned vkb = kb0 + 16384u + (unsigned)(kt << 11) + vrow;
#pragma unroll
            for (int dt = 0; dt < 4; dt++) {
                unsigned bv[4];
                ldsm4t(bv, vkb + vb[dt]);
                mma16816(oO[2 * dt + 0], ah, &bv[0]);
                mma16816(oO[2 * dt + 1], ah, &bv[2]);
            }
        }
    }
#undef FK_ISSUE

    // ---- write ctx hi ----
#pragma unroll
    for (int i = 0; i < 2; i++) {
        float inv = 1.f / lL[i];
        int ib = 2 * i;
        size_t tok = (size_t)(n * TT + q0 + wid * 16 + qr + i * 8);
#pragma unroll
        for (int nt = 0; nt < 8; nt++) {
            float v0 = oO[nt][ib] * inv, v1 = oO[nt][ib + 1] * inv;
            int col = h * 64 + nt * 8 + 2 * tig;
            *(__half2*)(ch + tok * DD + col) = __floats2half2_rn(v0, v1);
        }
    }
}

// ---------------- mask pre-scale by log2(e) ----------------------------------
__global__ void scale_mask_kernel(const float* __restrict__ m,
                                  float* __restrict__ o, int n)
{
    int i = blockIdx.x * 256 + threadIdx.x;
    if (i < n) o[i] = m[i] * 1.4426950408889634f;
}

// ---------------- LayerNorm -> fp16 hi(/lo), float4 vectorized ---------------
template <int WLO>
__global__ __launch_bounds__(256) void ln_fp16_kernel(
    const float* __restrict__ x, const float* __restrict__ g,
    const float* __restrict__ b,
    __half* __restrict__ zh, __half* __restrict__ zl)
{
    int row = blockIdx.x;
    const float* xr = x + (size_t)row * DD;
    int tid = threadIdx.x;
    float4 v = *(const float4*)(xr + tid * 4);
    float sum = v.x + v.y + v.z + v.w;
    float sq  = v.x * v.x + v.y * v.y + v.z * v.z + v.w * v.w;
#pragma unroll
    for (int o = 16; o > 0; o >>= 1) {
        sum += __shfl_xor_sync(0xffffffffu, sum, o);
        sq  += __shfl_xor_sync(0xffffffffu, sq,  o);
    }
    __shared__ float red[2][8];
    int w = tid >> 5, l = tid & 31;
    if (l == 0) { red[0][w] = sum; red[1][w] = sq; }
    __syncthreads();
    if (tid < 32) {
        float s = (tid < 8) ? red[0][tid] : 0.f;
        float q = (tid < 8) ? red[1][tid] : 0.f;
#pragma unroll
        for (int o = 4; o > 0; o >>= 1) {
            s += __shfl_xor_sync(0xffffffffu, s, o);
            q += __shfl_xor_sync(0xffffffffu, q, o);
        }
        if (tid == 0) { red[0][0] = s; red[1][0] = q; }
    }
    __syncthreads();
    float mu   = red[0][0] * (1.f / DD);
    float var  = red[1][0] * (1.f / DD) - mu * mu;
    float rstd = rsqrtf(var + 1e-5f);
    int c = tid * 4;
    float4 gv = *(const float4*)(g + c);
    float4 bv = *(const float4*)(b + c);
    float y0 = (v.x - mu) * rstd * gv.x + bv.x;
    float y1 = (v.y - mu) * rstd * gv.y + bv.y;
    float y2 = (v.z - mu) * rstd * gv.z + bv.z;
    float y3 = (v.w - mu) * rstd * gv.w + bv.w;
    __half2 h0 = __floats2half2_rn(y0, y1);
    __half2 h1 = __floats2half2_rn(y2, y3);
    *(__half2*)(zh + (size_t)row * DD + c)     = h0;
    *(__half2*)(zh + (size_t)row * DD + c + 2) = h1;
    if (WLO) {
        *(__half2*)(zl + (size_t)row * DD + c) =
            __floats2half2_rn(y0 - __half2float(__low2half(h0)),
                              y1 - __half2float(__high2half(h0)));
        *(__half2*)(zl + (size_t)row * DD + c + 2) =
            __floats2half2_rn(y2 - __half2float(__low2half(h1)),
                              y3 - __half2float(__high2half(h1)));
    }
}

// ---------------- weight transpose W[K,N] -> T[N,K] fp16 hi(/lo) -------------
template <int SPLIT>
__global__ __launch_bounds__(256) void transpose_kernel(
    const float* __restrict__ W, __half* __restrict__ Th,
    __half* __restrict__ Tl, int K, int N)
{
    __shared__ float t[32][129];
    int tid = threadIdx.x;
    int k0 = blockIdx.y * 32, n0 = blockIdx.x * 128;
    int kk = tid >> 3, nn = (tid & 7) * 4;
#pragma unroll
    for (int i = 0; i < 4; i++) {
        float4 v = *(const float4*)(W + (size_t)(k0 + kk) * N + n0 + i * 32 + nn);
        t[kk][i * 32 + nn + 0] = v.x; t[kk][i * 32 + nn + 1] = v.y;
        t[kk][i * 32 + nn + 2] = v.z; t[kk][i * 32 + nn + 3] = v.w;
    }
    __syncthreads();
    int wid = tid >> 5, lane = tid & 31;
    int k2 = (lane & 15) * 2;
#pragma unroll
    for (int i = 0; i < 8; i++) {
        int nrow = wid * 16 + i * 2 + (lane >> 4);
        float a = t[k2][nrow], b = t[k2 + 1][nrow];
        __half ha = __float2half_rn(a), hb = __float2half_rn(b);
        *(__half2*)(Th + (size_t)(n0 + nrow) * K + k0 + k2) = __halves2half2(ha, hb);
        if (SPLIT)
            *(__half2*)(Tl + (size_t)(n0 + nrow) * K + k0 + k2) =
                __halves2half2(__float2half_rn(a - __half2float(ha)),
                               __float2half_rn(b - __half2float(hb)));
    }
}

// ---------------- launch -----------------------------------------------------
extern "C" void kernel_launch(void* const* d_in, const int* in_sizes, int n_in,
                              void* d_out, int out_size)
{
    const float* x     = (const float*)d_in[0];
    const float* mask  = (const float*)d_in[1];
    const float* Wqkv  = (const float*)d_in[2];
    const float* Wout  = (const float*)d_in[3];
    const float* ln1_g = (const float*)d_in[4];
    const float* ln1_b = (const float*)d_in[5];
    const float* ln2_g = (const float*)d_in[6];
    const float* ln2_b = (const float*)d_in[7];
    const float* W1    = (const float*)d_in[8];
    const float* b1    = (const float*)d_in[9];
    const float* W2    = (const float*)d_in[10];
    const float* b2    = (const float*)d_in[11];
    float* out = (float*)d_out;

    float *x1, *msc;
    __half *qh, *ql, *zh, *zl, *ch, *hb;
    __half *wqh, *wql, *woh, *w1t, *w2t;
    cudaGetSymbolAddress((void**)&x1,  g_x1);
    cudaGetSymbolAddress((void**)&msc, g_msc);
    cudaGetSymbolAddress((void**)&qh,  g_qh);
    cudaGetSymbolAddress((void**)&ql,  g_ql);
    cudaGetSymbolAddress((void**)&zh,  g_zh);
    cudaGetSymbolAddress((void**)&zl,  g_zl);
    cudaGetSymbolAddress((void**)&ch,  g_ch);
    cudaGetSymbolAddress((void**)&hb,  g_hb);
    cudaGetSymbolAddress((void**)&wqh, g_wqh);
    cudaGetSymbolAddress((void**)&wql, g_wql);
    cudaGetSymbolAddress((void**)&woh, g_woh);
    cudaGetSymbolAddress((void**)&w1t, g_w1t);
    cudaGetSymbolAddress((void**)&w2t, g_w2t);

    cudaFuncSetAttribute(flash_hmma,
                         cudaFuncAttributeMaxDynamicSharedMemorySize, FK_SMEM);
    cudaFuncSetAttribute(hmma_gemm<3, 0, 2>,
                         cudaFuncAttributeMaxDynamicSharedMemorySize, GEMM_SMEM3);
    cudaFuncSetAttribute(hmma_gemm<1, 0, 1>,
                         cudaFuncAttributeMaxDynamicSharedMemorySize, GEMM_SMEM1);
    cudaFuncSetAttribute(hmma_gemm<1, 1, 0>,
                         cudaFuncAttributeMaxDynamicSharedMemorySize, GEMM_SMEM1);
    cudaFuncSetAttribute(hmma_gemm<1, 2, 1>,
                         cudaFuncAttributeMaxDynamicSharedMemorySize, GEMM_SMEM1);
    cudaFuncSetAttribute(hmma_gemm<1, 3, 0>,
                         cudaFuncAttributeMaxDynamicSharedMemorySize, GEMM_SMEM1);

    // 0. weight transposes + fp16 split; mask pre-scale
    transpose_kernel<1><<<dim3(3 * DD / 128, DD / 32), 256>>>(Wqkv, wqh, wql, DD, 3 * DD);
    transpose_kernel<0><<<dim3(DD / 128, DD / 32),     256>>>(Wout, woh, nullptr, DD, DD);
    transpose_kernel<0><<<dim3(4 * DD / 128, DD / 32), 256>>>(W1, w1t, nullptr, DD, 4 * DD);
    transpose_kernel<0><<<dim3(DD / 128, 4 * DD / 32), 256>>>(W2, w2t, nullptr, 4 * DD, DD);
    scale_mask_kernel<<<(NB * TT + 255) / 256, 256>>>(mask, msc, NB * TT);

    // 1. LN1 -> fp16 hi/lo
    ln_fp16_kernel<1><<<MTOK, 256>>>(x, ln1_g, ln1_b, zh, zl);
    // 2a. QK = z @ Wqkv[:, :2048]  (fused 3-pass) -> fp16 hi/lo, ldc=3072
    hmma_gemm<3, 0, 2><<<dim3(2 * DD / 128, MTOK / 128), 256, GEMM_SMEM3>>>(
        zh, zl, wqh, wql, nullptr, nullptr, nullptr, qh, ql,
        MTOK, 2 * DD, DD, 3 * DD);
    // 2b. V = z @ Wqkv[:, 2048:]  (1-pass) -> fp16 hi only, ldc=3072
    hmma_gemm<1, 0, 1><<<dim3(DD / 128, MTOK / 128), 256, GEMM_SMEM1>>>(
        zh, nullptr, wqh + (size_t)(2 * DD) * DD, nullptr, nullptr, nullptr,
        nullptr, qh + 2 * DD, nullptr, MTOK, DD, DD, 3 * DD);
    // 3. attention (HMMA, 3-pass QK / 1-pass PV, base-2 softmax) -> ctx hi
    flash_hmma<<<dim3(TT / 128, NB * HH), 256, FK_SMEM>>>(qh, ql, msc, ch);
    // 4. x1 = x + ctx @ Wout  (1-pass)
    hmma_gemm<1, 1, 0><<<dim3(DD / 128, MTOK / 128), 256, GEMM_SMEM1>>>(
        ch, nullptr, woh, nullptr, x, nullptr, x1, nullptr, nullptr,
        MTOK, DD, DD, DD);
    // 5. LN2 -> fp16 hi
    ln_fp16_kernel<0><<<MTOK, 256>>>(x1, ln2_g, ln2_b, zh, nullptr);
    // 6. h = gelu(z2 @ W1 + b1) -> fp16
    hmma_gemm<1, 2, 1><<<dim3(4 * DD / 128, MTOK / 128), 256, GEMM_SMEM1>>>(
        zh, nullptr, w1t, nullptr, nullptr, b1, nullptr, hb, nullptr,
        MTOK, 4 * DD, DD, 4 * DD);
    // 7. out = x1 + h @ W2 + b2
    hmma_gemm<1, 3, 0><<<dim3(DD / 128, MTOK / 128), 256, GEMM_SMEM1>>>(
        hb, nullptr, w2t, nullptr, x1, b2, out, nullptr, nullptr,
        MTOK, DD, 4 * DD, DD);
}

// round 17
// speedup vs baseline: 8.6849x; 1.0035x over previous
#include <cuda_runtime.h>
#include <cuda_fp16.h>
#include <math.h>

// Problem constants
#define NB 4
#define TT 2048
#define DD 1024
#define HH 16
#define DKK 64
#define MTOK (NB*TT)          // 8192 tokens

// ---------------- scratch (device globals; no allocation allowed) -----------
__device__ float g_x1 [MTOK * DD];        // 32 MB fp32
__device__ float g_msc[NB * TT];          // mask * log2(e)
__device__ __half g_qh [MTOK * 3 * DD];   // qkv hi (48 MB)
__device__ __half g_ql [MTOK * 3 * DD];   // qkv lo (Q,K regions used)
__device__ __half g_zh [MTOK * DD];       // LN out hi
__device__ __half g_zl [MTOK * DD];       // LN out lo
__device__ __half g_ch [MTOK * DD];       // ctx hi
__device__ __half g_hb [MTOK * 4 * DD];   // FFN hidden (fp16)
__device__ __half g_wqh[3 * DD * DD];     // Wqkv^T hi  [3072,1024]
__device__ __half g_wql[3 * DD * DD];
__device__ __half g_woh[DD * DD];         // Wout^T hi  [1024,1024]
__device__ __half g_w1t[4 * DD * DD];     // W1^T [4096,1024]
__device__ __half g_w2t[DD * 4 * DD];     // W2^T [1024,4096]

// ---------------- PTX helpers ------------------------------------------------
__device__ __forceinline__ unsigned smem_u32(const void* p) {
    unsigned a;
    asm("{ .reg .u64 t; cvta.to.shared.u64 t, %1; cvt.u32.u64 %0, t; }"
        : "=r"(a) : "l"(p));
    return a;
}
__device__ __forceinline__ void cp16(unsigned dst, const void* src) {
    asm volatile("cp.async.cg.shared.global [%0], [%1], 16;"
                 :: "r"(dst), "l"(src) : "memory");
}
__device__ __forceinline__ void cpcommit() {
    asm volatile("cp.async.commit_group;" ::: "memory");
}
template <int N> __device__ __forceinline__ void cpwait() {
    asm volatile("cp.async.wait_group %0;" :: "n"(N) : "memory");
}
__device__ __forceinline__ void ldsm4(unsigned* r, unsigned addr) {
    asm volatile("ldmatrix.sync.aligned.m8n8.x4.shared.b16 {%0,%1,%2,%3}, [%4];"
                 : "=r"(r[0]), "=r"(r[1]), "=r"(r[2]), "=r"(r[3]) : "r"(addr));
}
__device__ __forceinline__ void ldsm4t(unsigned* r, unsigned addr) {
    asm volatile("ldmatrix.sync.aligned.m8n8.x4.trans.shared.b16 {%0,%1,%2,%3}, [%4];"
                 : "=r"(r[0]), "=r"(r[1]), "=r"(r[2]), "=r"(r[3]) : "r"(addr));
}
__device__ __forceinline__ void mma16816(float* d, const unsigned* a,
                                         const unsigned* b) {
    asm volatile(
        "mma.sync.aligned.m16n8k16.row.col.f32.f16.f16.f32 "
        "{%0,%1,%2,%3}, {%4,%5,%6,%7}, {%8,%9}, {%0,%1,%2,%3};"
        : "+f"(d[0]), "+f"(d[1]), "+f"(d[2]), "+f"(d[3])
        : "r"(a[0]), "r"(a[1]), "r"(a[2]), "r"(a[3]), "r"(b[0]), "r"(b[1]));
}
__device__ __forceinline__ unsigned h2u(__half2 v) {
    union { __half2 h; unsigned u; } c; c.h = v; return c.u;
}

#define GSW(off) ((off) ^ ((((unsigned)(off)) >> 3) & 0x70u))

// ---------------- fused multi-pass HMMA fp16 GEMM ----------------------------
// C[M,N] = A@B^T. NPASS=3: Ah*Bh+Ah*Bl+Al*Bh fused. NPASS=2: Ah*(Bh+Bl).
// NPASS=1: Ah*Bh.  A[M,K], B[N,K] K-major fp16. Tile 128x128, k-chunk 64,
// 3-stage pipeline, single __syncthreads per k-iteration.
// ldc: row stride of C (and R). N is the GEMM width (B rows).
// EPI: 0 none, 1 +R, 2 +bias,gelu, 3 +bias+R.
// OUTB: 0 fp32 Cf, 1 fp16 Cb, 2 fp16 hi->Cb + lo->Cb2.
#define GEMM_SMEM3 (3 * 65536 + 1024)
#define GEMM_SMEM1 (3 * 32768 + 1024)

template <int NPASS, int EPI, int OUTB>
__global__ __launch_bounds__(256) void hmma_gemm(
    const __half* __restrict__ Ah, const __half* __restrict__ Al,
    const __half* __restrict__ Bh, const __half* __restrict__ Bl,
    const float* __restrict__ R, const float* __restrict__ bias,
    float* __restrict__ Cf, __half* __restrict__ Cb,
    __half* __restrict__ Cb2,
    int M, int N, int K, int ldc)
{
    constexpr unsigned TS  = (NPASS == 3) ? 65536u : ((NPASS == 2) ? 49152u : 32768u);
    constexpr unsigned BOF = (NPASS == 3) ? 32768u : 16384u;   // B-hi offset

    extern __shared__ char dsm[];
    unsigned smb    = smem_u32(dsm);
    unsigned tile_u = (smb + 1023u) & ~1023u;

    int tid = threadIdx.x, wid = tid >> 5, lane = tid & 31;
    int wm = wid & 3, wn = wid >> 2;
    int bm = blockIdx.y << 7, bn = blockIdx.x << 7;

    const int nk = K >> 6;

    int li  = lane & 7, sub = lane >> 3;
    unsigned aoff[2];
#pragma unroll
    for (int mt = 0; mt < 2; mt++) {
        unsigned r = (unsigned)(wm * 32 + mt * 16 + (sub & 1) * 8 + li);
        aoff[mt] = (r << 7) + (unsigned)((sub >> 1) << 4);
        aoff[mt] ^= (r & 7u) << 4;
    }
    unsigned boff[4];
#pragma unroll
    for (int ng = 0; ng < 4; ng++) {
        unsigned r = (unsigned)(wn * 64 + ng * 16 + (sub >> 1) * 8 + li);
        boff[ng] = (r << 7) + (unsigned)((sub & 1) << 4);
        boff[ng] ^= (r & 7u) << 4;
    }

    int ld_row = tid >> 3;
    int ld_kb  = (tid & 7) << 4;

    float d[2][8][4];
#pragma unroll
    for (int mt = 0; mt < 2; mt++)
#pragma unroll
        for (int nt = 0; nt < 8; nt++)
#pragma unroll
            for (int j = 0; j < 4; j++) d[mt][nt][j] = 0.f;

#define ISSUE(it_) do {                                                        \
    unsigned base_ = tile_u + (unsigned)((it_) % 3) * TS;                      \
    const __half* AsH_ = Ah + (size_t)bm * K + ((it_) << 6);                   \
    const __half* BsH_ = Bh + (size_t)bn * K + ((it_) << 6);                   \
    _Pragma("unroll")                                                          \
    for (int i_ = 0; i_ < 4; i_++) {                                           \
        int row_ = ld_row + i_ * 32;                                           \
        unsigned so_ = GSW((unsigned)((row_ << 7) | ld_kb));                   \
        cp16(base_ + so_, (const char*)(AsH_ + (size_t)row_ * K) + ld_kb);     \
        cp16(base_ + BOF + so_, (const char*)(BsH_ + (size_t)row_ * K) + ld_kb); \
        if (NPASS >= 2) {                                                      \
            const __half* BsL_ = Bl + (size_t)bn * K + ((it_) << 6);           \
            cp16(base_ + BOF + 16384u + so_,                                   \
                 (const char*)(BsL_ + (size_t)row_ * K) + ld_kb);              \
        }                                                                      \
        if (NPASS == 3) {                                                      \
            const __half* AsL_ = Al + (size_t)bm * K + ((it_) << 6);           \
            cp16(base_ + 16384u + so_,                                         \
                 (const char*)(AsL_ + (size_t)row_ * K) + ld_kb);              \
        }                                                                      \
    }                                                                          \
    cpcommit();                                                                \
} while (0)

    ISSUE(0);
    if (nk > 1) ISSUE(1);

    for (int it = 0; it < nk; ++it) {
        if (it + 1 < nk) cpwait<1>(); else cpwait<0>();
        __syncthreads();
        if (it + 2 < nk) ISSUE(it + 2);
        unsigned ab = tile_u + (unsigned)(it % 3) * TS;
        unsigned bb = ab + BOF;
#pragma unroll
        for (int ks = 0; ks < 4; ks++) {
            unsigned kx = (unsigned)(ks << 5);
            unsigned aH[2][4], aL[2][4];
#pragma unroll
            for (int mt = 0; mt < 2; mt++) ldsm4(aH[mt], ab + (aoff[mt] ^ kx));
            if (NPASS == 3) {
#pragma unroll
                for (int mt = 0; mt < 2; mt++)
                    ldsm4(aL[mt], ab + 16384u + (aoff[mt] ^ kx));
            }
#pragma unroll
            for (int ng = 0; ng < 4; ng++) {
                unsigned bH[4];
                ldsm4(bH, bb + (boff[ng] ^ kx));
#pragma unroll
                for (int mt = 0; mt < 2; mt++) {
                    mma16816(d[mt][2 * ng + 0], aH[mt], &bH[0]);
                    mma16816(d[mt][2 * ng + 1], aH[mt], &bH[2]);
                }
                if (NPASS >= 2) {
                    unsigned bL[4];
                    ldsm4(bL, bb + 16384u + (boff[ng] ^ kx));
#pragma unroll
                    for (int mt = 0; mt < 2; mt++) {
                        mma16816(d[mt][2 * ng + 0], aH[mt], &bL[0]);
                        mma16816(d[mt][2 * ng + 1], aH[mt], &bL[2]);
                    }
                }
                if (NPASS == 3) {
#pragma unroll
                    for (int mt = 0; mt < 2; mt++) {
                        mma16816(d[mt][2 * ng + 0], aL[mt], &bH[0]);
                        mma16816(d[mt][2 * ng + 1], aL[mt], &bH[2]);
                    }
                }
            }
        }
    }
#undef ISSUE

    int qr = lane >> 2;
    int qc = (lane & 3) << 1;
#pragma unroll
    for (int mt = 0; mt < 2; mt++) {
#pragma unroll
        for (int nt = 0; nt < 8; nt++) {
            int r0 = bm + wm * 32 + mt * 16 + qr;
            int c  = bn + wn * 64 + nt * 8 + qc;
            float v[4];
#pragma unroll
            for (int j = 0; j < 4; j++) v[j] = d[mt][nt][j];
            if (EPI == 2 || EPI == 3) {
                float2 bv = *(const float2*)(bias + c);
                v[0] += bv.x; v[1] += bv.y; v[2] += bv.x; v[3] += bv.y;
            }
            if (EPI == 2) {
#pragma unroll
                for (int j = 0; j < 4; j++)
                    v[j] = 0.5f * v[j] * (1.0f + erff(v[j] * 0.7071067811865475f));
            }
            if (EPI == 1 || EPI == 3) {
                float2 r1 = *(const float2*)(R + (size_t)r0 * ldc + c);
                float2 r2 = *(const float2*)(R + (size_t)(r0 + 8) * ldc + c);
                v[0] += r1.x; v[1] += r1.y; v[2] += r2.x; v[3] += r2.y;
            }
            if (OUTB == 1) {
                *(__half2*)(Cb + (size_t)r0 * ldc + c) =
                    __floats2half2_rn(v[0], v[1]);
                *(__half2*)(Cb + (size_t)(r0 + 8) * ldc + c) =
                    __floats2half2_rn(v[2], v[3]);
            } else if (OUTB == 2) {
                __half2 h0 = __floats2half2_rn(v[0], v[1]);
                __half2 h1 = __floats2half2_rn(v[2], v[3]);
                *(__half2*)(Cb + (size_t)r0 * ldc + c) = h0;
                *(__half2*)(Cb + (size_t)(r0 + 8) * ldc + c) = h1;
                *(__half2*)(Cb2 + (size_t)r0 * ldc + c) =
                    __floats2half2_rn(v[0] - __half2float(__low2half(h0)),
                                      v[1] - __half2float(__high2half(h0)));
                *(__half2*)(Cb2 + (size_t)(r0 + 8) * ldc + c) =
                    __floats2half2_rn(v[2] - __half2float(__low2half(h1)),
                                      v[3] - __half2float(__high2half(h1)));
            } else {
                *(float2*)(Cf + (size_t)r0 * ldc + c) = make_float2(v[0], v[1]);
                *(float2*)(Cf + (size_t)(r0 + 8) * ldc + c) = make_float2(v[2], v[3]);
            }
        }
    }
}

// ---------------- HMMA flash attention --------------------------------------
// CTA: 128 q-rows of one (n,h); iterate 32 s-blocks of 64. 8 warps x 16 rows.
// QK^T 3-pass split fp16, online softmax in base-2 (exp2f), PV 1-pass fp16.
// Q staged through the KV ring area in a prologue (dead after fragment grab),
// so SMEM = 3*24K ring + mask = 74.5 KB -> 3 CTAs/SM.
#define FK_BUF  24576u
#define FK_MASK (3u * FK_BUF)           // 73728
#define FK_SMEM 74496                   // 73728 + 3*256
#define FK_SC   0.1803368801111244f     // 0.125 * log2(e)

__global__ __launch_bounds__(256) void flash_hmma(
    const __half* __restrict__ qh, const __half* __restrict__ ql,
    const float* __restrict__ mask2,
    __half* __restrict__ ch)
{
    extern __shared__ char fsm[];
    unsigned sb = smem_u32(fsm);

    int tid = threadIdx.x, wid = tid >> 5, lane = tid & 31;
    int qr = lane >> 2, tig = lane & 3;
    int bh = blockIdx.y, n = bh >> 4, h = bh & 15;
    int q0 = blockIdx.x << 7;
    const float* maskp = mask2 + (size_t)n * TT;

    const char* qbH = (const char*)(qh + (size_t)(n * TT + q0) * 3072) + h * 128;
    const char* qbL = (const char*)(ql + (size_t)(n * TT + q0) * 3072) + h * 128;
    const char* kvH = (const char*)(qh + (size_t)n * TT * 3072) + h * 128;
    const char* kvL = (const char*)(ql + (size_t)n * TT * 3072) + h * 128;

#define FK_ISSUE(it_) do {                                                     \
    int s0_ = (it_) << 6;                                                      \
    unsigned kb_ = sb + (unsigned)((it_) % 3) * FK_BUF;                        \
    _Pragma("unroll")                                                          \
    for (int i_ = 0; i_ < 2; i_++) {                                           \
        int v_ = tid + (i_ << 8);                                              \
        int row_ = v_ >> 3; int kb2_ = (v_ & 7) << 4;                          \
        unsigned so_ = GSW((unsigned)((row_ << 7) | kb2_));                    \
        size_t gb_ = (size_t)(s0_ + row_) * 6144 + kb2_;                       \
        cp16(kb_ + so_,          kvH + gb_ + 2048);                            \
        cp16(kb_ + 8192u + so_,  kvL + gb_ + 2048);                            \
        cp16(kb_ + 16384u + so_, kvH + gb_ + 4096);                            \
    }                                                                          \
    if (tid < 16)                                                              \
        cp16(sb + FK_MASK + (unsigned)((it_) % 3) * 256u + (tid << 4),         \
             maskp + s0_ + tid * 4);                                           \
    cpcommit();                                                                \
} while (0)

    // fragment offsets
    int li = lane & 7, sub = lane >> 3;
    unsigned m4 = (unsigned)li << 4;
    unsigned qoff;
    {
        unsigned r = (unsigned)(wid * 16 + (sub & 1) * 8 + li);
        qoff = (r << 7) + ((unsigned)((sub >> 1) << 4) ^ m4);
    }
    unsigned koff[4];
#pragma unroll
    for (int ng = 0; ng < 4; ng++) {
        unsigned r = (unsigned)(ng * 16 + (sub >> 1) * 8 + li);
        koff[ng] = (r << 7) + ((unsigned)((sub & 1) << 4) ^ m4);
    }
    unsigned vrow = (unsigned)((sub & 1) * 8 + li) << 7;
    unsigned vb[4];
#pragma unroll
    for (int dt = 0; dt < 4; dt++)
        vb[dt] = ((unsigned)((sub >> 1) << 4) + (unsigned)(dt << 5)) ^ m4;

    // ---- prologue: stage Q through ring area, grab fragments, free it ----
    unsigned qHf[4][4], qLf[4][4];
#pragma unroll
    for (int i = 0; i < 4; i++) {
        int v = tid + (i << 8);
        int row = v >> 3; int kb = (v & 7) << 4;
        unsigned so = GSW((unsigned)((row << 7) | kb));
        cp16(sb + so,          qbH + (size_t)row * 6144 + kb);
        cp16(sb + 16384u + so, qbL + (size_t)row * 6144 + kb);
    }
    cpcommit();
    cpwait<0>();
    __syncthreads();
#pragma unroll
    for (int ks = 0; ks < 4; ks++) {
        unsigned kx = (unsigned)(ks << 5);
        ldsm4(qHf[ks], sb + (qoff ^ kx));
        ldsm4(qLf[ks], sb + 16384u + (qoff ^ kx));
    }
    __syncthreads();      // all warps done reading Q before ring reuse
    FK_ISSUE(0);
    FK_ISSUE(1);

    float sS[8][4], oO[8][4];
    float mM[2] = {-1e30f, -1e30f}, lL[2] = {0.f, 0.f};
#pragma unroll
    for (int nt = 0; nt < 8; nt++)
#pragma unroll
        for (int j = 0; j < 4; j++) oO[nt][j] = 0.f;

    for (int it = 0; it < TT / 64; ++it) {
        if (it == TT / 64 - 1) cpwait<0>(); else cpwait<1>();
        __syncthreads();
        if (it + 2 < TT / 64) FK_ISSUE(it + 2);
        unsigned kb0 = sb + (unsigned)(it % 3) * FK_BUF;

        // ---- S = Q@K^T (3-pass fp16) ----
#pragma unroll
        for (int nt = 0; nt < 8; nt++)
#pragma unroll
            for (int j = 0; j < 4; j++) sS[nt][j] = 0.f;
#pragma unroll
        for (int ks = 0; ks < 4; ks++) {
            unsigned kx = (unsigned)(ks << 5);
#pragma unroll
            for (int ng = 0; ng < 4; ng++) {
                unsigned bH[4], bL[4];
                ldsm4(bH, kb0 + (koff[ng] ^ kx));
                ldsm4(bL, kb0 + 8192u + (koff[ng] ^ kx));
                mma16816(sS[2 * ng + 0], qHf[ks], &bH[0]);
                mma16816(sS[2 * ng + 1], qHf[ks], &bH[2]);
                mma16816(sS[2 * ng + 0], qHf[ks], &bL[0]);
                mma16816(sS[2 * ng + 1], qHf[ks], &bL[2]);
                mma16816(sS[2 * ng + 0], qLf[ks], &bH[0]);
                mma16816(sS[2 * ng + 1], qLf[ks], &bH[2]);
            }
        }

        // ---- scale (0.125*log2e) + mask (pre-scaled by log2e) ----
        const float* mbuf = (const float*)(fsm + FK_MASK + (it % 3) * 256);
#pragma unroll
        for (int nt = 0; nt < 8; nt++) {
            float2 mv = *(const float2*)(mbuf + nt * 8 + 2 * tig);
            sS[nt][0] = fmaf(sS[nt][0], FK_SC, mv.x);
            sS[nt][1] = fmaf(sS[nt][1], FK_SC, mv.y);
            sS[nt][2] = fmaf(sS[nt][2], FK_SC, mv.x);
            sS[nt][3] = fmaf(sS[nt][3], FK_SC, mv.y);
        }

        // ---- online softmax, base-2 (2 rows/thread) ----
#pragma unroll
        for (int i = 0; i < 2; i++) {
            int ib = 2 * i;
            float mx = -1e30f;
#pragma unroll
            for (int nt = 0; nt < 8; nt++)
                mx = fmaxf(mx, fmaxf(sS[nt][ib], sS[nt][ib + 1]));
            mx = fmaxf(mx, __shfl_xor_sync(0xffffffffu, mx, 1));
            mx = fmaxf(mx, __shfl_xor_sync(0xffffffffu, mx, 2));
            float mnew  = fmaxf(mM[i], mx);
            float alpha = exp2f(mM[i] - mnew);
            float rsum = 0.f;
#pragma unroll
            for (int nt = 0; nt < 8; nt++) {
                float p0 = exp2f(sS[nt][ib]     - mnew);
                float p1 = exp2f(sS[nt][ib + 1] - mnew);
                sS[nt][ib] = p0; sS[nt][ib + 1] = p1;
                rsum += p0 + p1;
            }
            rsum += __shfl_xor_sync(0xffffffffu, rsum, 1);
            rsum += __shfl_xor_sync(0xffffffffu, rsum, 2);
            lL[i] = lL[i] * alpha + rsum;
            mM[i] = mnew;
#pragma unroll
            for (int nt = 0; nt < 8; nt++) {
                oO[nt][ib] *= alpha; oO[nt][ib + 1] *= alpha;
            }
        }

        // ---- O += P@V (1-pass fp16: Ph*Vh) ----
#pragma unroll
        for (int kt = 0; kt < 4; kt++) {
            unsigned ah[4];
#pragma unroll
            for (int half = 0; half < 2; half++) {
                int nt = 2 * kt + half;
                ah[2 * half + 0] = h2u(__floats2half2_rn(sS[nt][0], sS[nt][1]));
                ah[2 * half + 1] = h2u(__floats2half2_rn(sS[nt][2], sS[nt][3]));
            }
            unsigned vkb = kb0 + 16384u + (unsigned)(kt << 11) + vrow;
#pragma unroll
            for (int dt = 0; dt < 4; dt++) {
                unsigned bv[4];
                ldsm4t(bv, vkb + vb[dt]);
                mma16816(oO[2 * dt + 0], ah, &bv[0]);
                mma16816(oO[2 * dt + 1], ah, &bv[2]);
            }
        }
    }
#undef FK_ISSUE

    // ---- write ctx hi ----
#pragma unroll
    for (int i = 0; i < 2; i++) {
        float inv = 1.f / lL[i];
        int ib = 2 * i;
        size_t tok = (size_t)(n * TT + q0 + wid * 16 + qr + i * 8);
#pragma unroll
        for (int nt = 0; nt < 8; nt++) {
            float v0 = oO[nt][ib] * inv, v1 = oO[nt][ib + 1] * inv;
            int col = h * 64 + nt * 8 + 2 * tig;
            *(__half2*)(ch + tok * DD + col) = __floats2half2_rn(v0, v1);
        }
    }
}

// ---------------- fused prep: 4 weight transposes + mask scale ---------------
// seg0 Wqkv(split)  768 blocks | seg1 Wout 256 | seg2 W1 1024 | seg3 W2 1024
// | last block: mask * log2(e).  Total 3073 blocks, 256 threads.
__device__ __forceinline__ void transpose_body(
    const float* __restrict__ W, __half* __restrict__ Th,
    __half* __restrict__ Tl, int K, int N, int bx, int by, int split)
{
    __shared__ float t[32][129];
    int tid = threadIdx.x;
    int k0 = by * 32, n0 = bx * 128;
    int kk = tid >> 3, nn = (tid & 7) * 4;
#pragma unroll
    for (int i = 0; i < 4; i++) {
        float4 v = *(const float4*)(W + (size_t)(k0 + kk) * N + n0 + i * 32 + nn);
        t[kk][i * 32 + nn + 0] = v.x; t[kk][i * 32 + nn + 1] = v.y;
        t[kk][i * 32 + nn + 2] = v.z; t[kk][i * 32 + nn + 3] = v.w;
    }
    __syncthreads();
    int wid = tid >> 5, lane = tid & 31;
    int k2 = (lane & 15) * 2;
#pragma unroll
    for (int i = 0; i < 8; i++) {
        int nrow = wid * 16 + i * 2 + (lane >> 4);
        float a = t[k2][nrow], b = t[k2 + 1][nrow];
        __half ha = __float2half_rn(a), hb = __float2half_rn(b);
        *(__half2*)(Th + (size_t)(n0 + nrow) * K + k0 + k2) = __halves2half2(ha, hb);
        if (split)
            *(__half2*)(Tl + (size_t)(n0 + nrow) * K + k0 + k2) =
                __halves2half2(__float2half_rn(a - __half2float(ha)),
                               __float2half_rn(b - __half2float(hb)));
    }
}

__global__ __launch_bounds__(256) void prep_kernel(
    const float* __restrict__ Wqkv, const float* __restrict__ Wout,
    const float* __restrict__ W1,   const float* __restrict__ W2,
    const float* __restrict__ mask, float* __restrict__ msc,
    __half* __restrict__ wqh, __half* __restrict__ wql,
    __half* __restrict__ woh, __half* __restrict__ w1t,
    __half* __restrict__ w2t)
{
    int b = blockIdx.x;
    if (b < 768) {                       // Wqkv [1024,3072] -> split
        transpose_body(Wqkv, wqh, wql, DD, 3 * DD, b % 24, b / 24, 1);
    } else if (b < 1024) {               // Wout [1024,1024]
        int r = b - 768;
        transpose_body(Wout, woh, nullptr, DD, DD, r % 8, r / 8, 0);
    } else if (b < 2048) {               // W1 [1024,4096]
        int r = b - 1024;
        transpose_body(W1, w1t, nullptr, DD, 4 * DD, r % 32, r / 32, 0);
    } else if (b < 3072) {               // W2 [4096,1024]
        int r = b - 2048;
        transpose_body(W2, w2t, nullptr, 4 * DD, DD, r % 8, r / 8, 0);
    } else {                             // mask scale
        for (int i = threadIdx.x; i < NB * TT; i += 256)
            msc[i] = mask[i] * 1.4426950408889634f;
    }
}

// ---------------- LayerNorm -> fp16 hi(/lo), float4 vectorized ---------------
template <int WLO>
__global__ __launch_bounds__(256) void ln_fp16_kernel(
    const float* __restrict__ x, const float* __restrict__ g,
    const float* __restrict__ b,
    __half* __restrict__ zh, __half* __restrict__ zl)
{
    int row = blockIdx.x;
    const float* xr = x + (size_t)row * DD;
    int tid = threadIdx.x;
    float4 v = *(const float4*)(xr + tid * 4);
    float sum = v.x + v.y + v.z + v.w;
    float sq  = v.x * v.x + v.y * v.y + v.z * v.z + v.w * v.w;
#pragma unroll
    for (int o = 16; o > 0; o >>= 1) {
        sum += __shfl_xor_sync(0xffffffffu, sum, o);
        sq  += __shfl_xor_sync(0xffffffffu, sq,  o);
    }
    __shared__ float red[2][8];
    int w = tid >> 5, l = tid & 31;
    if (l == 0) { red[0][w] = sum; red[1][w] = sq; }
    __syncthreads();
    if (tid < 32) {
        float s = (tid < 8) ? red[0][tid] : 0.f;
        float q = (tid < 8) ? red[1][tid] : 0.f;
#pragma unroll
        for (int o = 4; o > 0; o >>= 1) {
            s += __shfl_xor_sync(0xffffffffu, s, o);
            q += __shfl_xor_sync(0xffffffffu, q, o);
        }
        if (tid == 0) { red[0][0] = s; red[1][0] = q; }
    }
    __syncthreads();
    float mu   = red[0][0] * (1.f / DD);
    float var  = red[1][0] * (1.f / DD) - mu * mu;
    float rstd = rsqrtf(var + 1e-5f);
    int c = tid * 4;
    float4 gv = *(const float4*)(g + c);
    float4 bv = *(const float4*)(b + c);
    float y0 = (v.x - mu) * rstd * gv.x + bv.x;
    float y1 = (v.y - mu) * rstd * gv.y + bv.y;
    float y2 = (v.z - mu) * rstd * gv.z + bv.z;
    float y3 = (v.w - mu) * rstd * gv.w + bv.w;
    __half2 h0 = __floats2half2_rn(y0, y1);
    __half2 h1 = __floats2half2_rn(y2, y3);
    *(__half2*)(zh + (size_t)row * DD + c)     = h0;
    *(__half2*)(zh + (size_t)row * DD + c + 2) = h1;
    if (WLO) {
        *(__half2*)(zl + (size_t)row * DD + c) =
            __floats2half2_rn(y0 - __half2float(__low2half(h0)),
                              y1 - __half2float(__high2half(h0)));
        *(__half2*)(zl + (size_t)row * DD + c + 2) =
            __floats2half2_rn(y2 - __half2float(__low2half(h1)),
                              y3 - __half2float(__high2half(h1)));
    }
}

// ---------------- launch -----------------------------------------------------
extern "C" void kernel_launch(void* const* d_in, const int* in_sizes, int n_in,
                              void* d_out, int out_size)
{
    const float* x     = (const float*)d_in[0];
    const float* mask  = (const float*)d_in[1];
    const float* Wqkv  = (const float*)d_in[2];
    const float* Wout  = (const float*)d_in[3];
    const float* ln1_g = (const float*)d_in[4];
    const float* ln1_b = (const float*)d_in[5];
    const float* ln2_g = (const float*)d_in[6];
    const float* ln2_b = (const float*)d_in[7];
    const float* W1    = (const float*)d_in[8];
    const float* b1    = (const float*)d_in[9];
    const float* W2    = (const float*)d_in[10];
    const float* b2    = (const float*)d_in[11];
    float* out = (float*)d_out;

    float *x1, *msc;
    __half *qh, *ql, *zh, *zl, *ch, *hb;
    __half *wqh, *wql, *woh, *w1t, *w2t;
    cudaGetSymbolAddress((void**)&x1,  g_x1);
    cudaGetSymbolAddress((void**)&msc, g_msc);
    cudaGetSymbolAddress((void**)&qh,  g_qh);
    cudaGetSymbolAddress((void**)&ql,  g_ql);
    cudaGetSymbolAddress((void**)&zh,  g_zh);
    cudaGetSymbolAddress((void**)&zl,  g_zl);
    cudaGetSymbolAddress((void**)&ch,  g_ch);
    cudaGetSymbolAddress((void**)&hb,  g_hb);
    cudaGetSymbolAddress((void**)&wqh, g_wqh);
    cudaGetSymbolAddress((void**)&wql, g_wql);
    cudaGetSymbolAddress((void**)&woh, g_woh);
    cudaGetSymbolAddress((void**)&w1t, g_w1t);
    cudaGetSymbolAddress((void**)&w2t, g_w2t);

    cudaFuncSetAttribute(flash_hmma,
                         cudaFuncAttributeMaxDynamicSharedMemorySize, FK_SMEM);
    cudaFuncSetAttribute(hmma_gemm<3, 0, 2>,
                         cudaFuncAttributeMaxDynamicSharedMemorySize, GEMM_SMEM3);
    cudaFuncSetAttribute(hmma_gemm<1, 0, 1>,
                         cudaFuncAttributeMaxDynamicSharedMemorySize, GEMM_SMEM1);
    cudaFuncSetAttribute(hmma_gemm<1, 1, 0>,
                         cudaFuncAttributeMaxDynamicSharedMemorySize, GEMM_SMEM1);
    cudaFuncSetAttribute(hmma_gemm<1, 2, 1>,
                         cudaFuncAttributeMaxDynamicSharedMemorySize, GEMM_SMEM1);
    cudaFuncSetAttribute(hmma_gemm<1, 3, 0>,
                         cudaFuncAttributeMaxDynamicSharedMemorySize, GEMM_SMEM1);

    // 0. fused prep: all weight transposes + mask scale in one launch
    prep_kernel<<<3073, 256>>>(Wqkv, Wout, W1, W2, mask, msc,
                               wqh, wql, woh, w1t, w2t);

    // 1. LN1 -> fp16 hi/lo
    ln_fp16_kernel<1><<<MTOK, 256>>>(x, ln1_g, ln1_b, zh, zl);
    // 2a. QK = z @ Wqkv[:, :2048]  (fused 3-pass) -> fp16 hi/lo, ldc=3072
    hmma_gemm<3, 0, 2><<<dim3(2 * DD / 128, MTOK / 128), 256, GEMM_SMEM3>>>(
        zh, zl, wqh, wql, nullptr, nullptr, nullptr, qh, ql,
        MTOK, 2 * DD, DD, 3 * DD);
    // 2b. V = z @ Wqkv[:, 2048:]  (1-pass) -> fp16 hi only, ldc=3072
    hmma_gemm<1, 0, 1><<<dim3(DD / 128, MTOK / 128), 256, GEMM_SMEM1>>>(
        zh, nullptr, wqh + (size_t)(2 * DD) * DD, nullptr, nullptr, nullptr,
        nullptr, qh + 2 * DD, nullptr, MTOK, DD, DD, 3 * DD);
    // 3. attention (HMMA, 3-pass QK / 1-pass PV, base-2 softmax) -> ctx hi
    flash_hmma<<<dim3(TT / 128, NB * HH), 256, FK_SMEM>>>(qh, ql, msc, ch);
    // 4. x1 = x + ctx @ Wout  (1-pass)
    hmma_gemm<1, 1, 0><<<dim3(DD / 128, MTOK / 128), 256, GEMM_SMEM1>>>(
        ch, nullptr, woh, nullptr, x, nullptr, x1, nullptr, nullptr,
        MTOK, DD, DD, DD);
    // 5. LN2 -> fp16 hi
    ln_fp16_kernel<0><<<MTOK, 256>>>(x1, ln2_g, ln2_b, zh, nullptr);
    // 6. h = gelu(z2 @ W1 + b1) -> fp16
    hmma_gemm<1, 2, 1><<<dim3(4 * DD / 128, MTOK / 128), 256, GEMM_SMEM1>>>(
        zh, nullptr, w1t, nullptr, nullptr, b1, nullptr, hb, nullptr,
        MTOK, 4 * DD, DD, 4 * DD);
    // 7. out = x1 + h @ W2 + b2
    hmma_gemm<1, 3, 0><<<dim3(DD / 128, MTOK / 128), 256, GEMM_SMEM1>>>(
        hb, nullptr, w2t, nullptr, x1, b2, out, nullptr, nullptr,
        MTOK, DD, 4 * DD, DD);
}